// round 2
// baseline (speedup 1.0000x reference)
#include <cuda_runtime.h>
#include <math.h>

// Problem dims
#define BB   8
#define TT   12
#define NN   512
#define FINN 3
#define DD   128
#define HH   4
#define HMM  256
#define LL   3
#define PP   12
#define TOK  (BB*TT*NN)          // 49152 tokens

// ---------------- scratch (static device globals; allocation-free) ----------
__device__ float g_h  [TOK*DD];      // layer input / residual
__device__ float g_h2 [TOK*DD];      // post-temporal hidden
__device__ float g_qkv[TOK*3*DD];    // fused qkv [tok, 384]
__device__ float g_att[TOK*DD];      // attention output (pre-proj)
__device__ float g_cat[TOK*2*DD];    // [geo | sem]
__device__ float g_mlp[TOK*HMM];     // fc1 out
__device__ float g_m  [TOK*DD];      // fc2 out
__device__ float g_pre[TOK*DD];      // pre-LN
__device__ float g_xc [TOK*LL*DD];   // concat of layer outputs [tok, 384]

// ---------------- embedding + positional encoding ---------------------------
__global__ void embed_kernel(const float* __restrict__ x,
                             const float* __restrict__ tokW,
                             const float* __restrict__ tokb,
                             float* __restrict__ h)
{
    size_t idx = (size_t)blockIdx.x * 256 + threadIdx.x;   // token*128 + d
    size_t token = idx >> 7;
    int d = (int)(idx & 127);
    int t = (int)((token / NN) % TT);
    const float* xp = x + token * FINN;
    float val = xp[0]*tokW[d*3+0] + xp[1]*tokW[d*3+1] + xp[2]*tokW[d*3+2] + tokb[d];
    int i2 = d & ~1;
    float div = expf((float)i2 * (-logf(10000.0f) / (float)DD));
    float ang = (float)t * div;
    val += (d & 1) ? cosf(ang) : sinf(ang);
    h[idx] = val;
}

// ---------------- generic 128x128x8 SIMT GEMM: C = act(A @ W^T + bias [+extra])
// A: [M,K] row-major (lda=K), W: [N,K] row-major, C: ldc with pointer pre-offset.
// grid = (N/128, M/128), block = 256. M,N multiples of 128; K multiple of 8.
__global__ void gemm_kernel(const float* __restrict__ A, const float* __restrict__ W,
                            const float* __restrict__ bias, const float* __restrict__ extra,
                            float* __restrict__ C, int K, int ldc, int act)
{
    __shared__ float As[8][128];
    __shared__ float Ws[8][128];
    const int tid = threadIdx.x;
    const int m0 = blockIdx.y * 128;
    const int n0 = blockIdx.x * 128;
    const int ty = tid >> 4, tx = tid & 15;
    const int lrow = tid >> 1;
    const int lcol = (tid & 1) << 2;
    const float* Ap = A + (size_t)(m0 + lrow) * K + lcol;
    const float* Wp = W + (size_t)(n0 + lrow) * K + lcol;

    float acc[8][8];
#pragma unroll
    for (int i = 0; i < 8; ++i)
#pragma unroll
        for (int j = 0; j < 8; ++j) acc[i][j] = 0.f;

    for (int k0 = 0; k0 < K; k0 += 8) {
        float4 a4 = *(const float4*)(Ap + k0);
        float4 w4 = *(const float4*)(Wp + k0);
        __syncthreads();
        As[lcol+0][lrow] = a4.x; As[lcol+1][lrow] = a4.y;
        As[lcol+2][lrow] = a4.z; As[lcol+3][lrow] = a4.w;
        Ws[lcol+0][lrow] = w4.x; Ws[lcol+1][lrow] = w4.y;
        Ws[lcol+2][lrow] = w4.z; Ws[lcol+3][lrow] = w4.w;
        __syncthreads();
#pragma unroll
        for (int kk = 0; kk < 8; ++kk) {
            float a[8], b[8];
            *(float4*)(a)   = *(const float4*)(&As[kk][ty*8]);
            *(float4*)(a+4) = *(const float4*)(&As[kk][ty*8+4]);
            *(float4*)(b)   = *(const float4*)(&Ws[kk][tx*8]);
            *(float4*)(b+4) = *(const float4*)(&Ws[kk][tx*8+4]);
#pragma unroll
            for (int i = 0; i < 8; ++i)
#pragma unroll
                for (int j = 0; j < 8; ++j)
                    acc[i][j] = fmaf(a[i], b[j], acc[i][j]);
        }
    }
#pragma unroll
    for (int i = 0; i < 8; ++i) {
        int row = m0 + ty*8 + i;
#pragma unroll
        for (int j = 0; j < 8; ++j) {
            int col = n0 + tx*8 + j;
            float v = acc[i][j] + bias[col];
            if (extra) v += extra[(size_t)row * ldc + col];
            if (act == 1) v = 0.5f * v * (1.0f + erff(v * 0.70710678118654752f));
            C[(size_t)row * ldc + col] = v;
        }
    }
}

// ---------------- temporal attention (over T=12, per (b,n)) -----------------
// qkv layout [tok, 384] (q|k|v), head h -> cols h*32..h*32+31. out: [tok,128]
__global__ void temporal_attn_kernel(const float* __restrict__ qkv,
                                     float* __restrict__ out)
{
    const int bidx = blockIdx.x;        // b*512 + n
    const int b = bidx >> 9, n = bidx & 511;
    const int tid = threadIdx.x;        // 128
    __shared__ float q[TT][DD], k[TT][DD], v[TT][DD];
    __shared__ float S[HH][TT][TT];
#pragma unroll
    for (int t = 0; t < TT; ++t) {
        size_t row = ((size_t)(b*TT + t) * NN + n) * 384;
        q[t][tid] = qkv[row + tid];
        k[t][tid] = qkv[row + 128 + tid];
        v[t][tid] = qkv[row + 256 + tid];
    }
    __syncthreads();
    const float scale = 0.17677669529663687f;   // 1/sqrt(32)
    for (int idx = tid; idx < HH*TT*TT; idx += 128) {
        int hh = idx / (TT*TT);
        int rem = idx - hh*(TT*TT);
        int xx = rem / TT, yy = rem - xx*TT;
        float s = 0.f;
#pragma unroll
        for (int e = 0; e < 32; ++e)
            s = fmaf(q[xx][hh*32+e], k[yy][hh*32+e], s);
        S[hh][xx][yy] = s * scale;
    }
    __syncthreads();
    if (tid < HH*TT) {
        int hh = tid / TT, xx = tid % TT;
        float mx = -1e30f;
#pragma unroll
        for (int y = 0; y < TT; ++y) mx = fmaxf(mx, S[hh][xx][y]);
        float sum = 0.f;
#pragma unroll
        for (int y = 0; y < TT; ++y) { float p = __expf(S[hh][xx][y]-mx); S[hh][xx][y] = p; sum += p; }
        float inv = 1.f / sum;
#pragma unroll
        for (int y = 0; y < TT; ++y) S[hh][xx][y] *= inv;
    }
    __syncthreads();
    const int hh = tid >> 5;
    for (int xx = 0; xx < TT; ++xx) {
        float o = 0.f;
#pragma unroll
        for (int yy = 0; yy < TT; ++yy) o = fmaf(S[hh][xx][yy], v[yy][tid], o);
        out[((size_t)(b*TT + xx) * NN + n) * DD + tid] = o;
    }
}

// ---------------- spatial attention (over N=512, per (b,t,head)) ------------
// fused online softmax; 64-query tile per block, 256 threads.
__global__ void spatial_attn_kernel(const float* __restrict__ qkv,
                                    float* __restrict__ out)
{
    const int qtile = blockIdx.x;     // 8
    const int head  = blockIdx.y;     // 4
    const int bt    = blockIdx.z;     // 96
    const int tid = threadIdx.x;
    const int ty = tid >> 4, tx = tid & 15;

    __shared__ float Qs[32][64];      // [e][qi]
    __shared__ float Ks[32][64];      // [e][kj]
    __shared__ float Vs[64][32];      // [j][e]
    __shared__ float Ps[64][68];      // [j][qi], padded (68*4B keeps 16B align)

    const size_t base = (size_t)bt * NN;
    const float* qb = qkv + (base + (size_t)qtile*64) * 384 + head*32;
    for (int i = tid; i < 64*32; i += 256) {
        int r = i >> 5, e = i & 31;
        Qs[e][r] = qb[(size_t)r*384 + e];
    }

    float m[4], l[4], acc0[4], acc1[4];
#pragma unroll
    for (int r = 0; r < 4; ++r) { m[r] = -1e30f; l[r] = 0.f; acc0[r] = 0.f; acc1[r] = 0.f; }
    const float scale = 0.17677669529663687f;

    for (int kt = 0; kt < NN/64; ++kt) {
        __syncthreads();   // prev tile's P@V readers done before K/V overwrite
        const float* kb = qkv + (base + (size_t)kt*64) * 384 + 128 + head*32;
        const float* vb = kb + 128;
        for (int i = tid; i < 64*32; i += 256) {
            int r = i >> 5, e = i & 31;
            Ks[e][r] = kb[(size_t)r*384 + e];
            Vs[r][e] = vb[(size_t)r*384 + e];
        }
        __syncthreads();

        float s[4][4];
#pragma unroll
        for (int r = 0; r < 4; ++r)
#pragma unroll
            for (int c = 0; c < 4; ++c) s[r][c] = 0.f;
#pragma unroll
        for (int e = 0; e < 32; ++e) {
            float4 qa = *(const float4*)(&Qs[e][ty*4]);
            float4 ka = *(const float4*)(&Ks[e][tx*4]);
            float aa[4] = {qa.x, qa.y, qa.z, qa.w};
            float bb[4] = {ka.x, ka.y, ka.z, ka.w};
#pragma unroll
            for (int r = 0; r < 4; ++r)
#pragma unroll
                for (int c = 0; c < 4; ++c)
                    s[r][c] = fmaf(aa[r], bb[c], s[r][c]);
        }
#pragma unroll
        for (int r = 0; r < 4; ++r) {
            float rm = -1e30f;
#pragma unroll
            for (int c = 0; c < 4; ++c) { s[r][c] *= scale; rm = fmaxf(rm, s[r][c]); }
#pragma unroll
            for (int off = 8; off; off >>= 1)
                rm = fmaxf(rm, __shfl_xor_sync(0xffffffffu, rm, off));
            float nm = fmaxf(m[r], rm);
            float corr = __expf(m[r] - nm);
            m[r] = nm;
            float rs = 0.f;
#pragma unroll
            for (int c = 0; c < 4; ++c) {
                float p = __expf(s[r][c] - nm);
                Ps[tx*4 + c][ty*4 + r] = p;
                rs += p;
            }
#pragma unroll
            for (int off = 8; off; off >>= 1)
                rs += __shfl_xor_sync(0xffffffffu, rs, off);
            l[r] = l[r]*corr + rs;
            acc0[r] *= corr; acc1[r] *= corr;
        }
        __syncthreads();
#pragma unroll 4
        for (int j = 0; j < 64; ++j) {
            float4 p4 = *(const float4*)(&Ps[j][ty*4]);
            float2 v2 = *(const float2*)(&Vs[j][tx*2]);
            acc0[0] = fmaf(p4.x, v2.x, acc0[0]); acc1[0] = fmaf(p4.x, v2.y, acc1[0]);
            acc0[1] = fmaf(p4.y, v2.x, acc0[1]); acc1[1] = fmaf(p4.y, v2.y, acc1[1]);
            acc0[2] = fmaf(p4.z, v2.x, acc0[2]); acc1[2] = fmaf(p4.z, v2.y, acc1[2]);
            acc0[3] = fmaf(p4.w, v2.x, acc0[3]); acc1[3] = fmaf(p4.w, v2.y, acc1[3]);
        }
    }
#pragma unroll
    for (int r = 0; r < 4; ++r) {
        float inv = 1.f / l[r];
        size_t row = base + (size_t)qtile*64 + ty*4 + r;
        float* op = out + row*DD + head*32 + tx*2;
        op[0] = acc0[r]*inv;
        op[1] = acc1[r]*inv;
    }
}

// ---------------- layernorm (one token per warp) -----------------------------
__global__ void ln_kernel(const float* __restrict__ pre, const float* __restrict__ g,
                          const float* __restrict__ bta, float* __restrict__ h,
                          float* __restrict__ xc /* pre-offset by l*128 */)
{
    const int warp = threadIdx.x >> 5, lane = threadIdx.x & 31;
    size_t token = (size_t)blockIdx.x * 8 + warp;
    const float* p = pre + token * DD;
    float v[4];
#pragma unroll
    for (int i = 0; i < 4; ++i) v[i] = p[lane + 32*i];
    float s = v[0] + v[1] + v[2] + v[3];
#pragma unroll
    for (int o = 16; o; o >>= 1) s += __shfl_xor_sync(0xffffffffu, s, o);
    float mean = s * (1.f/128.f);
    float q = 0.f;
#pragma unroll
    for (int i = 0; i < 4; ++i) { v[i] -= mean; q += v[i]*v[i]; }
#pragma unroll
    for (int o = 16; o; o >>= 1) q += __shfl_xor_sync(0xffffffffu, q, o);
    float inv = rsqrtf(q * (1.f/128.f) + 1e-5f);
#pragma unroll
    for (int i = 0; i < 4; ++i) {
        int d = lane + 32*i;
        float o = v[i] * inv * g[d] + bta[d];
        h[token*DD + d] = o;
        xc[token*(LL*DD) + d] = o;
    }
}

// ---------------- output head: relu(xc @T end1W + b1) @ end2W + b2 ----------
__global__ void head_kernel(const float* __restrict__ xc, const float* __restrict__ w1g,
                            const float* __restrict__ b1g, const float* __restrict__ w2g,
                            const float* __restrict__ b2g, float* __restrict__ y)
{
    const int bidx = blockIdx.x;          // b*512 + n
    const int b = bidx >> 9, n = bidx & 511;
    const int tid = threadIdx.x;          // 128
    __shared__ float xs[TT][LL*DD];
    __shared__ float w1[PP][TT];
    __shared__ float b1[PP];
    __shared__ float w2[LL*DD];
    __shared__ float red[PP][4];
    for (int t = 0; t < TT; ++t) {
        size_t rowoff = ((size_t)(b*TT + t) * NN + n) * (LL*DD);
        for (int c = tid; c < LL*DD; c += 128) xs[t][c] = xc[rowoff + c];
    }
    // FIX: PP*TT = 144 > blockDim (128); must stride, not guard.
    for (int i = tid; i < PP*TT; i += 128) w1[i/TT][i%TT] = w1g[i];
    if (tid < PP) b1[tid] = b1g[tid];
    for (int c = tid; c < LL*DD; c += 128) w2[c] = w2g[c];
    __syncthreads();

    float part[PP];
#pragma unroll
    for (int p = 0; p < PP; ++p) part[p] = 0.f;
    for (int c = tid; c < LL*DD; c += 128) {
        float xt[TT];
#pragma unroll
        for (int t = 0; t < TT; ++t) xt[t] = xs[t][c];
        float wc = w2[c];
#pragma unroll
        for (int p = 0; p < PP; ++p) {
            float sacc = b1[p];
#pragma unroll
            for (int t = 0; t < TT; ++t) sacc = fmaf(xt[t], w1[p][t], sacc);
            sacc = fmaxf(sacc, 0.f);
            part[p] = fmaf(sacc, wc, part[p]);
        }
    }
    const int warp = tid >> 5, lane = tid & 31;
#pragma unroll
    for (int p = 0; p < PP; ++p) {
        float sv = part[p];
#pragma unroll
        for (int o = 16; o; o >>= 1) sv += __shfl_xor_sync(0xffffffffu, sv, o);
        if (lane == 0) red[p][warp] = sv;
    }
    __syncthreads();
    if (tid < PP) {
        float sv = red[tid][0] + red[tid][1] + red[tid][2] + red[tid][3];
        y[(size_t)(b*PP + tid) * NN + n] = sv + b2g[0];
    }
}

// ---------------- launcher ---------------------------------------------------
extern "C" void kernel_launch(void* const* d_in, const int* in_sizes, int n_in,
                              void* d_out, int out_size)
{
    (void)in_sizes; (void)n_in; (void)out_size;
    const float* x      = (const float*)d_in[0];
    const float* tokW   = (const float*)d_in[1];
    const float* tokb   = (const float*)d_in[2];
    const float* t_qkvW = (const float*)d_in[3];
    const float* t_qkvb = (const float*)d_in[4];
    const float* t_pW   = (const float*)d_in[5];
    const float* t_pb   = (const float*)d_in[6];
    const float* g_qkvW = (const float*)d_in[7];
    const float* g_qkvb = (const float*)d_in[8];
    const float* g_pW   = (const float*)d_in[9];
    const float* g_pb   = (const float*)d_in[10];
    const float* s_qkvW = (const float*)d_in[11];
    const float* s_qkvb = (const float*)d_in[12];
    const float* s_pW   = (const float*)d_in[13];
    const float* s_pb   = (const float*)d_in[14];
    const float* resW   = (const float*)d_in[15];
    const float* resb   = (const float*)d_in[16];
    const float* normW  = (const float*)d_in[17];
    const float* normb  = (const float*)d_in[18];
    const float* fc1W   = (const float*)d_in[19];
    const float* fc1b   = (const float*)d_in[20];
    const float* fc2W   = (const float*)d_in[21];
    const float* fc2b   = (const float*)d_in[22];
    const float* e1W    = (const float*)d_in[23];
    const float* e1b    = (const float*)d_in[24];
    const float* e2W    = (const float*)d_in[25];
    const float* e2b    = (const float*)d_in[26];
    float* out = (float*)d_out;

    float *hA, *hB, *qkvB, *attB, *catB, *mlpB, *mB, *preB, *xcB;
    cudaGetSymbolAddress((void**)&hA,   g_h);
    cudaGetSymbolAddress((void**)&hB,   g_h2);
    cudaGetSymbolAddress((void**)&qkvB, g_qkv);
    cudaGetSymbolAddress((void**)&attB, g_att);
    cudaGetSymbolAddress((void**)&catB, g_cat);
    cudaGetSymbolAddress((void**)&mlpB, g_mlp);
    cudaGetSymbolAddress((void**)&mB,   g_m);
    cudaGetSymbolAddress((void**)&preB, g_pre);
    cudaGetSymbolAddress((void**)&xcB,  g_xc);

    const int MB = TOK / 128;   // 384 row-tiles

    embed_kernel<<<(TOK*DD)/256, 256>>>(x, tokW, tokb, hA);

    for (int l = 0; l < LL; ++l) {
        const size_t oqW = (size_t)l*3*DD*DD, oqb = (size_t)l*3*DD;
        const size_t opW = (size_t)l*DD*DD,  opb = (size_t)l*DD;

        // temporal attention
        gemm_kernel<<<dim3(3, MB), 256>>>(hA, t_qkvW + oqW, t_qkvb + oqb, nullptr,
                                          qkvB, DD, 3*DD, 0);
        temporal_attn_kernel<<<BB*NN, 128>>>(qkvB, attB);
        gemm_kernel<<<dim3(1, MB), 256>>>(attB, t_pW + opW, t_pb + opb, nullptr,
                                          hB, DD, DD, 0);
        // geo spatial attention -> cat[:,0:128]
        gemm_kernel<<<dim3(3, MB), 256>>>(hB, g_qkvW + oqW, g_qkvb + oqb, nullptr,
                                          qkvB, DD, 3*DD, 0);
        spatial_attn_kernel<<<dim3(NN/64, HH, BB*TT), 256>>>(qkvB, attB);
        gemm_kernel<<<dim3(1, MB), 256>>>(attB, g_pW + opW, g_pb + opb, nullptr,
                                          catB, DD, 2*DD, 0);
        // sem spatial attention -> cat[:,128:256]
        gemm_kernel<<<dim3(3, MB), 256>>>(hB, s_qkvW + oqW, s_qkvb + oqb, nullptr,
                                          qkvB, DD, 3*DD, 0);
        spatial_attn_kernel<<<dim3(NN/64, HH, BB*TT), 256>>>(qkvB, attB);
        gemm_kernel<<<dim3(1, MB), 256>>>(attB, s_pW + opW, s_pb + opb, nullptr,
                                          catB + DD, DD, 2*DD, 0);
        // MLP
        gemm_kernel<<<dim3(2, MB), 256>>>(catB, fc1W + (size_t)l*HMM*2*DD, fc1b + (size_t)l*HMM,
                                          nullptr, mlpB, 2*DD, HMM, 1 /*gelu*/);
        gemm_kernel<<<dim3(1, MB), 256>>>(mlpB, fc2W + (size_t)l*DD*HMM, fc2b + (size_t)l*DD,
                                          nullptr, mB, HMM, DD, 0);
        // residual linear + add + layernorm
        gemm_kernel<<<dim3(1, MB), 256>>>(hA, resW + opW, resb + opb, mB,
                                          preB, DD, DD, 0);
        ln_kernel<<<TOK/8, 256>>>(preB, normW + (size_t)l*DD, normb + (size_t)l*DD,
                                  hA, xcB + (size_t)l*DD);
    }

    head_kernel<<<BB*NN, 128>>>(xcB, e1W, e1b, e2W, e2b, out);
}

// round 4
// speedup vs baseline: 1.1941x; 1.1941x over previous
#include <cuda_runtime.h>
#include <cuda_bf16.h>
#include <math.h>
#include <stdint.h>

#define BB   8
#define TT   12
#define NN   512
#define FINN 3
#define DD   128
#define HH   4
#define HMM  256
#define LL   3
#define PP   12
#define TOK  (BB*TT*NN)          // 49152 tokens

typedef __nv_bfloat16 bf16;

// ---------------- fp32 scratch ----------------------------------------------
__device__ float g_qkv[TOK*3*DD];
__device__ float g_m  [TOK*DD];
__device__ float g_pre[TOK*DD];
__device__ float g_xc [TOK*LL*DD];
// ---------------- bf16 hi/lo activation scratch -----------------------------
__device__ bf16 a_hA_hi[TOK*DD];   __device__ bf16 a_hA_lo[TOK*DD];
__device__ bf16 a_hB_hi[TOK*DD];   __device__ bf16 a_hB_lo[TOK*DD];
__device__ bf16 a_at_hi[TOK*DD];   __device__ bf16 a_at_lo[TOK*DD];
__device__ bf16 a_ct_hi[TOK*2*DD]; __device__ bf16 a_ct_lo[TOK*2*DD];
__device__ bf16 a_ml_hi[TOK*HMM];  __device__ bf16 a_ml_lo[TOK*HMM];
// ---------------- bf16 hi/lo weights ----------------------------------------
__device__ bf16 w_tq_hi[LL*3*DD*DD]; __device__ bf16 w_tq_lo[LL*3*DD*DD];
__device__ bf16 w_gq_hi[LL*3*DD*DD]; __device__ bf16 w_gq_lo[LL*3*DD*DD];
__device__ bf16 w_sq_hi[LL*3*DD*DD]; __device__ bf16 w_sq_lo[LL*3*DD*DD];
__device__ bf16 w_tp_hi[LL*DD*DD];   __device__ bf16 w_tp_lo[LL*DD*DD];
__device__ bf16 w_gp_hi[LL*DD*DD];   __device__ bf16 w_gp_lo[LL*DD*DD];
__device__ bf16 w_sp_hi[LL*DD*DD];   __device__ bf16 w_sp_lo[LL*DD*DD];
__device__ bf16 w_rs_hi[LL*DD*DD];   __device__ bf16 w_rs_lo[LL*DD*DD];
__device__ bf16 w_f1_hi[LL*HMM*2*DD];__device__ bf16 w_f1_lo[LL*HMM*2*DD];
__device__ bf16 w_f2_hi[LL*DD*HMM]; __device__ bf16 w_f2_lo[LL*DD*HMM];

__device__ __forceinline__ uint32_t smem_u32(const void* p) {
    uint32_t a;
    asm("{ .reg .u64 t; cvta.to.shared.u64 t, %1; cvt.u32.u64 %0, t; }"
        : "=r"(a) : "l"(p));
    return a;
}

// ================= weight fp32 -> bf16 hi/lo conversion ======================
__global__ void cvt_kernel(const float* __restrict__ src, bf16* __restrict__ hi,
                           bf16* __restrict__ lo, int n)
{
    int i = blockIdx.x * 256 + threadIdx.x;
    if (i < n) {
        float x = src[i];
        bf16 h = __float2bfloat16(x);
        hi[i] = h;
        lo[i] = __float2bfloat16(x - __bfloat162float(h));
    }
}

// ================= mma.sync GEMM: C = act(A @ W^T + bias [+extra]) ==========
// A: hi/lo bf16 [M,K]; W: hi/lo bf16 [N,K]; 3 passes hi*hi + hi*lo + lo*hi
// accumulated in fp32 registers. grid=(N/128, M/128), 256 threads (8 warps 2x4).
__global__ void __launch_bounds__(256, 2)
mma_gemm(const bf16* __restrict__ Ahi, const bf16* __restrict__ Alo,
         const bf16* __restrict__ Whi, const bf16* __restrict__ Wlo,
         const float* __restrict__ bias, const float* __restrict__ extra,
         int K, float* __restrict__ outf, bf16* __restrict__ ohi,
         bf16* __restrict__ olo, int ldo, int gelu)
{
    __shared__ bf16 As[2][128][40];   // 40-halves stride: conflict-free ldmatrix
    __shared__ bf16 Bs[2][128][40];

    const int tid  = threadIdx.x;
    const int wid  = tid >> 5;
    const int lane = tid & 31;
    const int warp_m = wid >> 2;      // 0..1  -> 64-row slab
    const int warp_n = wid & 3;       // 0..3  -> 32-col slab
    const int m0 = blockIdx.y * 128;
    const int n0 = blockIdx.x * 128;

    float acc[4][4][4];
#pragma unroll
    for (int mi = 0; mi < 4; ++mi)
#pragma unroll
        for (int ni = 0; ni < 4; ++ni)
#pragma unroll
            for (int r = 0; r < 4; ++r) acc[mi][ni][r] = 0.f;

    const int KC = K >> 5;            // 32-wide K chunks per pass
    const int NI = 3 * KC;

    auto load_chunk = [&](int buf, int i) {
        const int pass = i / KC, kp = i - pass * KC;
        const bf16* Asrc = (pass < 2)  ? Ahi : Alo;
        const bf16* Bsrc = (pass == 1) ? Wlo : Whi;
        const int kof = kp * 32;
#pragma unroll
        for (int t = 0; t < 2; ++t) {
            const int c   = tid + t * 256;      // 0..511 16B-chunks
            const int row = c >> 2;
            const int cc  = c & 3;
            uint4 va = *(const uint4*)(Asrc + (size_t)(m0 + row) * K + kof + cc * 8);
            uint4 vb = *(const uint4*)(Bsrc + (size_t)(n0 + row) * K + kof + cc * 8);
            *(uint4*)(&As[buf][row][cc * 8]) = va;
            *(uint4*)(&Bs[buf][row][cc * 8]) = vb;
        }
    };

    auto compute = [&](int buf) {
#pragma unroll
        for (int ks = 0; ks < 2; ++ks) {
            const int k = ks * 16;
            uint32_t a[4][4], b[4][2];
#pragma unroll
            for (int mi = 0; mi < 4; ++mi) {
                const int row = warp_m * 64 + mi * 16 + (lane & 15);
                const int col = k + (lane >> 4) * 8;
                uint32_t ad = smem_u32(&As[buf][row][col]);
                asm volatile("ldmatrix.sync.aligned.m8n8.x4.shared.b16 {%0,%1,%2,%3}, [%4];"
                             : "=r"(a[mi][0]), "=r"(a[mi][1]), "=r"(a[mi][2]), "=r"(a[mi][3])
                             : "r"(ad));
            }
#pragma unroll
            for (int ni = 0; ni < 4; ++ni) {
                const int l16 = lane & 15;
                const int row = warp_n * 32 + ni * 8 + (l16 & 7);
                const int col = k + (l16 >> 3) * 8;
                uint32_t bd = smem_u32(&Bs[buf][row][col]);
                asm volatile("ldmatrix.sync.aligned.m8n8.x2.shared.b16 {%0,%1}, [%2];"
                             : "=r"(b[ni][0]), "=r"(b[ni][1]) : "r"(bd));
            }
#pragma unroll
            for (int mi = 0; mi < 4; ++mi)
#pragma unroll
                for (int ni = 0; ni < 4; ++ni) {
                    asm volatile(
                        "mma.sync.aligned.m16n8k16.row.col.f32.bf16.bf16.f32 "
                        "{%0,%1,%2,%3}, {%4,%5,%6,%7}, {%8,%9}, {%0,%1,%2,%3};"
                        : "+f"(acc[mi][ni][0]), "+f"(acc[mi][ni][1]),
                          "+f"(acc[mi][ni][2]), "+f"(acc[mi][ni][3])
                        : "r"(a[mi][0]), "r"(a[mi][1]), "r"(a[mi][2]), "r"(a[mi][3]),
                          "r"(b[ni][0]), "r"(b[ni][1]));
                }
        }
    };

    load_chunk(0, 0);
    __syncthreads();
    int buf = 0;
    for (int i = 0; i < NI; ++i) {
        if (i + 1 < NI) load_chunk(buf ^ 1, i + 1);
        compute(buf);
        __syncthreads();
        buf ^= 1;
    }

    // ---- epilogue: registers -> bias/extra/gelu -> global -------------------
    const int quad = lane >> 2, qi = lane & 3;
#pragma unroll
    for (int mi = 0; mi < 4; ++mi)
#pragma unroll
        for (int ni = 0; ni < 4; ++ni)
#pragma unroll
            for (int h = 0; h < 2; ++h) {
                const int row = m0 + warp_m * 64 + mi * 16 + quad + h * 8;
                const int col = n0 + warp_n * 32 + ni * 8 + qi * 2;
                float v0 = acc[mi][ni][h * 2 + 0] + bias[col];
                float v1 = acc[mi][ni][h * 2 + 1] + bias[col + 1];
                const size_t o = (size_t)row * ldo + col;
                if (extra) { v0 += extra[o]; v1 += extra[o + 1]; }
                if (gelu) {
                    v0 = 0.5f * v0 * (1.0f + erff(v0 * 0.70710678118654752f));
                    v1 = 0.5f * v1 * (1.0f + erff(v1 * 0.70710678118654752f));
                }
                if (outf) { outf[o] = v0; outf[o + 1] = v1; }
                if (ohi) {
                    bf16 h0 = __float2bfloat16(v0), h1 = __float2bfloat16(v1);
                    ohi[o]     = h0; olo[o]     = __float2bfloat16(v0 - __bfloat162float(h0));
                    ohi[o + 1] = h1; olo[o + 1] = __float2bfloat16(v1 - __bfloat162float(h1));
                }
            }
}

// ---------------- embedding + positional encoding (writes hi/lo) ------------
__global__ void embed_kernel(const float* __restrict__ x,
                             const float* __restrict__ tokW,
                             const float* __restrict__ tokb,
                             bf16* __restrict__ hhi, bf16* __restrict__ hlo)
{
    size_t idx = (size_t)blockIdx.x * 256 + threadIdx.x;   // token*128 + d
    size_t token = idx >> 7;
    int d = (int)(idx & 127);
    int t = (int)((token / NN) % TT);
    const float* xp = x + token * FINN;
    float val = xp[0]*tokW[d*3+0] + xp[1]*tokW[d*3+1] + xp[2]*tokW[d*3+2] + tokb[d];
    int i2 = d & ~1;
    float div = expf((float)i2 * (-logf(10000.0f) / (float)DD));
    float ang = (float)t * div;
    val += (d & 1) ? cosf(ang) : sinf(ang);
    bf16 h = __float2bfloat16(val);
    hhi[idx] = h;
    hlo[idx] = __float2bfloat16(val - __bfloat162float(h));
}

// ---------------- temporal attention (over T=12) — writes hi/lo -------------
__global__ void temporal_attn_kernel(const float* __restrict__ qkv,
                                     bf16* __restrict__ ohi, bf16* __restrict__ olo)
{
    const int bidx = blockIdx.x;        // b*512 + n
    const int b = bidx >> 9, n = bidx & 511;
    const int tid = threadIdx.x;        // 128
    __shared__ float q[TT][DD], k[TT][DD], v[TT][DD];
    __shared__ float S[HH][TT][TT];
#pragma unroll
    for (int t = 0; t < TT; ++t) {
        size_t row = ((size_t)(b*TT + t) * NN + n) * 384;
        q[t][tid] = qkv[row + tid];
        k[t][tid] = qkv[row + 128 + tid];
        v[t][tid] = qkv[row + 256 + tid];
    }
    __syncthreads();
    const float scale = 0.17677669529663687f;   // 1/sqrt(32)
    for (int idx = tid; idx < HH*TT*TT; idx += 128) {
        int hh = idx / (TT*TT);
        int rem = idx - hh*(TT*TT);
        int xx = rem / TT, yy = rem - xx*TT;
        float s = 0.f;
#pragma unroll
        for (int e = 0; e < 32; ++e)
            s = fmaf(q[xx][hh*32+e], k[yy][hh*32+e], s);
        S[hh][xx][yy] = s * scale;
    }
    __syncthreads();
    if (tid < HH*TT) {
        int hh = tid / TT, xx = tid % TT;
        float mx = -1e30f;
#pragma unroll
        for (int y = 0; y < TT; ++y) mx = fmaxf(mx, S[hh][xx][y]);
        float sum = 0.f;
#pragma unroll
        for (int y = 0; y < TT; ++y) { float p = __expf(S[hh][xx][y]-mx); S[hh][xx][y] = p; sum += p; }
        float inv = 1.f / sum;
#pragma unroll
        for (int y = 0; y < TT; ++y) S[hh][xx][y] *= inv;
    }
    __syncthreads();
    const int hh = tid >> 5;
    for (int xx = 0; xx < TT; ++xx) {
        float o = 0.f;
#pragma unroll
        for (int yy = 0; yy < TT; ++yy) o = fmaf(S[hh][xx][yy], v[yy][tid], o);
        size_t oi = ((size_t)(b*TT + xx) * NN + n) * DD + tid;
        bf16 h = __float2bfloat16(o);
        ohi[oi] = h;
        olo[oi] = __float2bfloat16(o - __bfloat162float(h));
    }
}

// ---------------- spatial attention (over N=512) — writes hi/lo -------------
__global__ void spatial_attn_kernel(const float* __restrict__ qkv,
                                    bf16* __restrict__ outhi, bf16* __restrict__ outlo)
{
    const int qtile = blockIdx.x;     // 8
    const int head  = blockIdx.y;     // 4
    const int bt    = blockIdx.z;     // 96
    const int tid = threadIdx.x;
    const int ty = tid >> 4, tx = tid & 15;

    __shared__ float Qs[32][64];
    __shared__ float Ks[32][64];
    __shared__ float Vs[64][32];
    __shared__ float Ps[64][68];

    const size_t base = (size_t)bt * NN;
    const float* qb = qkv + (base + (size_t)qtile*64) * 384 + head*32;
    for (int i = tid; i < 64*32; i += 256) {
        int r = i >> 5, e = i & 31;
        Qs[e][r] = qb[(size_t)r*384 + e];
    }

    float m[4], l[4], acc0[4], acc1[4];
#pragma unroll
    for (int r = 0; r < 4; ++r) { m[r] = -1e30f; l[r] = 0.f; acc0[r] = 0.f; acc1[r] = 0.f; }
    const float scale = 0.17677669529663687f;

    for (int kt = 0; kt < NN/64; ++kt) {
        __syncthreads();
        const float* kb = qkv + (base + (size_t)kt*64) * 384 + 128 + head*32;
        const float* vb = kb + 128;
        for (int i = tid; i < 64*32; i += 256) {
            int r = i >> 5, e = i & 31;
            Ks[e][r] = kb[(size_t)r*384 + e];
            Vs[r][e] = vb[(size_t)r*384 + e];
        }
        __syncthreads();

        float s[4][4];
#pragma unroll
        for (int r = 0; r < 4; ++r)
#pragma unroll
            for (int c = 0; c < 4; ++c) s[r][c] = 0.f;
#pragma unroll
        for (int e = 0; e < 32; ++e) {
            float4 qa = *(const float4*)(&Qs[e][ty*4]);
            float4 ka = *(const float4*)(&Ks[e][tx*4]);
            float aa[4] = {qa.x, qa.y, qa.z, qa.w};
            float bb[4] = {ka.x, ka.y, ka.z, ka.w};
#pragma unroll
            for (int r = 0; r < 4; ++r)
#pragma unroll
                for (int c = 0; c < 4; ++c)
                    s[r][c] = fmaf(aa[r], bb[c], s[r][c]);
        }
#pragma unroll
        for (int r = 0; r < 4; ++r) {
            float rm = -1e30f;
#pragma unroll
            for (int c = 0; c < 4; ++c) { s[r][c] *= scale; rm = fmaxf(rm, s[r][c]); }
#pragma unroll
            for (int off = 8; off; off >>= 1)
                rm = fmaxf(rm, __shfl_xor_sync(0xffffffffu, rm, off));
            float nm = fmaxf(m[r], rm);
            float corr = __expf(m[r] - nm);
            m[r] = nm;
            float rs = 0.f;
#pragma unroll
            for (int c = 0; c < 4; ++c) {
                float p = __expf(s[r][c] - nm);
                Ps[tx*4 + c][ty*4 + r] = p;
                rs += p;
            }
#pragma unroll
            for (int off = 8; off; off >>= 1)
                rs += __shfl_xor_sync(0xffffffffu, rs, off);
            l[r] = l[r]*corr + rs;
            acc0[r] *= corr; acc1[r] *= corr;
        }
        __syncthreads();
#pragma unroll 4
        for (int j = 0; j < 64; ++j) {
            float4 p4 = *(const float4*)(&Ps[j][ty*4]);
            float2 v2 = *(const float2*)(&Vs[j][tx*2]);
            acc0[0] = fmaf(p4.x, v2.x, acc0[0]); acc1[0] = fmaf(p4.x, v2.y, acc1[0]);
            acc0[1] = fmaf(p4.y, v2.x, acc0[1]); acc1[1] = fmaf(p4.y, v2.y, acc1[1]);
            acc0[2] = fmaf(p4.z, v2.x, acc0[2]); acc1[2] = fmaf(p4.z, v2.y, acc1[2]);
            acc0[3] = fmaf(p4.w, v2.x, acc0[3]); acc1[3] = fmaf(p4.w, v2.y, acc1[3]);
        }
    }
#pragma unroll
    for (int r = 0; r < 4; ++r) {
        float inv = 1.f / l[r];
        size_t row = base + (size_t)qtile*64 + ty*4 + r;
        size_t oi = row*DD + head*32 + tx*2;
        float v0 = acc0[r]*inv, v1 = acc1[r]*inv;
        bf16 h0 = __float2bfloat16(v0), h1 = __float2bfloat16(v1);
        outhi[oi]   = h0; outlo[oi]   = __float2bfloat16(v0 - __bfloat162float(h0));
        outhi[oi+1] = h1; outlo[oi+1] = __float2bfloat16(v1 - __bfloat162float(h1));
    }
}

// ---------------- layernorm — writes hi/lo + fp32 slice of xc ---------------
__global__ void ln_kernel(const float* __restrict__ pre, const float* __restrict__ g,
                          const float* __restrict__ bta,
                          bf16* __restrict__ hhi, bf16* __restrict__ hlo,
                          float* __restrict__ xc /* pre-offset by l*128 */)
{
    const int warp = threadIdx.x >> 5, lane = threadIdx.x & 31;
    size_t token = (size_t)blockIdx.x * 8 + warp;
    const float* p = pre + token * DD;
    float v[4];
#pragma unroll
    for (int i = 0; i < 4; ++i) v[i] = p[lane + 32*i];
    float s = v[0] + v[1] + v[2] + v[3];
#pragma unroll
    for (int o = 16; o; o >>= 1) s += __shfl_xor_sync(0xffffffffu, s, o);
    float mean = s * (1.f/128.f);
    float q = 0.f;
#pragma unroll
    for (int i = 0; i < 4; ++i) { v[i] -= mean; q += v[i]*v[i]; }
#pragma unroll
    for (int o = 16; o; o >>= 1) q += __shfl_xor_sync(0xffffffffu, q, o);
    float inv = rsqrtf(q * (1.f/128.f) + 1e-5f);
#pragma unroll
    for (int i = 0; i < 4; ++i) {
        int d = lane + 32*i;
        float o = v[i] * inv * g[d] + bta[d];
        bf16 h = __float2bfloat16(o);
        hhi[token*DD + d] = h;
        hlo[token*DD + d] = __float2bfloat16(o - __bfloat162float(h));
        xc[token*(LL*DD) + d] = o;
    }
}

// ---------------- output head ------------------------------------------------
__global__ void head_kernel(const float* __restrict__ xc, const float* __restrict__ w1g,
                            const float* __restrict__ b1g, const float* __restrict__ w2g,
                            const float* __restrict__ b2g, float* __restrict__ y)
{
    const int bidx = blockIdx.x;          // b*512 + n
    const int b = bidx >> 9, n = bidx & 511;
    const int tid = threadIdx.x;          // 128
    __shared__ float xs[TT][LL*DD];
    __shared__ float w1[PP][TT];
    __shared__ float b1[PP];
    __shared__ float w2[LL*DD];
    __shared__ float red[PP][4];
    for (int t = 0; t < TT; ++t) {
        size_t rowoff = ((size_t)(b*TT + t) * NN + n) * (LL*DD);
        for (int c = tid; c < LL*DD; c += 128) xs[t][c] = xc[rowoff + c];
    }
    for (int i = tid; i < PP*TT; i += 128) w1[i/TT][i%TT] = w1g[i];
    if (tid < PP) b1[tid] = b1g[tid];
    for (int c = tid; c < LL*DD; c += 128) w2[c] = w2g[c];
    __syncthreads();

    float part[PP];
#pragma unroll
    for (int p = 0; p < PP; ++p) part[p] = 0.f;
    for (int c = tid; c < LL*DD; c += 128) {
        float xt[TT];
#pragma unroll
        for (int t = 0; t < TT; ++t) xt[t] = xs[t][c];
        float wc = w2[c];
#pragma unroll
        for (int p = 0; p < PP; ++p) {
            float sacc = b1[p];
#pragma unroll
            for (int t = 0; t < TT; ++t) sacc = fmaf(xt[t], w1[p][t], sacc);
            sacc = fmaxf(sacc, 0.f);
            part[p] = fmaf(sacc, wc, part[p]);
        }
    }
    const int warp = tid >> 5, lane = tid & 31;
#pragma unroll
    for (int p = 0; p < PP; ++p) {
        float sv = part[p];
#pragma unroll
        for (int o = 16; o; o >>= 1) sv += __shfl_xor_sync(0xffffffffu, sv, o);
        if (lane == 0) red[p][warp] = sv;
    }
    __syncthreads();
    if (tid < PP) {
        float sv = red[tid][0] + red[tid][1] + red[tid][2] + red[tid][3];
        y[(size_t)(b*PP + tid) * NN + n] = sv + b2g[0];
    }
}

// ---------------- launcher ---------------------------------------------------
extern "C" void kernel_launch(void* const* d_in, const int* in_sizes, int n_in,
                              void* d_out, int out_size)
{
    (void)in_sizes; (void)n_in; (void)out_size;
    const float* x      = (const float*)d_in[0];
    const float* tokW   = (const float*)d_in[1];
    const float* tokb   = (const float*)d_in[2];
    const float* t_qkvW = (const float*)d_in[3];
    const float* t_qkvb = (const float*)d_in[4];
    const float* t_pW   = (const float*)d_in[5];
    const float* t_pb   = (const float*)d_in[6];
    const float* g_qkvW = (const float*)d_in[7];
    const float* g_qkvb = (const float*)d_in[8];
    const float* g_pW   = (const float*)d_in[9];
    const float* g_pb   = (const float*)d_in[10];
    const float* s_qkvW = (const float*)d_in[11];
    const float* s_qkvb = (const float*)d_in[12];
    const float* s_pW   = (const float*)d_in[13];
    const float* s_pb   = (const float*)d_in[14];
    const float* resW   = (const float*)d_in[15];
    const float* resb   = (const float*)d_in[16];
    const float* normW  = (const float*)d_in[17];
    const float* normb  = (const float*)d_in[18];
    const float* fc1W   = (const float*)d_in[19];
    const float* fc1b   = (const float*)d_in[20];
    const float* fc2W   = (const float*)d_in[21];
    const float* fc2b   = (const float*)d_in[22];
    const float* e1W    = (const float*)d_in[23];
    const float* e1b    = (const float*)d_in[24];
    const float* e2W    = (const float*)d_in[25];
    const float* e2b    = (const float*)d_in[26];
    float* out = (float*)d_out;

    float *qkvB, *mB, *preB, *xcB;
    cudaGetSymbolAddress((void**)&qkvB, g_qkv);
    cudaGetSymbolAddress((void**)&mB,   g_m);
    cudaGetSymbolAddress((void**)&preB, g_pre);
    cudaGetSymbolAddress((void**)&xcB,  g_xc);

    bf16 *hAh,*hAl,*hBh,*hBl,*ath,*atl,*cth,*ctl,*mlh,*mll;
    cudaGetSymbolAddress((void**)&hAh, a_hA_hi); cudaGetSymbolAddress((void**)&hAl, a_hA_lo);
    cudaGetSymbolAddress((void**)&hBh, a_hB_hi); cudaGetSymbolAddress((void**)&hBl, a_hB_lo);
    cudaGetSymbolAddress((void**)&ath, a_at_hi); cudaGetSymbolAddress((void**)&atl, a_at_lo);
    cudaGetSymbolAddress((void**)&cth, a_ct_hi); cudaGetSymbolAddress((void**)&ctl, a_ct_lo);
    cudaGetSymbolAddress((void**)&mlh, a_ml_hi); cudaGetSymbolAddress((void**)&mll, a_ml_lo);

    bf16 *tqh,*tql,*gqh,*gql,*sqh,*sql,*tph,*tpl,*gph,*gpl,*sph,*spl,*rsh,*rsl,*f1h,*f1l,*f2h,*f2l;
    cudaGetSymbolAddress((void**)&tqh, w_tq_hi); cudaGetSymbolAddress((void**)&tql, w_tq_lo);
    cudaGetSymbolAddress((void**)&gqh, w_gq_hi); cudaGetSymbolAddress((void**)&gql, w_gq_lo);
    cudaGetSymbolAddress((void**)&sqh, w_sq_hi); cudaGetSymbolAddress((void**)&sql, w_sq_lo);
    cudaGetSymbolAddress((void**)&tph, w_tp_hi); cudaGetSymbolAddress((void**)&tpl, w_tp_lo);
    cudaGetSymbolAddress((void**)&gph, w_gp_hi); cudaGetSymbolAddress((void**)&gpl, w_gp_lo);
    cudaGetSymbolAddress((void**)&sph, w_sp_hi); cudaGetSymbolAddress((void**)&spl, w_sp_lo);
    cudaGetSymbolAddress((void**)&rsh, w_rs_hi); cudaGetSymbolAddress((void**)&rsl, w_rs_lo);
    cudaGetSymbolAddress((void**)&f1h, w_f1_hi); cudaGetSymbolAddress((void**)&f1l, w_f1_lo);
    cudaGetSymbolAddress((void**)&f2h, w_f2_hi); cudaGetSymbolAddress((void**)&f2l, w_f2_lo);

    // weight conversions
    const int NQ = LL*3*DD*DD, NPw = LL*DD*DD, NF1 = LL*HMM*2*DD, NF2 = LL*DD*HMM;
    cvt_kernel<<<(NQ+255)/256,256>>>(t_qkvW, tqh, tql, NQ);
    cvt_kernel<<<(NQ+255)/256,256>>>(g_qkvW, gqh, gql, NQ);
    cvt_kernel<<<(NQ+255)/256,256>>>(s_qkvW, sqh, sql, NQ);
    cvt_kernel<<<(NPw+255)/256,256>>>(t_pW, tph, tpl, NPw);
    cvt_kernel<<<(NPw+255)/256,256>>>(g_pW, gph, gpl, NPw);
    cvt_kernel<<<(NPw+255)/256,256>>>(s_pW, sph, spl, NPw);
    cvt_kernel<<<(NPw+255)/256,256>>>(resW, rsh, rsl, NPw);
    cvt_kernel<<<(NF1+255)/256,256>>>(fc1W, f1h, f1l, NF1);
    cvt_kernel<<<(NF2+255)/256,256>>>(fc2W, f2h, f2l, NF2);

    const int MBt = TOK / 128;   // 384 row tiles

    embed_kernel<<<(TOK*DD)/256, 256>>>(x, tokW, tokb, hAh, hAl);

    for (int l = 0; l < LL; ++l) {
        const size_t oq = (size_t)l*3*DD*DD, oqb = (size_t)l*3*DD;
        const size_t op = (size_t)l*DD*DD,   opb = (size_t)l*DD;

        // temporal attention
        mma_gemm<<<dim3(3, MBt), 256>>>(hAh, hAl, tqh+oq, tql+oq, t_qkvb+oqb,
                                        nullptr, DD, qkvB, nullptr, nullptr, 3*DD, 0);
        temporal_attn_kernel<<<BB*NN, 128>>>(qkvB, ath, atl);
        mma_gemm<<<dim3(1, MBt), 256>>>(ath, atl, tph+op, tpl+op, t_pb+opb,
                                        nullptr, DD, nullptr, hBh, hBl, DD, 0);
        // geo spatial attention -> cat[:,0:128]
        mma_gemm<<<dim3(3, MBt), 256>>>(hBh, hBl, gqh+oq, gql+oq, g_qkvb+oqb,
                                        nullptr, DD, qkvB, nullptr, nullptr, 3*DD, 0);
        spatial_attn_kernel<<<dim3(NN/64, HH, BB*TT), 256>>>(qkvB, ath, atl);
        mma_gemm<<<dim3(1, MBt), 256>>>(ath, atl, gph+op, gpl+op, g_pb+opb,
                                        nullptr, DD, nullptr, cth, ctl, 2*DD, 0);
        // sem spatial attention -> cat[:,128:256]
        mma_gemm<<<dim3(3, MBt), 256>>>(hBh, hBl, sqh+oq, sql+oq, s_qkvb+oqb,
                                        nullptr, DD, qkvB, nullptr, nullptr, 3*DD, 0);
        spatial_attn_kernel<<<dim3(NN/64, HH, BB*TT), 256>>>(qkvB, ath, atl);
        mma_gemm<<<dim3(1, MBt), 256>>>(ath, atl, sph+op, spl+op, s_pb+opb,
                                        nullptr, DD, nullptr, cth+DD, ctl+DD, 2*DD, 0);
        // MLP
        mma_gemm<<<dim3(2, MBt), 256>>>(cth, ctl, f1h+(size_t)l*HMM*2*DD, f1l+(size_t)l*HMM*2*DD,
                                        fc1b+(size_t)l*HMM, nullptr, 2*DD,
                                        nullptr, mlh, mll, HMM, 1 /*gelu*/);
        mma_gemm<<<dim3(1, MBt), 256>>>(mlh, mll, f2h+(size_t)l*DD*HMM, f2l+(size_t)l*DD*HMM,
                                        fc2b+opb, nullptr, HMM, mB, nullptr, nullptr, DD, 0);
        // residual linear + add + layernorm
        mma_gemm<<<dim3(1, MBt), 256>>>(hAh, hAl, rsh+op, rsl+op, resb+opb,
                                        mB, DD, preB, nullptr, nullptr, DD, 0);
        ln_kernel<<<TOK/8, 256>>>(preB, normW+opb, normb+opb, hAh, hAl, xcB + (size_t)l*DD);
    }

    head_kernel<<<BB*NN, 128>>>(xcB, e1W, e1b, e2W, e2b, out);
}

// round 5
// speedup vs baseline: 1.8807x; 1.5750x over previous
#include <cuda_runtime.h>
#include <cuda_bf16.h>
#include <cuda_fp16.h>
#include <math.h>
#include <stdint.h>

#define BB   8
#define TT   12
#define NN   512
#define FINN 3
#define DD   128
#define HH   4
#define HMM  256
#define LL   3
#define PP   12
#define TOK  (BB*TT*NN)          // 49152 tokens

typedef __nv_bfloat16 bf16;

// ---------------- fp32 scratch ----------------------------------------------
__device__ float g_qkv[TOK*3*DD];
__device__ float g_m  [TOK*DD];
__device__ float g_pre[TOK*DD];
__device__ float g_xc [TOK*LL*DD];
// ---------------- bf16 hi/lo activation scratch -----------------------------
__device__ bf16 a_hA_hi[TOK*DD];   __device__ bf16 a_hA_lo[TOK*DD];
__device__ bf16 a_hB_hi[TOK*DD];   __device__ bf16 a_hB_lo[TOK*DD];
__device__ bf16 a_at_hi[TOK*DD];   __device__ bf16 a_at_lo[TOK*DD];
__device__ bf16 a_ct_hi[TOK*2*DD]; __device__ bf16 a_ct_lo[TOK*2*DD];
__device__ bf16 a_ml_hi[TOK*HMM];  __device__ bf16 a_ml_lo[TOK*HMM];
// ---------------- bf16 hi/lo weights ----------------------------------------
__device__ bf16 w_tq_hi[LL*3*DD*DD]; __device__ bf16 w_tq_lo[LL*3*DD*DD];
__device__ bf16 w_gq_hi[LL*3*DD*DD]; __device__ bf16 w_gq_lo[LL*3*DD*DD];
__device__ bf16 w_sq_hi[LL*3*DD*DD]; __device__ bf16 w_sq_lo[LL*3*DD*DD];
__device__ bf16 w_tp_hi[LL*DD*DD];   __device__ bf16 w_tp_lo[LL*DD*DD];
__device__ bf16 w_gp_hi[LL*DD*DD];   __device__ bf16 w_gp_lo[LL*DD*DD];
__device__ bf16 w_sp_hi[LL*DD*DD];   __device__ bf16 w_sp_lo[LL*DD*DD];
__device__ bf16 w_rs_hi[LL*DD*DD];   __device__ bf16 w_rs_lo[LL*DD*DD];
__device__ bf16 w_f1_hi[LL*HMM*2*DD];__device__ bf16 w_f1_lo[LL*HMM*2*DD];
__device__ bf16 w_f2_hi[LL*DD*HMM]; __device__ bf16 w_f2_lo[LL*DD*HMM];

__device__ __forceinline__ uint32_t smem_u32(const void* p) {
    uint32_t a;
    asm("{ .reg .u64 t; cvta.to.shared.u64 t, %1; cvt.u32.u64 %0, t; }"
        : "=r"(a) : "l"(p));
    return a;
}
__device__ __forceinline__ uint32_t pack2h(float a, float b) {
    __half2 h = __floats2half2_rn(a, b);
    return *(uint32_t*)&h;
}

// ================= weight fp32 -> bf16 hi/lo conversion ======================
__global__ void cvt_kernel(const float* __restrict__ src, bf16* __restrict__ hi,
                           bf16* __restrict__ lo, int n)
{
    int i = blockIdx.x * 256 + threadIdx.x;
    if (i < n) {
        float x = src[i];
        bf16 h = __float2bfloat16(x);
        hi[i] = h;
        lo[i] = __float2bfloat16(x - __bfloat162float(h));
    }
}

// ================= mma.sync GEMM: C = act(A @ W^T + bias [+extra]) ==========
__global__ void __launch_bounds__(256, 2)
mma_gemm(const bf16* __restrict__ Ahi, const bf16* __restrict__ Alo,
         const bf16* __restrict__ Whi, const bf16* __restrict__ Wlo,
         const float* __restrict__ bias, const float* __restrict__ extra,
         int K, float* __restrict__ outf, bf16* __restrict__ ohi,
         bf16* __restrict__ olo, int ldo, int gelu)
{
    __shared__ bf16 As[2][128][40];
    __shared__ bf16 Bs[2][128][40];

    const int tid  = threadIdx.x;
    const int wid  = tid >> 5;
    const int lane = tid & 31;
    const int warp_m = wid >> 2;
    const int warp_n = wid & 3;
    const int m0 = blockIdx.y * 128;
    const int n0 = blockIdx.x * 128;

    float acc[4][4][4];
#pragma unroll
    for (int mi = 0; mi < 4; ++mi)
#pragma unroll
        for (int ni = 0; ni < 4; ++ni)
#pragma unroll
            for (int r = 0; r < 4; ++r) acc[mi][ni][r] = 0.f;

    const int KC = K >> 5;
    const int NI = 3 * KC;

    auto load_chunk = [&](int buf, int i) {
        const int pass = i / KC, kp = i - pass * KC;
        const bf16* Asrc = (pass < 2)  ? Ahi : Alo;
        const bf16* Bsrc = (pass == 1) ? Wlo : Whi;
        const int kof = kp * 32;
#pragma unroll
        for (int t = 0; t < 2; ++t) {
            const int c   = tid + t * 256;
            const int row = c >> 2;
            const int cc  = c & 3;
            uint4 va = *(const uint4*)(Asrc + (size_t)(m0 + row) * K + kof + cc * 8);
            uint4 vb = *(const uint4*)(Bsrc + (size_t)(n0 + row) * K + kof + cc * 8);
            *(uint4*)(&As[buf][row][cc * 8]) = va;
            *(uint4*)(&Bs[buf][row][cc * 8]) = vb;
        }
    };

    auto compute = [&](int buf) {
#pragma unroll
        for (int ks = 0; ks < 2; ++ks) {
            const int k = ks * 16;
            uint32_t a[4][4], b[4][2];
#pragma unroll
            for (int mi = 0; mi < 4; ++mi) {
                const int row = warp_m * 64 + mi * 16 + (lane & 15);
                const int col = k + (lane >> 4) * 8;
                uint32_t ad = smem_u32(&As[buf][row][col]);
                asm volatile("ldmatrix.sync.aligned.m8n8.x4.shared.b16 {%0,%1,%2,%3}, [%4];"
                             : "=r"(a[mi][0]), "=r"(a[mi][1]), "=r"(a[mi][2]), "=r"(a[mi][3])
                             : "r"(ad));
            }
#pragma unroll
            for (int ni = 0; ni < 4; ++ni) {
                const int l16 = lane & 15;
                const int row = warp_n * 32 + ni * 8 + (l16 & 7);
                const int col = k + (l16 >> 3) * 8;
                uint32_t bd = smem_u32(&Bs[buf][row][col]);
                asm volatile("ldmatrix.sync.aligned.m8n8.x2.shared.b16 {%0,%1}, [%2];"
                             : "=r"(b[ni][0]), "=r"(b[ni][1]) : "r"(bd));
            }
#pragma unroll
            for (int mi = 0; mi < 4; ++mi)
#pragma unroll
                for (int ni = 0; ni < 4; ++ni) {
                    asm volatile(
                        "mma.sync.aligned.m16n8k16.row.col.f32.bf16.bf16.f32 "
                        "{%0,%1,%2,%3}, {%4,%5,%6,%7}, {%8,%9}, {%0,%1,%2,%3};"
                        : "+f"(acc[mi][ni][0]), "+f"(acc[mi][ni][1]),
                          "+f"(acc[mi][ni][2]), "+f"(acc[mi][ni][3])
                        : "r"(a[mi][0]), "r"(a[mi][1]), "r"(a[mi][2]), "r"(a[mi][3]),
                          "r"(b[ni][0]), "r"(b[ni][1]));
                }
        }
    };

    load_chunk(0, 0);
    __syncthreads();
    int buf = 0;
    for (int i = 0; i < NI; ++i) {
        if (i + 1 < NI) load_chunk(buf ^ 1, i + 1);
        compute(buf);
        __syncthreads();
        buf ^= 1;
    }

    const int quad = lane >> 2, qi = lane & 3;
#pragma unroll
    for (int mi = 0; mi < 4; ++mi)
#pragma unroll
        for (int ni = 0; ni < 4; ++ni)
#pragma unroll
            for (int h = 0; h < 2; ++h) {
                const int row = m0 + warp_m * 64 + mi * 16 + quad + h * 8;
                const int col = n0 + warp_n * 32 + ni * 8 + qi * 2;
                float v0 = acc[mi][ni][h * 2 + 0] + bias[col];
                float v1 = acc[mi][ni][h * 2 + 1] + bias[col + 1];
                const size_t o = (size_t)row * ldo + col;
                if (extra) { v0 += extra[o]; v1 += extra[o + 1]; }
                if (gelu) {
                    v0 = 0.5f * v0 * (1.0f + erff(v0 * 0.70710678118654752f));
                    v1 = 0.5f * v1 * (1.0f + erff(v1 * 0.70710678118654752f));
                }
                if (outf) { outf[o] = v0; outf[o + 1] = v1; }
                if (ohi) {
                    bf16 h0 = __float2bfloat16(v0), h1 = __float2bfloat16(v1);
                    ohi[o]     = h0; olo[o]     = __float2bfloat16(v0 - __bfloat162float(h0));
                    ohi[o + 1] = h1; olo[o + 1] = __float2bfloat16(v1 - __bfloat162float(h1));
                }
            }
}

// ---------------- embedding + positional encoding (writes hi/lo) ------------
__global__ void embed_kernel(const float* __restrict__ x,
                             const float* __restrict__ tokW,
                             const float* __restrict__ tokb,
                             bf16* __restrict__ hhi, bf16* __restrict__ hlo)
{
    size_t idx = (size_t)blockIdx.x * 256 + threadIdx.x;
    size_t token = idx >> 7;
    int d = (int)(idx & 127);
    int t = (int)((token / NN) % TT);
    const float* xp = x + token * FINN;
    float val = xp[0]*tokW[d*3+0] + xp[1]*tokW[d*3+1] + xp[2]*tokW[d*3+2] + tokb[d];
    int i2 = d & ~1;
    float div = expf((float)i2 * (-logf(10000.0f) / (float)DD));
    float ang = (float)t * div;
    val += (d & 1) ? cosf(ang) : sinf(ang);
    bf16 h = __float2bfloat16(val);
    hhi[idx] = h;
    hlo[idx] = __float2bfloat16(val - __bfloat162float(h));
}

// ---------------- temporal attention (over T=12) — writes hi/lo -------------
__global__ void temporal_attn_kernel(const float* __restrict__ qkv,
                                     bf16* __restrict__ ohi, bf16* __restrict__ olo)
{
    const int bidx = blockIdx.x;
    const int b = bidx >> 9, n = bidx & 511;
    const int tid = threadIdx.x;
    __shared__ float q[TT][DD], k[TT][DD], v[TT][DD];
    __shared__ float S[HH][TT][TT];
#pragma unroll
    for (int t = 0; t < TT; ++t) {
        size_t row = ((size_t)(b*TT + t) * NN + n) * 384;
        q[t][tid] = qkv[row + tid];
        k[t][tid] = qkv[row + 128 + tid];
        v[t][tid] = qkv[row + 256 + tid];
    }
    __syncthreads();
    const float scale = 0.17677669529663687f;
    for (int idx = tid; idx < HH*TT*TT; idx += 128) {
        int hh = idx / (TT*TT);
        int rem = idx - hh*(TT*TT);
        int xx = rem / TT, yy = rem - xx*TT;
        float s = 0.f;
#pragma unroll
        for (int e = 0; e < 32; ++e)
            s = fmaf(q[xx][hh*32+e], k[yy][hh*32+e], s);
        S[hh][xx][yy] = s * scale;
    }
    __syncthreads();
    if (tid < HH*TT) {
        int hh = tid / TT, xx = tid % TT;
        float mx = -1e30f;
#pragma unroll
        for (int y = 0; y < TT; ++y) mx = fmaxf(mx, S[hh][xx][y]);
        float sum = 0.f;
#pragma unroll
        for (int y = 0; y < TT; ++y) { float p = __expf(S[hh][xx][y]-mx); S[hh][xx][y] = p; sum += p; }
        float inv = 1.f / sum;
#pragma unroll
        for (int y = 0; y < TT; ++y) S[hh][xx][y] *= inv;
    }
    __syncthreads();
    const int hh = tid >> 5;
    for (int xx = 0; xx < TT; ++xx) {
        float o = 0.f;
#pragma unroll
        for (int yy = 0; yy < TT; ++yy) o = fmaf(S[hh][xx][yy], v[yy][tid], o);
        size_t oi = ((size_t)(b*TT + xx) * NN + n) * DD + tid;
        bf16 h = __float2bfloat16(o);
        ohi[oi] = h;
        olo[oi] = __float2bfloat16(o - __bfloat162float(h));
    }
}

// ============ spatial attention via tensor cores (flash, fp16) ==============
// block = 128 queries x (bt, head); 8 warps x 16 rows. 4 key tiles of 128.
__global__ void __launch_bounds__(256, 1)
spatial_attn_mma(const float* __restrict__ qkv,
                 bf16* __restrict__ outhi, bf16* __restrict__ outlo)
{
    const int qtile = blockIdx.x;     // 0..3
    const int head  = blockIdx.y;     // 0..3
    const int bt    = blockIdx.z;     // 0..95
    const int tid  = threadIdx.x;
    const int wid  = tid >> 5;
    const int lane = tid & 31;
    const int l16  = lane & 15;

    __shared__ __half Qs[128][40];    // [q][e], padded
    __shared__ __half Ks[128][40];    // [j][e]
    __shared__ __half Vt[32][136];    // [e][j] transposed, padded

    const size_t base = (size_t)bt * NN;
    const float scale = 0.17677669529663687f;   // folded into Q

    for (int i = tid; i < 128*32; i += 256) {
        int r = i >> 5, e = i & 31;
        Qs[r][e] = __float2half(qkv[(base + (size_t)qtile*128 + r)*384 + head*32 + e] * scale);
    }
    __syncthreads();

    // resident Q fragments: 2 k-chunks of 16
    uint32_t qf[2][4];
#pragma unroll
    for (int kc = 0; kc < 2; ++kc) {
        uint32_t ad = smem_u32(&Qs[wid*16 + l16][kc*16 + (lane>>4)*8]);
        asm volatile("ldmatrix.sync.aligned.m8n8.x4.shared.b16 {%0,%1,%2,%3}, [%4];"
                     : "=r"(qf[kc][0]), "=r"(qf[kc][1]), "=r"(qf[kc][2]), "=r"(qf[kc][3])
                     : "r"(ad));
    }

    float m0 = -1e30f, m1 = -1e30f, l0 = 0.f, l1 = 0.f;
    float oacc[4][4];
#pragma unroll
    for (int ef = 0; ef < 4; ++ef)
#pragma unroll
        for (int r = 0; r < 4; ++r) oacc[ef][r] = 0.f;

    for (int kt = 0; kt < 4; ++kt) {
        __syncthreads();            // previous tile's consumers done
        for (int i = tid; i < 128*32; i += 256) {
            int j = i >> 5, e = i & 31;
            const float* rp = qkv + (base + (size_t)kt*128 + j)*384 + 128 + head*32 + e;
            Ks[j][e] = __float2half(rp[0]);
            Vt[e][j] = __float2half(rp[128]);
        }
        __syncthreads();

        // S = Q.K^T : 16 n-frags of 8 keys
        float sacc[16][4];
#pragma unroll
        for (int nf = 0; nf < 16; ++nf) {
            sacc[nf][0] = sacc[nf][1] = sacc[nf][2] = sacc[nf][3] = 0.f;
#pragma unroll
            for (int kc = 0; kc < 2; ++kc) {
                uint32_t b0, b1;
                uint32_t bd = smem_u32(&Ks[nf*8 + (l16 & 7)][kc*16 + (l16 >> 3)*8]);
                asm volatile("ldmatrix.sync.aligned.m8n8.x2.shared.b16 {%0,%1}, [%2];"
                             : "=r"(b0), "=r"(b1) : "r"(bd));
                asm volatile(
                    "mma.sync.aligned.m16n8k16.row.col.f32.f16.f16.f32 "
                    "{%0,%1,%2,%3}, {%4,%5,%6,%7}, {%8,%9}, {%0,%1,%2,%3};"
                    : "+f"(sacc[nf][0]), "+f"(sacc[nf][1]),
                      "+f"(sacc[nf][2]), "+f"(sacc[nf][3])
                    : "r"(qf[kc][0]), "r"(qf[kc][1]), "r"(qf[kc][2]), "r"(qf[kc][3]),
                      "r"(b0), "r"(b1));
            }
        }

        // row maxes (rows: r0 = lane>>2 for c0/c1, r0+8 for c2/c3)
        float mx0 = -1e30f, mx1 = -1e30f;
#pragma unroll
        for (int nf = 0; nf < 16; ++nf) {
            mx0 = fmaxf(mx0, fmaxf(sacc[nf][0], sacc[nf][1]));
            mx1 = fmaxf(mx1, fmaxf(sacc[nf][2], sacc[nf][3]));
        }
        mx0 = fmaxf(mx0, __shfl_xor_sync(0xffffffffu, mx0, 1));
        mx0 = fmaxf(mx0, __shfl_xor_sync(0xffffffffu, mx0, 2));
        mx1 = fmaxf(mx1, __shfl_xor_sync(0xffffffffu, mx1, 1));
        mx1 = fmaxf(mx1, __shfl_xor_sync(0xffffffffu, mx1, 2));
        const float nm0 = fmaxf(m0, mx0), nm1 = fmaxf(m1, mx1);
        const float c0 = __expf(m0 - nm0), c1 = __expf(m1 - nm1);
        m0 = nm0; m1 = nm1;
#pragma unroll
        for (int ef = 0; ef < 4; ++ef) {
            oacc[ef][0] *= c0; oacc[ef][1] *= c0;
            oacc[ef][2] *= c1; oacc[ef][3] *= c1;
        }

        float rs0 = 0.f, rs1 = 0.f;
#pragma unroll
        for (int jc = 0; jc < 8; ++jc) {            // 16-key chunks
            float p00 = __expf(sacc[2*jc][0]   - nm0);
            float p01 = __expf(sacc[2*jc][1]   - nm0);
            float p10 = __expf(sacc[2*jc][2]   - nm1);
            float p11 = __expf(sacc[2*jc][3]   - nm1);
            float p20 = __expf(sacc[2*jc+1][0] - nm0);
            float p21 = __expf(sacc[2*jc+1][1] - nm0);
            float p30 = __expf(sacc[2*jc+1][2] - nm1);
            float p31 = __expf(sacc[2*jc+1][3] - nm1);
            rs0 += p00 + p01 + p20 + p21;
            rs1 += p10 + p11 + p30 + p31;
            uint32_t pf0 = pack2h(p00, p01);        // C-frag -> A-frag identity
            uint32_t pf1 = pack2h(p10, p11);
            uint32_t pf2 = pack2h(p20, p21);
            uint32_t pf3 = pack2h(p30, p31);
#pragma unroll
            for (int ef = 0; ef < 4; ++ef) {
                uint32_t b0, b1;
                uint32_t bd = smem_u32(&Vt[ef*8 + (l16 & 7)][jc*16 + (l16 >> 3)*8]);
                asm volatile("ldmatrix.sync.aligned.m8n8.x2.shared.b16 {%0,%1}, [%2];"
                             : "=r"(b0), "=r"(b1) : "r"(bd));
                asm volatile(
                    "mma.sync.aligned.m16n8k16.row.col.f32.f16.f16.f32 "
                    "{%0,%1,%2,%3}, {%4,%5,%6,%7}, {%8,%9}, {%0,%1,%2,%3};"
                    : "+f"(oacc[ef][0]), "+f"(oacc[ef][1]),
                      "+f"(oacc[ef][2]), "+f"(oacc[ef][3])
                    : "r"(pf0), "r"(pf1), "r"(pf2), "r"(pf3),
                      "r"(b0), "r"(b1));
            }
        }
        rs0 += __shfl_xor_sync(0xffffffffu, rs0, 1);
        rs0 += __shfl_xor_sync(0xffffffffu, rs0, 2);
        rs1 += __shfl_xor_sync(0xffffffffu, rs1, 1);
        rs1 += __shfl_xor_sync(0xffffffffu, rs1, 2);
        l0 = l0 * c0 + rs0;
        l1 = l1 * c1 + rs1;
    }

    // epilogue: normalize and store hi/lo bf16
    const float i0 = 1.f / l0, i1 = 1.f / l1;
    const int r0 = wid*16 + (lane >> 2);
#pragma unroll
    for (int ef = 0; ef < 4; ++ef) {
        const int col = head*32 + ef*8 + (lane & 3)*2;
        size_t rowA = (base + (size_t)qtile*128 + r0) * DD + col;
        size_t rowB = (base + (size_t)qtile*128 + r0 + 8) * DD + col;
        float v0 = oacc[ef][0] * i0, v1 = oacc[ef][1] * i0;
        float v2 = oacc[ef][2] * i1, v3 = oacc[ef][3] * i1;
        bf16 h0 = __float2bfloat16(v0), h1 = __float2bfloat16(v1);
        bf16 h2 = __float2bfloat16(v2), h3 = __float2bfloat16(v3);
        outhi[rowA]   = h0; outlo[rowA]   = __float2bfloat16(v0 - __bfloat162float(h0));
        outhi[rowA+1] = h1; outlo[rowA+1] = __float2bfloat16(v1 - __bfloat162float(h1));
        outhi[rowB]   = h2; outlo[rowB]   = __float2bfloat16(v2 - __bfloat162float(h2));
        outhi[rowB+1] = h3; outlo[rowB+1] = __float2bfloat16(v3 - __bfloat162float(h3));
    }
}

// ---------------- layernorm — writes hi/lo + fp32 slice of xc ---------------
__global__ void ln_kernel(const float* __restrict__ pre, const float* __restrict__ g,
                          const float* __restrict__ bta,
                          bf16* __restrict__ hhi, bf16* __restrict__ hlo,
                          float* __restrict__ xc)
{
    const int warp = threadIdx.x >> 5, lane = threadIdx.x & 31;
    size_t token = (size_t)blockIdx.x * 8 + warp;
    const float* p = pre + token * DD;
    float v[4];
#pragma unroll
    for (int i = 0; i < 4; ++i) v[i] = p[lane + 32*i];
    float s = v[0] + v[1] + v[2] + v[3];
#pragma unroll
    for (int o = 16; o; o >>= 1) s += __shfl_xor_sync(0xffffffffu, s, o);
    float mean = s * (1.f/128.f);
    float q = 0.f;
#pragma unroll
    for (int i = 0; i < 4; ++i) { v[i] -= mean; q += v[i]*v[i]; }
#pragma unroll
    for (int o = 16; o; o >>= 1) q += __shfl_xor_sync(0xffffffffu, q, o);
    float inv = rsqrtf(q * (1.f/128.f) + 1e-5f);
#pragma unroll
    for (int i = 0; i < 4; ++i) {
        int d = lane + 32*i;
        float o = v[i] * inv * g[d] + bta[d];
        bf16 h = __float2bfloat16(o);
        hhi[token*DD + d] = h;
        hlo[token*DD + d] = __float2bfloat16(o - __bfloat162float(h));
        xc[token*(LL*DD) + d] = o;
    }
}

// ---------------- output head ------------------------------------------------
__global__ void head_kernel(const float* __restrict__ xc, const float* __restrict__ w1g,
                            const float* __restrict__ b1g, const float* __restrict__ w2g,
                            const float* __restrict__ b2g, float* __restrict__ y)
{
    const int bidx = blockIdx.x;
    const int b = bidx >> 9, n = bidx & 511;
    const int tid = threadIdx.x;
    __shared__ float xs[TT][LL*DD];
    __shared__ float w1[PP][TT];
    __shared__ float b1[PP];
    __shared__ float w2[LL*DD];
    __shared__ float red[PP][4];
    for (int t = 0; t < TT; ++t) {
        size_t rowoff = ((size_t)(b*TT + t) * NN + n) * (LL*DD);
        for (int c = tid; c < LL*DD; c += 128) xs[t][c] = xc[rowoff + c];
    }
    for (int i = tid; i < PP*TT; i += 128) w1[i/TT][i%TT] = w1g[i];
    if (tid < PP) b1[tid] = b1g[tid];
    for (int c = tid; c < LL*DD; c += 128) w2[c] = w2g[c];
    __syncthreads();

    float part[PP];
#pragma unroll
    for (int p = 0; p < PP; ++p) part[p] = 0.f;
    for (int c = tid; c < LL*DD; c += 128) {
        float xt[TT];
#pragma unroll
        for (int t = 0; t < TT; ++t) xt[t] = xs[t][c];
        float wc = w2[c];
#pragma unroll
        for (int p = 0; p < PP; ++p) {
            float sacc = b1[p];
#pragma unroll
            for (int t = 0; t < TT; ++t) sacc = fmaf(xt[t], w1[p][t], sacc);
            sacc = fmaxf(sacc, 0.f);
            part[p] = fmaf(sacc, wc, part[p]);
        }
    }
    const int warp = tid >> 5, lane = tid & 31;
#pragma unroll
    for (int p = 0; p < PP; ++p) {
        float sv = part[p];
#pragma unroll
        for (int o = 16; o; o >>= 1) sv += __shfl_xor_sync(0xffffffffu, sv, o);
        if (lane == 0) red[p][warp] = sv;
    }
    __syncthreads();
    if (tid < PP) {
        float sv = red[tid][0] + red[tid][1] + red[tid][2] + red[tid][3];
        y[(size_t)(b*PP + tid) * NN + n] = sv + b2g[0];
    }
}

// ---------------- launcher ---------------------------------------------------
extern "C" void kernel_launch(void* const* d_in, const int* in_sizes, int n_in,
                              void* d_out, int out_size)
{
    (void)in_sizes; (void)n_in; (void)out_size;
    const float* x      = (const float*)d_in[0];
    const float* tokW   = (const float*)d_in[1];
    const float* tokb   = (const float*)d_in[2];
    const float* t_qkvW = (const float*)d_in[3];
    const float* t_qkvb = (const float*)d_in[4];
    const float* t_pW   = (const float*)d_in[5];
    const float* t_pb   = (const float*)d_in[6];
    const float* g_qkvW = (const float*)d_in[7];
    const float* g_qkvb = (const float*)d_in[8];
    const float* g_pW   = (const float*)d_in[9];
    const float* g_pb   = (const float*)d_in[10];
    const float* s_qkvW = (const float*)d_in[11];
    const float* s_qkvb = (const float*)d_in[12];
    const float* s_pW   = (const float*)d_in[13];
    const float* s_pb   = (const float*)d_in[14];
    const float* resW   = (const float*)d_in[15];
    const float* resb   = (const float*)d_in[16];
    const float* normW  = (const float*)d_in[17];
    const float* normb  = (const float*)d_in[18];
    const float* fc1W   = (const float*)d_in[19];
    const float* fc1b   = (const float*)d_in[20];
    const float* fc2W   = (const float*)d_in[21];
    const float* fc2b   = (const float*)d_in[22];
    const float* e1W    = (const float*)d_in[23];
    const float* e1b    = (const float*)d_in[24];
    const float* e2W    = (const float*)d_in[25];
    const float* e2b    = (const float*)d_in[26];
    float* out = (float*)d_out;

    float *qkvB, *mB, *preB, *xcB;
    cudaGetSymbolAddress((void**)&qkvB, g_qkv);
    cudaGetSymbolAddress((void**)&mB,   g_m);
    cudaGetSymbolAddress((void**)&preB, g_pre);
    cudaGetSymbolAddress((void**)&xcB,  g_xc);

    bf16 *hAh,*hAl,*hBh,*hBl,*ath,*atl,*cth,*ctl,*mlh,*mll;
    cudaGetSymbolAddress((void**)&hAh, a_hA_hi); cudaGetSymbolAddress((void**)&hAl, a_hA_lo);
    cudaGetSymbolAddress((void**)&hBh, a_hB_hi); cudaGetSymbolAddress((void**)&hBl, a_hB_lo);
    cudaGetSymbolAddress((void**)&ath, a_at_hi); cudaGetSymbolAddress((void**)&atl, a_at_lo);
    cudaGetSymbolAddress((void**)&cth, a_ct_hi); cudaGetSymbolAddress((void**)&ctl, a_ct_lo);
    cudaGetSymbolAddress((void**)&mlh, a_ml_hi); cudaGetSymbolAddress((void**)&mll, a_ml_lo);

    bf16 *tqh,*tql,*gqh,*gql,*sqh,*sql,*tph,*tpl,*gph,*gpl,*sph,*spl,*rsh,*rsl,*f1h,*f1l,*f2h,*f2l;
    cudaGetSymbolAddress((void**)&tqh, w_tq_hi); cudaGetSymbolAddress((void**)&tql, w_tq_lo);
    cudaGetSymbolAddress((void**)&gqh, w_gq_hi); cudaGetSymbolAddress((void**)&gql, w_gq_lo);
    cudaGetSymbolAddress((void**)&sqh, w_sq_hi); cudaGetSymbolAddress((void**)&sql, w_sq_lo);
    cudaGetSymbolAddress((void**)&tph, w_tp_hi); cudaGetSymbolAddress((void**)&tpl, w_tp_lo);
    cudaGetSymbolAddress((void**)&gph, w_gp_hi); cudaGetSymbolAddress((void**)&gpl, w_gp_lo);
    cudaGetSymbolAddress((void**)&sph, w_sp_hi); cudaGetSymbolAddress((void**)&spl, w_sp_lo);
    cudaGetSymbolAddress((void**)&rsh, w_rs_hi); cudaGetSymbolAddress((void**)&rsl, w_rs_lo);
    cudaGetSymbolAddress((void**)&f1h, w_f1_hi); cudaGetSymbolAddress((void**)&f1l, w_f1_lo);
    cudaGetSymbolAddress((void**)&f2h, w_f2_hi); cudaGetSymbolAddress((void**)&f2l, w_f2_lo);

    const int NQ = LL*3*DD*DD, NPw = LL*DD*DD, NF1 = LL*HMM*2*DD, NF2 = LL*DD*HMM;
    cvt_kernel<<<(NQ+255)/256,256>>>(t_qkvW, tqh, tql, NQ);
    cvt_kernel<<<(NQ+255)/256,256>>>(g_qkvW, gqh, gql, NQ);
    cvt_kernel<<<(NQ+255)/256,256>>>(s_qkvW, sqh, sql, NQ);
    cvt_kernel<<<(NPw+255)/256,256>>>(t_pW, tph, tpl, NPw);
    cvt_kernel<<<(NPw+255)/256,256>>>(g_pW, gph, gpl, NPw);
    cvt_kernel<<<(NPw+255)/256,256>>>(s_pW, sph, spl, NPw);
    cvt_kernel<<<(NPw+255)/256,256>>>(resW, rsh, rsl, NPw);
    cvt_kernel<<<(NF1+255)/256,256>>>(fc1W, f1h, f1l, NF1);
    cvt_kernel<<<(NF2+255)/256,256>>>(fc2W, f2h, f2l, NF2);

    const int MBt = TOK / 128;

    embed_kernel<<<(TOK*DD)/256, 256>>>(x, tokW, tokb, hAh, hAl);

    for (int l = 0; l < LL; ++l) {
        const size_t oq = (size_t)l*3*DD*DD, oqb = (size_t)l*3*DD;
        const size_t op = (size_t)l*DD*DD,   opb = (size_t)l*DD;

        // temporal attention
        mma_gemm<<<dim3(3, MBt), 256>>>(hAh, hAl, tqh+oq, tql+oq, t_qkvb+oqb,
                                        nullptr, DD, qkvB, nullptr, nullptr, 3*DD, 0);
        temporal_attn_kernel<<<BB*NN, 128>>>(qkvB, ath, atl);
        mma_gemm<<<dim3(1, MBt), 256>>>(ath, atl, tph+op, tpl+op, t_pb+opb,
                                        nullptr, DD, nullptr, hBh, hBl, DD, 0);
        // geo spatial attention -> cat[:,0:128]
        mma_gemm<<<dim3(3, MBt), 256>>>(hBh, hBl, gqh+oq, gql+oq, g_qkvb+oqb,
                                        nullptr, DD, qkvB, nullptr, nullptr, 3*DD, 0);
        spatial_attn_mma<<<dim3(NN/128, HH, BB*TT), 256>>>(qkvB, ath, atl);
        mma_gemm<<<dim3(1, MBt), 256>>>(ath, atl, gph+op, gpl+op, g_pb+opb,
                                        nullptr, DD, nullptr, cth, ctl, 2*DD, 0);
        // sem spatial attention -> cat[:,128:256]
        mma_gemm<<<dim3(3, MBt), 256>>>(hBh, hBl, sqh+oq, sql+oq, s_qkvb+oqb,
                                        nullptr, DD, qkvB, nullptr, nullptr, 3*DD, 0);
        spatial_attn_mma<<<dim3(NN/128, HH, BB*TT), 256>>>(qkvB, ath, atl);
        mma_gemm<<<dim3(1, MBt), 256>>>(ath, atl, sph+op, spl+op, s_pb+opb,
                                        nullptr, DD, nullptr, cth+DD, ctl+DD, 2*DD, 0);
        // MLP
        mma_gemm<<<dim3(2, MBt), 256>>>(cth, ctl, f1h+(size_t)l*HMM*2*DD, f1l+(size_t)l*HMM*2*DD,
                                        fc1b+(size_t)l*HMM, nullptr, 2*DD,
                                        nullptr, mlh, mll, HMM, 1 /*gelu*/);
        mma_gemm<<<dim3(1, MBt), 256>>>(mlh, mll, f2h+(size_t)l*DD*HMM, f2l+(size_t)l*DD*HMM,
                                        fc2b+opb, nullptr, HMM, mB, nullptr, nullptr, DD, 0);
        // residual linear + add + layernorm
        mma_gemm<<<dim3(1, MBt), 256>>>(hAh, hAl, rsh+op, rsl+op, resb+opb,
                                        mB, DD, preB, nullptr, nullptr, DD, 0);
        ln_kernel<<<TOK/8, 256>>>(preB, normW+opb, normb+opb, hAh, hAl, xcB + (size_t)l*DD);
    }

    head_kernel<<<BB*NN, 128>>>(xcB, e1W, e1b, e2W, e2b, out);
}

// round 6
// speedup vs baseline: 2.0666x; 1.0988x over previous
#include <cuda_runtime.h>
#include <cuda_bf16.h>
#include <cuda_fp16.h>
#include <math.h>
#include <stdint.h>

#define BB   8
#define TT   12
#define NN   512
#define FINN 3
#define DD   128
#define HH   4
#define HMM  256
#define LL   3
#define PP   12
#define TOK  (BB*TT*NN)          // 49152 tokens

typedef __nv_bfloat16 bf16;

// ---------------- fp32 scratch ----------------------------------------------
__device__ float g_qkv[TOK*3*DD];
__device__ float g_pre[TOK*DD];
__device__ float g_xc [TOK*LL*DD];
// ---------------- bf16 hi/lo activation scratch -----------------------------
__device__ bf16 a_hA_hi[TOK*DD];   __device__ bf16 a_hA_lo[TOK*DD];
__device__ bf16 a_hB_hi[TOK*DD];   __device__ bf16 a_hB_lo[TOK*DD];
__device__ bf16 a_at_hi[TOK*DD];   __device__ bf16 a_at_lo[TOK*DD];
__device__ bf16 a_ct_hi[TOK*2*DD]; __device__ bf16 a_ct_lo[TOK*2*DD];
__device__ bf16 a_ml_hi[TOK*HMM];  __device__ bf16 a_ml_lo[TOK*HMM];
// ---------------- bf16 hi/lo weights ----------------------------------------
__device__ bf16 w_tq_hi[LL*3*DD*DD]; __device__ bf16 w_tq_lo[LL*3*DD*DD];
__device__ bf16 w_gq_hi[LL*3*DD*DD]; __device__ bf16 w_gq_lo[LL*3*DD*DD];
__device__ bf16 w_sq_hi[LL*3*DD*DD]; __device__ bf16 w_sq_lo[LL*3*DD*DD];
__device__ bf16 w_tp_hi[LL*DD*DD];   __device__ bf16 w_tp_lo[LL*DD*DD];
__device__ bf16 w_gp_hi[LL*DD*DD];   __device__ bf16 w_gp_lo[LL*DD*DD];
__device__ bf16 w_sp_hi[LL*DD*DD];   __device__ bf16 w_sp_lo[LL*DD*DD];
__device__ bf16 w_f1_hi[LL*HMM*2*DD];__device__ bf16 w_f1_lo[LL*HMM*2*DD];
// combined [fc2 | res] weight: [L][128][384]
__device__ bf16 w_cb_hi[LL*DD*(HMM+DD)]; __device__ bf16 w_cb_lo[LL*DD*(HMM+DD)];

__device__ __forceinline__ uint32_t smem_u32(const void* p) {
    uint32_t a;
    asm("{ .reg .u64 t; cvta.to.shared.u64 t, %1; cvt.u32.u64 %0, t; }"
        : "=r"(a) : "l"(p));
    return a;
}
__device__ __forceinline__ uint32_t pack2h(float a, float b) {
    __half2 h = __floats2half2_rn(a, b);
    return *(uint32_t*)&h;
}
#define CP_ASYNC16(dst, src) \
    asm volatile("cp.async.cg.shared.global [%0], [%1], 16;" :: "r"(dst), "l"(src))
#define CP_COMMIT() asm volatile("cp.async.commit_group;" ::: "memory")
#define CP_WAIT(n)  asm volatile("cp.async.wait_group %0;" :: "n"(n) : "memory")

// ================= weight fp32 -> bf16 hi/lo conversion ======================
__global__ void cvt_kernel(const float* __restrict__ src, bf16* __restrict__ hi,
                           bf16* __restrict__ lo, int n)
{
    int i = blockIdx.x * 256 + threadIdx.x;
    if (i < n) {
        float x = src[i];
        bf16 h = __float2bfloat16(x);
        hi[i] = h;
        lo[i] = __float2bfloat16(x - __bfloat162float(h));
    }
}
// combined [fc2W | resW] -> [L][128][384] hi/lo
__global__ void cvt_cmb_kernel(const float* __restrict__ f2, const float* __restrict__ rs,
                               bf16* __restrict__ hi, bf16* __restrict__ lo)
{
    int i = blockIdx.x * 256 + threadIdx.x;
    const int KK = HMM + DD;
    if (i >= LL*DD*KK) return;
    int l = i / (DD*KK);
    int r = (i / KK) % DD;
    int k = i % KK;
    float x = (k < HMM) ? f2[((size_t)l*DD + r)*HMM + k]
                        : rs[((size_t)l*DD + r)*DD + (k - HMM)];
    bf16 h = __float2bfloat16(x);
    hi[i] = h;
    lo[i] = __float2bfloat16(x - __bfloat162float(h));
}

// ================= cp.async mma GEMM =========================================
// C = act(concat(A1,A2) @ W^T + bias [+bias2]); A in hi/lo bf16, 3 passes.
// A1: [M,K1], A2: [M,K2] (may be null, K2=0), W: [N, K1+K2].
// grid=(N/128, M/128), 256 threads (8 warps 2x4).
__global__ void __launch_bounds__(256, 2)
mma_gemm(const bf16* __restrict__ A1hi, const bf16* __restrict__ A1lo, int K1,
         const bf16* __restrict__ A2hi, const bf16* __restrict__ A2lo, int K2,
         const bf16* __restrict__ Whi, const bf16* __restrict__ Wlo,
         const float* __restrict__ bias, const float* __restrict__ bias2,
         float* __restrict__ outf, bf16* __restrict__ ohi,
         bf16* __restrict__ olo, int ldo, int gelu)
{
    __shared__ bf16 As[2][128][40];
    __shared__ bf16 Bs[2][128][40];

    const int tid  = threadIdx.x;
    const int wid  = tid >> 5;
    const int lane = tid & 31;
    const int warp_m = wid >> 2;
    const int warp_n = wid & 3;
    const int m0 = blockIdx.y * 128;
    const int n0 = blockIdx.x * 128;
    const int K  = K1 + K2;

    float acc[4][4][4];
#pragma unroll
    for (int mi = 0; mi < 4; ++mi)
#pragma unroll
        for (int ni = 0; ni < 4; ++ni)
#pragma unroll
            for (int r = 0; r < 4; ++r) acc[mi][ni][r] = 0.f;

    const int KC = K >> 5;
    const int NI = 3 * KC;

    auto load_chunk = [&](int buf, int i) {
        const int pass = i / KC, kp = i - pass * KC;
        const int kof = kp * 32;
        const bf16* Asrc; int lda, acol;
        if (kof < K1) { Asrc = (pass < 2) ? A1hi : A1lo; lda = K1; acol = kof; }
        else          { Asrc = (pass < 2) ? A2hi : A2lo; lda = K2; acol = kof - K1; }
        const bf16* Bsrc = (pass == 1) ? Wlo : Whi;
#pragma unroll
        for (int t = 0; t < 2; ++t) {
            const int c   = tid + t * 256;      // 0..511 16B-chunks
            const int row = c >> 2;
            const int cc  = c & 3;
            uint32_t da = smem_u32(&As[buf][row][cc * 8]);
            CP_ASYNC16(da, Asrc + (size_t)(m0 + row) * lda + acol + cc * 8);
            uint32_t db = smem_u32(&Bs[buf][row][cc * 8]);
            CP_ASYNC16(db, Bsrc + (size_t)(n0 + row) * K + kof + cc * 8);
        }
    };

    auto compute = [&](int buf) {
#pragma unroll
        for (int ks = 0; ks < 2; ++ks) {
            const int k = ks * 16;
            uint32_t a[4][4], b[4][2];
#pragma unroll
            for (int mi = 0; mi < 4; ++mi) {
                const int row = warp_m * 64 + mi * 16 + (lane & 15);
                const int col = k + (lane >> 4) * 8;
                uint32_t ad = smem_u32(&As[buf][row][col]);
                asm volatile("ldmatrix.sync.aligned.m8n8.x4.shared.b16 {%0,%1,%2,%3}, [%4];"
                             : "=r"(a[mi][0]), "=r"(a[mi][1]), "=r"(a[mi][2]), "=r"(a[mi][3])
                             : "r"(ad));
            }
#pragma unroll
            for (int ni = 0; ni < 4; ++ni) {
                const int l16 = lane & 15;
                const int row = warp_n * 32 + ni * 8 + (l16 & 7);
                const int col = k + (l16 >> 3) * 8;
                uint32_t bd = smem_u32(&Bs[buf][row][col]);
                asm volatile("ldmatrix.sync.aligned.m8n8.x2.shared.b16 {%0,%1}, [%2];"
                             : "=r"(b[ni][0]), "=r"(b[ni][1]) : "r"(bd));
            }
#pragma unroll
            for (int mi = 0; mi < 4; ++mi)
#pragma unroll
                for (int ni = 0; ni < 4; ++ni) {
                    asm volatile(
                        "mma.sync.aligned.m16n8k16.row.col.f32.bf16.bf16.f32 "
                        "{%0,%1,%2,%3}, {%4,%5,%6,%7}, {%8,%9}, {%0,%1,%2,%3};"
                        : "+f"(acc[mi][ni][0]), "+f"(acc[mi][ni][1]),
                          "+f"(acc[mi][ni][2]), "+f"(acc[mi][ni][3])
                        : "r"(a[mi][0]), "r"(a[mi][1]), "r"(a[mi][2]), "r"(a[mi][3]),
                          "r"(b[ni][0]), "r"(b[ni][1]));
                }
        }
    };

    load_chunk(0, 0);
    CP_COMMIT();
    int buf = 0;
    for (int i = 0; i < NI; ++i) {
        if (i + 1 < NI) {
            load_chunk(buf ^ 1, i + 1);
            CP_COMMIT();
            CP_WAIT(1);
        } else {
            CP_WAIT(0);
        }
        __syncthreads();
        compute(buf);
        __syncthreads();
        buf ^= 1;
    }

    const int quad = lane >> 2, qi = lane & 3;
#pragma unroll
    for (int mi = 0; mi < 4; ++mi)
#pragma unroll
        for (int ni = 0; ni < 4; ++ni)
#pragma unroll
            for (int h = 0; h < 2; ++h) {
                const int row = m0 + warp_m * 64 + mi * 16 + quad + h * 8;
                const int col = n0 + warp_n * 32 + ni * 8 + qi * 2;
                float v0 = acc[mi][ni][h * 2 + 0] + bias[col];
                float v1 = acc[mi][ni][h * 2 + 1] + bias[col + 1];
                if (bias2) { v0 += bias2[col]; v1 += bias2[col + 1]; }
                const size_t o = (size_t)row * ldo + col;
                if (gelu) {
                    v0 = 0.5f * v0 * (1.0f + erff(v0 * 0.70710678118654752f));
                    v1 = 0.5f * v1 * (1.0f + erff(v1 * 0.70710678118654752f));
                }
                if (outf) { outf[o] = v0; outf[o + 1] = v1; }
                if (ohi) {
                    bf16 h0 = __float2bfloat16(v0), h1 = __float2bfloat16(v1);
                    ohi[o]     = h0; olo[o]     = __float2bfloat16(v0 - __bfloat162float(h0));
                    ohi[o + 1] = h1; olo[o + 1] = __float2bfloat16(v1 - __bfloat162float(h1));
                }
            }
}

// ---------------- embedding + positional encoding (writes hi/lo) ------------
__global__ void embed_kernel(const float* __restrict__ x,
                             const float* __restrict__ tokW,
                             const float* __restrict__ tokb,
                             bf16* __restrict__ hhi, bf16* __restrict__ hlo)
{
    size_t idx = (size_t)blockIdx.x * 256 + threadIdx.x;
    size_t token = idx >> 7;
    int d = (int)(idx & 127);
    int t = (int)((token / NN) % TT);
    const float* xp = x + token * FINN;
    float val = xp[0]*tokW[d*3+0] + xp[1]*tokW[d*3+1] + xp[2]*tokW[d*3+2] + tokb[d];
    int i2 = d & ~1;
    float div = expf((float)i2 * (-logf(10000.0f) / (float)DD));
    float ang = (float)t * div;
    val += (d & 1) ? cosf(ang) : sinf(ang);
    bf16 h = __float2bfloat16(val);
    hhi[idx] = h;
    hlo[idx] = __float2bfloat16(val - __bfloat162float(h));
}

// ---------------- temporal attention (over T=12) — writes hi/lo -------------
__global__ void temporal_attn_kernel(const float* __restrict__ qkv,
                                     bf16* __restrict__ ohi, bf16* __restrict__ olo)
{
    const int bidx = blockIdx.x;
    const int b = bidx >> 9, n = bidx & 511;
    const int tid = threadIdx.x;
    __shared__ float q[TT][DD], k[TT][DD], v[TT][DD];
    __shared__ float S[HH][TT][TT];
#pragma unroll
    for (int t = 0; t < TT; ++t) {
        size_t row = ((size_t)(b*TT + t) * NN + n) * 384;
        q[t][tid] = qkv[row + tid];
        k[t][tid] = qkv[row + 128 + tid];
        v[t][tid] = qkv[row + 256 + tid];
    }
    __syncthreads();
    const float scale = 0.17677669529663687f;
    for (int idx = tid; idx < HH*TT*TT; idx += 128) {
        int hh = idx / (TT*TT);
        int rem = idx - hh*(TT*TT);
        int xx = rem / TT, yy = rem - xx*TT;
        float s = 0.f;
#pragma unroll
        for (int e = 0; e < 32; ++e)
            s = fmaf(q[xx][hh*32+e], k[yy][hh*32+e], s);
        S[hh][xx][yy] = s * scale;
    }
    __syncthreads();
    if (tid < HH*TT) {
        int hh = tid / TT, xx = tid % TT;
        float mx = -1e30f;
#pragma unroll
        for (int y = 0; y < TT; ++y) mx = fmaxf(mx, S[hh][xx][y]);
        float sum = 0.f;
#pragma unroll
        for (int y = 0; y < TT; ++y) { float p = __expf(S[hh][xx][y]-mx); S[hh][xx][y] = p; sum += p; }
        float inv = 1.f / sum;
#pragma unroll
        for (int y = 0; y < TT; ++y) S[hh][xx][y] *= inv;
    }
    __syncthreads();
    const int hh = tid >> 5;
    for (int xx = 0; xx < TT; ++xx) {
        float o = 0.f;
#pragma unroll
        for (int yy = 0; yy < TT; ++yy) o = fmaf(S[hh][xx][yy], v[yy][tid], o);
        size_t oi = ((size_t)(b*TT + xx) * NN + n) * DD + tid;
        bf16 h = __float2bfloat16(o);
        ohi[oi] = h;
        olo[oi] = __float2bfloat16(o - __bfloat162float(h));
    }
}

// ============ spatial attention via tensor cores (flash, fp16) ==============
__global__ void __launch_bounds__(256, 1)
spatial_attn_mma(const float* __restrict__ qkv,
                 bf16* __restrict__ outhi, bf16* __restrict__ outlo)
{
    const int qtile = blockIdx.x;
    const int head  = blockIdx.y;
    const int bt    = blockIdx.z;
    const int tid  = threadIdx.x;
    const int wid  = tid >> 5;
    const int lane = tid & 31;
    const int l16  = lane & 15;

    __shared__ __half Qs[128][40];
    __shared__ __half Ks[128][40];
    __shared__ __half Vt[32][136];

    const size_t base = (size_t)bt * NN;
    const float scale = 0.17677669529663687f;

    for (int i = tid; i < 128*32; i += 256) {
        int r = i >> 5, e = i & 31;
        Qs[r][e] = __float2half(qkv[(base + (size_t)qtile*128 + r)*384 + head*32 + e] * scale);
    }
    __syncthreads();

    uint32_t qf[2][4];
#pragma unroll
    for (int kc = 0; kc < 2; ++kc) {
        uint32_t ad = smem_u32(&Qs[wid*16 + l16][kc*16 + (lane>>4)*8]);
        asm volatile("ldmatrix.sync.aligned.m8n8.x4.shared.b16 {%0,%1,%2,%3}, [%4];"
                     : "=r"(qf[kc][0]), "=r"(qf[kc][1]), "=r"(qf[kc][2]), "=r"(qf[kc][3])
                     : "r"(ad));
    }

    float m0 = -1e30f, m1 = -1e30f, l0 = 0.f, l1 = 0.f;
    float oacc[4][4];
#pragma unroll
    for (int ef = 0; ef < 4; ++ef)
#pragma unroll
        for (int r = 0; r < 4; ++r) oacc[ef][r] = 0.f;

    for (int kt = 0; kt < 4; ++kt) {
        __syncthreads();
        for (int i = tid; i < 128*32; i += 256) {
            int j = i >> 5, e = i & 31;
            const float* rp = qkv + (base + (size_t)kt*128 + j)*384 + 128 + head*32 + e;
            Ks[j][e] = __float2half(rp[0]);
            Vt[e][j] = __float2half(rp[128]);
        }
        __syncthreads();

        float sacc[16][4];
#pragma unroll
        for (int nf = 0; nf < 16; ++nf) {
            sacc[nf][0] = sacc[nf][1] = sacc[nf][2] = sacc[nf][3] = 0.f;
#pragma unroll
            for (int kc = 0; kc < 2; ++kc) {
                uint32_t b0, b1;
                uint32_t bd = smem_u32(&Ks[nf*8 + (l16 & 7)][kc*16 + (l16 >> 3)*8]);
                asm volatile("ldmatrix.sync.aligned.m8n8.x2.shared.b16 {%0,%1}, [%2];"
                             : "=r"(b0), "=r"(b1) : "r"(bd));
                asm volatile(
                    "mma.sync.aligned.m16n8k16.row.col.f32.f16.f16.f32 "
                    "{%0,%1,%2,%3}, {%4,%5,%6,%7}, {%8,%9}, {%0,%1,%2,%3};"
                    : "+f"(sacc[nf][0]), "+f"(sacc[nf][1]),
                      "+f"(sacc[nf][2]), "+f"(sacc[nf][3])
                    : "r"(qf[kc][0]), "r"(qf[kc][1]), "r"(qf[kc][2]), "r"(qf[kc][3]),
                      "r"(b0), "r"(b1));
            }
        }

        float mx0 = -1e30f, mx1 = -1e30f;
#pragma unroll
        for (int nf = 0; nf < 16; ++nf) {
            mx0 = fmaxf(mx0, fmaxf(sacc[nf][0], sacc[nf][1]));
            mx1 = fmaxf(mx1, fmaxf(sacc[nf][2], sacc[nf][3]));
        }
        mx0 = fmaxf(mx0, __shfl_xor_sync(0xffffffffu, mx0, 1));
        mx0 = fmaxf(mx0, __shfl_xor_sync(0xffffffffu, mx0, 2));
        mx1 = fmaxf(mx1, __shfl_xor_sync(0xffffffffu, mx1, 1));
        mx1 = fmaxf(mx1, __shfl_xor_sync(0xffffffffu, mx1, 2));
        const float nm0 = fmaxf(m0, mx0), nm1 = fmaxf(m1, mx1);
        const float c0 = __expf(m0 - nm0), c1 = __expf(m1 - nm1);
        m0 = nm0; m1 = nm1;
#pragma unroll
        for (int ef = 0; ef < 4; ++ef) {
            oacc[ef][0] *= c0; oacc[ef][1] *= c0;
            oacc[ef][2] *= c1; oacc[ef][3] *= c1;
        }

        float rs0 = 0.f, rs1 = 0.f;
#pragma unroll
        for (int jc = 0; jc < 8; ++jc) {
            float p00 = __expf(sacc[2*jc][0]   - nm0);
            float p01 = __expf(sacc[2*jc][1]   - nm0);
            float p10 = __expf(sacc[2*jc][2]   - nm1);
            float p11 = __expf(sacc[2*jc][3]   - nm1);
            float p20 = __expf(sacc[2*jc+1][0] - nm0);
            float p21 = __expf(sacc[2*jc+1][1] - nm0);
            float p30 = __expf(sacc[2*jc+1][2] - nm1);
            float p31 = __expf(sacc[2*jc+1][3] - nm1);
            rs0 += p00 + p01 + p20 + p21;
            rs1 += p10 + p11 + p30 + p31;
            uint32_t pf0 = pack2h(p00, p01);
            uint32_t pf1 = pack2h(p10, p11);
            uint32_t pf2 = pack2h(p20, p21);
            uint32_t pf3 = pack2h(p30, p31);
#pragma unroll
            for (int ef = 0; ef < 4; ++ef) {
                uint32_t b0, b1;
                uint32_t bd = smem_u32(&Vt[ef*8 + (l16 & 7)][jc*16 + (l16 >> 3)*8]);
                asm volatile("ldmatrix.sync.aligned.m8n8.x2.shared.b16 {%0,%1}, [%2];"
                             : "=r"(b0), "=r"(b1) : "r"(bd));
                asm volatile(
                    "mma.sync.aligned.m16n8k16.row.col.f32.f16.f16.f32 "
                    "{%0,%1,%2,%3}, {%4,%5,%6,%7}, {%8,%9}, {%0,%1,%2,%3};"
                    : "+f"(oacc[ef][0]), "+f"(oacc[ef][1]),
                      "+f"(oacc[ef][2]), "+f"(oacc[ef][3])
                    : "r"(pf0), "r"(pf1), "r"(pf2), "r"(pf3),
                      "r"(b0), "r"(b1));
            }
        }
        rs0 += __shfl_xor_sync(0xffffffffu, rs0, 1);
        rs0 += __shfl_xor_sync(0xffffffffu, rs0, 2);
        rs1 += __shfl_xor_sync(0xffffffffu, rs1, 1);
        rs1 += __shfl_xor_sync(0xffffffffu, rs1, 2);
        l0 = l0 * c0 + rs0;
        l1 = l1 * c1 + rs1;
    }

    const float i0 = 1.f / l0, i1 = 1.f / l1;
    const int r0 = wid*16 + (lane >> 2);
#pragma unroll
    for (int ef = 0; ef < 4; ++ef) {
        const int col = head*32 + ef*8 + (lane & 3)*2;
        size_t rowA = (base + (size_t)qtile*128 + r0) * DD + col;
        size_t rowB = (base + (size_t)qtile*128 + r0 + 8) * DD + col;
        float v0 = oacc[ef][0] * i0, v1 = oacc[ef][1] * i0;
        float v2 = oacc[ef][2] * i1, v3 = oacc[ef][3] * i1;
        bf16 h0 = __float2bfloat16(v0), h1 = __float2bfloat16(v1);
        bf16 h2 = __float2bfloat16(v2), h3 = __float2bfloat16(v3);
        outhi[rowA]   = h0; outlo[rowA]   = __float2bfloat16(v0 - __bfloat162float(h0));
        outhi[rowA+1] = h1; outlo[rowA+1] = __float2bfloat16(v1 - __bfloat162float(h1));
        outhi[rowB]   = h2; outlo[rowB]   = __float2bfloat16(v2 - __bfloat162float(h2));
        outhi[rowB+1] = h3; outlo[rowB+1] = __float2bfloat16(v3 - __bfloat162float(h3));
    }
}

// ---------------- layernorm — writes hi/lo + fp32 slice of xc ---------------
__global__ void ln_kernel(const float* __restrict__ pre, const float* __restrict__ g,
                          const float* __restrict__ bta,
                          bf16* __restrict__ hhi, bf16* __restrict__ hlo,
                          float* __restrict__ xc)
{
    const int warp = threadIdx.x >> 5, lane = threadIdx.x & 31;
    size_t token = (size_t)blockIdx.x * 8 + warp;
    const float* p = pre + token * DD;
    float v[4];
#pragma unroll
    for (int i = 0; i < 4; ++i) v[i] = p[lane + 32*i];
    float s = v[0] + v[1] + v[2] + v[3];
#pragma unroll
    for (int o = 16; o; o >>= 1) s += __shfl_xor_sync(0xffffffffu, s, o);
    float mean = s * (1.f/128.f);
    float q = 0.f;
#pragma unroll
    for (int i = 0; i < 4; ++i) { v[i] -= mean; q += v[i]*v[i]; }
#pragma unroll
    for (int o = 16; o; o >>= 1) q += __shfl_xor_sync(0xffffffffu, q, o);
    float inv = rsqrtf(q * (1.f/128.f) + 1e-5f);
#pragma unroll
    for (int i = 0; i < 4; ++i) {
        int d = lane + 32*i;
        float o = v[i] * inv * g[d] + bta[d];
        bf16 h = __float2bfloat16(o);
        hhi[token*DD + d] = h;
        hlo[token*DD + d] = __float2bfloat16(o - __bfloat162float(h));
        xc[token*(LL*DD) + d] = o;
    }
}

// ---------------- output head ------------------------------------------------
__global__ void head_kernel(const float* __restrict__ xc, const float* __restrict__ w1g,
                            const float* __restrict__ b1g, const float* __restrict__ w2g,
                            const float* __restrict__ b2g, float* __restrict__ y)
{
    const int bidx = blockIdx.x;
    const int b = bidx >> 9, n = bidx & 511;
    const int tid = threadIdx.x;
    __shared__ float xs[TT][LL*DD];
    __shared__ float w1[PP][TT];
    __shared__ float b1[PP];
    __shared__ float w2[LL*DD];
    __shared__ float red[PP][4];
    for (int t = 0; t < TT; ++t) {
        size_t rowoff = ((size_t)(b*TT + t) * NN + n) * (LL*DD);
        for (int c = tid; c < LL*DD; c += 128) xs[t][c] = xc[rowoff + c];
    }
    for (int i = tid; i < PP*TT; i += 128) w1[i/TT][i%TT] = w1g[i];
    if (tid < PP) b1[tid] = b1g[tid];
    for (int c = tid; c < LL*DD; c += 128) w2[c] = w2g[c];
    __syncthreads();

    float part[PP];
#pragma unroll
    for (int p = 0; p < PP; ++p) part[p] = 0.f;
    for (int c = tid; c < LL*DD; c += 128) {
        float xt[TT];
#pragma unroll
        for (int t = 0; t < TT; ++t) xt[t] = xs[t][c];
        float wc = w2[c];
#pragma unroll
        for (int p = 0; p < PP; ++p) {
            float sacc = b1[p];
#pragma unroll
            for (int t = 0; t < TT; ++t) sacc = fmaf(xt[t], w1[p][t], sacc);
            sacc = fmaxf(sacc, 0.f);
            part[p] = fmaf(sacc, wc, part[p]);
        }
    }
    const int warp = tid >> 5, lane = tid & 31;
#pragma unroll
    for (int p = 0; p < PP; ++p) {
        float sv = part[p];
#pragma unroll
        for (int o = 16; o; o >>= 1) sv += __shfl_xor_sync(0xffffffffu, sv, o);
        if (lane == 0) red[p][warp] = sv;
    }
    __syncthreads();
    if (tid < PP) {
        float sv = red[tid][0] + red[tid][1] + red[tid][2] + red[tid][3];
        y[(size_t)(b*PP + tid) * NN + n] = sv + b2g[0];
    }
}

// ---------------- launcher ---------------------------------------------------
extern "C" void kernel_launch(void* const* d_in, const int* in_sizes, int n_in,
                              void* d_out, int out_size)
{
    (void)in_sizes; (void)n_in; (void)out_size;
    const float* x      = (const float*)d_in[0];
    const float* tokW   = (const float*)d_in[1];
    const float* tokb   = (const float*)d_in[2];
    const float* t_qkvW = (const float*)d_in[3];
    const float* t_qkvb = (const float*)d_in[4];
    const float* t_pW   = (const float*)d_in[5];
    const float* t_pb   = (const float*)d_in[6];
    const float* g_qkvW = (const float*)d_in[7];
    const float* g_qkvb = (const float*)d_in[8];
    const float* g_pW   = (const float*)d_in[9];
    const float* g_pb   = (const float*)d_in[10];
    const float* s_qkvW = (const float*)d_in[11];
    const float* s_qkvb = (const float*)d_in[12];
    const float* s_pW   = (const float*)d_in[13];
    const float* s_pb   = (const float*)d_in[14];
    const float* resW   = (const float*)d_in[15];
    const float* resb   = (const float*)d_in[16];
    const float* normW  = (const float*)d_in[17];
    const float* normb  = (const float*)d_in[18];
    const float* fc1W   = (const float*)d_in[19];
    const float* fc1b   = (const float*)d_in[20];
    const float* fc2W   = (const float*)d_in[21];
    const float* fc2b   = (const float*)d_in[22];
    const float* e1W    = (const float*)d_in[23];
    const float* e1b    = (const float*)d_in[24];
    const float* e2W    = (const float*)d_in[25];
    const float* e2b    = (const float*)d_in[26];
    float* out = (float*)d_out;

    float *qkvB, *preB, *xcB;
    cudaGetSymbolAddress((void**)&qkvB, g_qkv);
    cudaGetSymbolAddress((void**)&preB, g_pre);
    cudaGetSymbolAddress((void**)&xcB,  g_xc);

    bf16 *hAh,*hAl,*hBh,*hBl,*ath,*atl,*cth,*ctl,*mlh,*mll;
    cudaGetSymbolAddress((void**)&hAh, a_hA_hi); cudaGetSymbolAddress((void**)&hAl, a_hA_lo);
    cudaGetSymbolAddress((void**)&hBh, a_hB_hi); cudaGetSymbolAddress((void**)&hBl, a_hB_lo);
    cudaGetSymbolAddress((void**)&ath, a_at_hi); cudaGetSymbolAddress((void**)&atl, a_at_lo);
    cudaGetSymbolAddress((void**)&cth, a_ct_hi); cudaGetSymbolAddress((void**)&ctl, a_ct_lo);
    cudaGetSymbolAddress((void**)&mlh, a_ml_hi); cudaGetSymbolAddress((void**)&mll, a_ml_lo);

    bf16 *tqh,*tql,*gqh,*gql,*sqh,*sql,*tph,*tpl,*gph,*gpl,*sph,*spl,*f1h,*f1l,*cbh,*cbl;
    cudaGetSymbolAddress((void**)&tqh, w_tq_hi); cudaGetSymbolAddress((void**)&tql, w_tq_lo);
    cudaGetSymbolAddress((void**)&gqh, w_gq_hi); cudaGetSymbolAddress((void**)&gql, w_gq_lo);
    cudaGetSymbolAddress((void**)&sqh, w_sq_hi); cudaGetSymbolAddress((void**)&sql, w_sq_lo);
    cudaGetSymbolAddress((void**)&tph, w_tp_hi); cudaGetSymbolAddress((void**)&tpl, w_tp_lo);
    cudaGetSymbolAddress((void**)&gph, w_gp_hi); cudaGetSymbolAddress((void**)&gpl, w_gp_lo);
    cudaGetSymbolAddress((void**)&sph, w_sp_hi); cudaGetSymbolAddress((void**)&spl, w_sp_lo);
    cudaGetSymbolAddress((void**)&f1h, w_f1_hi); cudaGetSymbolAddress((void**)&f1l, w_f1_lo);
    cudaGetSymbolAddress((void**)&cbh, w_cb_hi); cudaGetSymbolAddress((void**)&cbl, w_cb_lo);

    const int NQ = LL*3*DD*DD, NPw = LL*DD*DD, NF1 = LL*HMM*2*DD, NCB = LL*DD*(HMM+DD);
    cvt_kernel<<<(NQ+255)/256,256>>>(t_qkvW, tqh, tql, NQ);
    cvt_kernel<<<(NQ+255)/256,256>>>(g_qkvW, gqh, gql, NQ);
    cvt_kernel<<<(NQ+255)/256,256>>>(s_qkvW, sqh, sql, NQ);
    cvt_kernel<<<(NPw+255)/256,256>>>(t_pW, tph, tpl, NPw);
    cvt_kernel<<<(NPw+255)/256,256>>>(g_pW, gph, gpl, NPw);
    cvt_kernel<<<(NPw+255)/256,256>>>(s_pW, sph, spl, NPw);
    cvt_kernel<<<(NF1+255)/256,256>>>(fc1W, f1h, f1l, NF1);
    cvt_cmb_kernel<<<(NCB+255)/256,256>>>(fc2W, resW, cbh, cbl);

    const int MBt = TOK / 128;

    embed_kernel<<<(TOK*DD)/256, 256>>>(x, tokW, tokb, hAh, hAl);

    for (int l = 0; l < LL; ++l) {
        const size_t oq = (size_t)l*3*DD*DD, oqb = (size_t)l*3*DD;
        const size_t op = (size_t)l*DD*DD,   opb = (size_t)l*DD;

        // temporal attention
        mma_gemm<<<dim3(3, MBt), 256>>>(hAh, hAl, DD, nullptr, nullptr, 0,
                                        tqh+oq, tql+oq, t_qkvb+oqb, nullptr,
                                        qkvB, nullptr, nullptr, 3*DD, 0);
        temporal_attn_kernel<<<BB*NN, 128>>>(qkvB, ath, atl);
        mma_gemm<<<dim3(1, MBt), 256>>>(ath, atl, DD, nullptr, nullptr, 0,
                                        tph+op, tpl+op, t_pb+opb, nullptr,
                                        nullptr, hBh, hBl, DD, 0);
        // geo spatial attention -> cat[:,0:128]
        mma_gemm<<<dim3(3, MBt), 256>>>(hBh, hBl, DD, nullptr, nullptr, 0,
                                        gqh+oq, gql+oq, g_qkvb+oqb, nullptr,
                                        qkvB, nullptr, nullptr, 3*DD, 0);
        spatial_attn_mma<<<dim3(NN/128, HH, BB*TT), 256>>>(qkvB, ath, atl);
        mma_gemm<<<dim3(1, MBt), 256>>>(ath, atl, DD, nullptr, nullptr, 0,
                                        gph+op, gpl+op, g_pb+opb, nullptr,
                                        nullptr, cth, ctl, 2*DD, 0);
        // sem spatial attention -> cat[:,128:256]
        mma_gemm<<<dim3(3, MBt), 256>>>(hBh, hBl, DD, nullptr, nullptr, 0,
                                        sqh+oq, sql+oq, s_qkvb+oqb, nullptr,
                                        qkvB, nullptr, nullptr, 3*DD, 0);
        spatial_attn_mma<<<dim3(NN/128, HH, BB*TT), 256>>>(qkvB, ath, atl);
        mma_gemm<<<dim3(1, MBt), 256>>>(ath, atl, DD, nullptr, nullptr, 0,
                                        sph+op, spl+op, s_pb+opb, nullptr,
                                        nullptr, cth+DD, ctl+DD, 2*DD, 0);
        // MLP fc1 (+gelu)
        mma_gemm<<<dim3(2, MBt), 256>>>(cth, ctl, 2*DD, nullptr, nullptr, 0,
                                        f1h+(size_t)l*HMM*2*DD, f1l+(size_t)l*HMM*2*DD,
                                        fc1b+(size_t)l*HMM, nullptr,
                                        nullptr, mlh, mll, HMM, 1);
        // fused fc2 + residual-linear: pre = mlp@fc2^T + hA@res^T + fc2b + resb
        mma_gemm<<<dim3(1, MBt), 256>>>(mlh, mll, HMM, hAh, hAl, DD,
                                        cbh+(size_t)l*DD*(HMM+DD), cbl+(size_t)l*DD*(HMM+DD),
                                        fc2b+opb, resb+opb,
                                        preB, nullptr, nullptr, DD, 0);
        ln_kernel<<<TOK/8, 256>>>(preB, normW+opb, normb+opb, hAh, hAl, xcB + (size_t)l*DD);
    }

    head_kernel<<<BB*NN, 128>>>(xcB, e1W, e1b, e2W, e2b, out);
}

// round 7
// speedup vs baseline: 2.1215x; 1.0266x over previous
#include <cuda_runtime.h>
#include <cuda_bf16.h>
#include <cuda_fp16.h>
#include <math.h>
#include <stdint.h>

#define BB   8
#define TT   12
#define NN   512
#define FINN 3
#define DD   128
#define HH   4
#define HMM  256
#define LL   3
#define PP   12
#define TOK  (BB*TT*NN)          // 49152 tokens

typedef __nv_bfloat16 bf16;

// ---------------- fp32 scratch ----------------------------------------------
__device__ float g_qkv  [TOK*3*DD];    // temporal qkv [tok,384]
__device__ float g_qkv12[TOK*6*DD];    // geo|sem qkv  [tok,768]
__device__ float g_pre[TOK*DD];
__device__ float g_xc [TOK*LL*DD];
__device__ float b_gs [LL*6*DD];       // combined geo|sem qkv bias
// ---------------- bf16 hi/lo activation scratch -----------------------------
__device__ bf16 a_hA_hi[TOK*DD];   __device__ bf16 a_hA_lo[TOK*DD];
__device__ bf16 a_hB_hi[TOK*DD];   __device__ bf16 a_hB_lo[TOK*DD];
__device__ bf16 a_at_hi[TOK*DD];   __device__ bf16 a_at_lo[TOK*DD];
__device__ bf16 a_a2_hi[TOK*DD];   __device__ bf16 a_a2_lo[TOK*DD];
__device__ bf16 a_ct_hi[TOK*2*DD]; __device__ bf16 a_ct_lo[TOK*2*DD];
__device__ bf16 a_ml_hi[TOK*HMM];  __device__ bf16 a_ml_lo[TOK*HMM];
// ---------------- bf16 hi/lo weights ----------------------------------------
__device__ bf16 w_tq_hi[LL*3*DD*DD]; __device__ bf16 w_tq_lo[LL*3*DD*DD];
__device__ bf16 w_gs_hi[LL*6*DD*DD]; __device__ bf16 w_gs_lo[LL*6*DD*DD];
__device__ bf16 w_tp_hi[LL*DD*DD];   __device__ bf16 w_tp_lo[LL*DD*DD];
__device__ bf16 w_gp_hi[LL*DD*DD];   __device__ bf16 w_gp_lo[LL*DD*DD];
__device__ bf16 w_sp_hi[LL*DD*DD];   __device__ bf16 w_sp_lo[LL*DD*DD];
__device__ bf16 w_f1_hi[LL*HMM*2*DD];__device__ bf16 w_f1_lo[LL*HMM*2*DD];
__device__ bf16 w_cb_hi[LL*DD*(HMM+DD)]; __device__ bf16 w_cb_lo[LL*DD*(HMM+DD)];

__device__ __forceinline__ uint32_t smem_u32(const void* p) {
    uint32_t a;
    asm("{ .reg .u64 t; cvta.to.shared.u64 t, %1; cvt.u32.u64 %0, t; }"
        : "=r"(a) : "l"(p));
    return a;
}
__device__ __forceinline__ uint32_t pack2h(float a, float b) {
    __half2 h = __floats2half2_rn(a, b);
    return *(uint32_t*)&h;
}
#define CP_ASYNC16(dst, src) \
    asm volatile("cp.async.cg.shared.global [%0], [%1], 16;" :: "r"(dst), "l"(src))
#define CP_COMMIT() asm volatile("cp.async.commit_group;" ::: "memory")
#define CP_WAIT(n)  asm volatile("cp.async.wait_group %0;" :: "n"(n) : "memory")

// ================= one-shot weight conversion ================================
__global__ void cvt_all(const float* __restrict__ t_qkvW,
                        const float* __restrict__ g_qkvW, const float* __restrict__ s_qkvW,
                        const float* __restrict__ t_pW,   const float* __restrict__ g_pW,
                        const float* __restrict__ s_pW,   const float* __restrict__ fc1W,
                        const float* __restrict__ fc2W,   const float* __restrict__ resW,
                        const float* __restrict__ g_qkvb, const float* __restrict__ s_qkvb)
{
    int i = blockIdx.x * 256 + threadIdx.x;
    const int NQ  = LL*3*DD*DD;        // 147456
    const int NGS = LL*6*DD*DD;        // 294912
    const int NPw = LL*DD*DD;          // 49152
    const int NF1 = LL*HMM*2*DD;       // 393216
    const int NCB = LL*DD*(HMM+DD);    // 147456
    float v; bf16 *hi, *lo; int off;
    if (i < NQ) { v = t_qkvW[i]; hi = w_tq_hi; lo = w_tq_lo; off = i; }
    else if ((i -= NQ) < NGS) {
        int l = i / (768*DD), r = (i / DD) % 768, k = i % DD;
        v = (r < 384) ? g_qkvW[((size_t)l*384 + r)*DD + k]
                      : s_qkvW[((size_t)l*384 + (r-384))*DD + k];
        if (k == 0) b_gs[l*768 + r] = (r < 384) ? g_qkvb[l*384 + r] : s_qkvb[l*384 + r - 384];
        hi = w_gs_hi; lo = w_gs_lo; off = i;
    }
    else if ((i -= NGS) < NPw) { v = t_pW[i]; hi = w_tp_hi; lo = w_tp_lo; off = i; }
    else if ((i -= NPw) < NPw) { v = g_pW[i]; hi = w_gp_hi; lo = w_gp_lo; off = i; }
    else if ((i -= NPw) < NPw) { v = s_pW[i]; hi = w_sp_hi; lo = w_sp_lo; off = i; }
    else if ((i -= NPw) < NF1) { v = fc1W[i]; hi = w_f1_hi; lo = w_f1_lo; off = i; }
    else if ((i -= NF1) < NCB) {
        const int KK = HMM + DD;
        int l = i / (DD*KK), r = (i / KK) % DD, k = i % KK;
        v = (k < HMM) ? fc2W[((size_t)l*DD + r)*HMM + k]
                      : resW[((size_t)l*DD + r)*DD + (k - HMM)];
        hi = w_cb_hi; lo = w_cb_lo; off = i;
    }
    else return;
    bf16 h = __float2bfloat16(v);
    hi[off] = h;
    lo[off] = __float2bfloat16(v - __bfloat162float(h));
}

// ================= chunk-fused 3-term mma GEMM ===============================
// C = act(concat(A1,A2) @ W^T + bias [+bias2]); per 32-wide k-chunk loads the
// 4 unique tiles (a_hi, a_lo, w_hi, w_lo) once, computes hh + hl + lh.
// grid=(N/128, M/128), 256 threads (8 warps 2x4). dyn smem = 2*4*10240 = 80KB.
__global__ void __launch_bounds__(256, 2)
mma_gemm(const bf16* __restrict__ A1hi, const bf16* __restrict__ A1lo, int K1,
         const bf16* __restrict__ A2hi, const bf16* __restrict__ A2lo, int K2,
         const bf16* __restrict__ Whi, const bf16* __restrict__ Wlo,
         const float* __restrict__ bias, const float* __restrict__ bias2,
         float* __restrict__ outf, bf16* __restrict__ ohi,
         bf16* __restrict__ olo, int ldo, int gelu)
{
    extern __shared__ bf16 sm[];      // [2][4][128*40]
    const int tid  = threadIdx.x;
    const int wid  = tid >> 5;
    const int lane = tid & 31;
    const int l16  = lane & 15;
    const int warp_m = wid >> 2;
    const int warp_n = wid & 3;
    const int m0 = blockIdx.y * 128;
    const int n0 = blockIdx.x * 128;
    const int K  = K1 + K2;
    const int KC = K >> 5;

    float acc[4][4][4];
#pragma unroll
    for (int mi = 0; mi < 4; ++mi)
#pragma unroll
        for (int ni = 0; ni < 4; ++ni)
#pragma unroll
            for (int r = 0; r < 4; ++r) acc[mi][ni][r] = 0.f;

    auto tile = [&](int st, int w) -> bf16* { return sm + (size_t)(st*4 + w) * 5120; };

    auto load_chunk = [&](int st, int kp) {
        const int kof = kp * 32;
        const bf16 *Ah, *Al; int lda, acol;
        if (kof < K1) { Ah = A1hi; Al = A1lo; lda = K1; acol = kof; }
        else          { Ah = A2hi; Al = A2lo; lda = K2; acol = kof - K1; }
        bf16* d0 = tile(st, 0); bf16* d1 = tile(st, 1);
        bf16* d2 = tile(st, 2); bf16* d3 = tile(st, 3);
#pragma unroll
        for (int t = 0; t < 2; ++t) {
            const int c   = tid + t * 256;      // 0..511
            const int row = c >> 2;
            const int cc  = (c & 3) * 8;
            const size_t aoff = (size_t)(m0 + row) * lda + acol + cc;
            const size_t woff = (size_t)(n0 + row) * K + kof + cc;
            const int so = row * 40 + cc;
            CP_ASYNC16(smem_u32(d0 + so), Ah  + aoff);
            CP_ASYNC16(smem_u32(d1 + so), Al  + aoff);
            CP_ASYNC16(smem_u32(d2 + so), Whi + woff);
            CP_ASYNC16(smem_u32(d3 + so), Wlo + woff);
        }
    };

    auto compute = [&](int st) {
        const bf16* Ah = tile(st, 0);
        const bf16* Al = tile(st, 1);
        const bf16* Wh = tile(st, 2);
        const bf16* Wl = tile(st, 3);
#pragma unroll
        for (int ks = 0; ks < 2; ++ks) {
            const int k = ks * 16;
            uint32_t ah[4][4], al[4][4], wh[4][2], wl[4][2];
#pragma unroll
            for (int mi = 0; mi < 4; ++mi) {
                const int so = (warp_m*64 + mi*16 + l16) * 40 + k + (lane >> 4) * 8;
                uint32_t adh = smem_u32(Ah + so);
                asm volatile("ldmatrix.sync.aligned.m8n8.x4.shared.b16 {%0,%1,%2,%3}, [%4];"
                             : "=r"(ah[mi][0]), "=r"(ah[mi][1]), "=r"(ah[mi][2]), "=r"(ah[mi][3])
                             : "r"(adh));
                uint32_t adl = smem_u32(Al + so);
                asm volatile("ldmatrix.sync.aligned.m8n8.x4.shared.b16 {%0,%1,%2,%3}, [%4];"
                             : "=r"(al[mi][0]), "=r"(al[mi][1]), "=r"(al[mi][2]), "=r"(al[mi][3])
                             : "r"(adl));
            }
#pragma unroll
            for (int ni = 0; ni < 4; ++ni) {
                const int so = (warp_n*32 + ni*8 + (l16 & 7)) * 40 + k + (l16 >> 3) * 8;
                uint32_t bdh = smem_u32(Wh + so);
                asm volatile("ldmatrix.sync.aligned.m8n8.x2.shared.b16 {%0,%1}, [%2];"
                             : "=r"(wh[ni][0]), "=r"(wh[ni][1]) : "r"(bdh));
                uint32_t bdl = smem_u32(Wl + so);
                asm volatile("ldmatrix.sync.aligned.m8n8.x2.shared.b16 {%0,%1}, [%2];"
                             : "=r"(wl[ni][0]), "=r"(wl[ni][1]) : "r"(bdl));
            }
#pragma unroll
            for (int mi = 0; mi < 4; ++mi)
#pragma unroll
                for (int ni = 0; ni < 4; ++ni) {
                    asm volatile(
                        "mma.sync.aligned.m16n8k16.row.col.f32.bf16.bf16.f32 "
                        "{%0,%1,%2,%3}, {%4,%5,%6,%7}, {%8,%9}, {%0,%1,%2,%3};"
                        : "+f"(acc[mi][ni][0]), "+f"(acc[mi][ni][1]),
                          "+f"(acc[mi][ni][2]), "+f"(acc[mi][ni][3])
                        : "r"(ah[mi][0]), "r"(ah[mi][1]), "r"(ah[mi][2]), "r"(ah[mi][3]),
                          "r"(wh[ni][0]), "r"(wh[ni][1]));
                    asm volatile(
                        "mma.sync.aligned.m16n8k16.row.col.f32.bf16.bf16.f32 "
                        "{%0,%1,%2,%3}, {%4,%5,%6,%7}, {%8,%9}, {%0,%1,%2,%3};"
                        : "+f"(acc[mi][ni][0]), "+f"(acc[mi][ni][1]),
                          "+f"(acc[mi][ni][2]), "+f"(acc[mi][ni][3])
                        : "r"(ah[mi][0]), "r"(ah[mi][1]), "r"(ah[mi][2]), "r"(ah[mi][3]),
                          "r"(wl[ni][0]), "r"(wl[ni][1]));
                    asm volatile(
                        "mma.sync.aligned.m16n8k16.row.col.f32.bf16.bf16.f32 "
                        "{%0,%1,%2,%3}, {%4,%5,%6,%7}, {%8,%9}, {%0,%1,%2,%3};"
                        : "+f"(acc[mi][ni][0]), "+f"(acc[mi][ni][1]),
                          "+f"(acc[mi][ni][2]), "+f"(acc[mi][ni][3])
                        : "r"(al[mi][0]), "r"(al[mi][1]), "r"(al[mi][2]), "r"(al[mi][3]),
                          "r"(wh[ni][0]), "r"(wh[ni][1]));
                }
        }
    };

    load_chunk(0, 0);
    CP_COMMIT();
    int buf = 0;
    for (int i = 0; i < KC; ++i) {
        if (i + 1 < KC) {
            load_chunk(buf ^ 1, i + 1);
            CP_COMMIT();
            CP_WAIT(1);
        } else {
            CP_WAIT(0);
        }
        __syncthreads();
        compute(buf);
        __syncthreads();
        buf ^= 1;
    }

    const int quad = lane >> 2, qi = lane & 3;
#pragma unroll
    for (int mi = 0; mi < 4; ++mi)
#pragma unroll
        for (int ni = 0; ni < 4; ++ni)
#pragma unroll
            for (int h = 0; h < 2; ++h) {
                const int row = m0 + warp_m * 64 + mi * 16 + quad + h * 8;
                const int col = n0 + warp_n * 32 + ni * 8 + qi * 2;
                float v0 = acc[mi][ni][h * 2 + 0] + bias[col];
                float v1 = acc[mi][ni][h * 2 + 1] + bias[col + 1];
                if (bias2) { v0 += bias2[col]; v1 += bias2[col + 1]; }
                const size_t o = (size_t)row * ldo + col;
                if (gelu) {
                    v0 = 0.5f * v0 * (1.0f + erff(v0 * 0.70710678118654752f));
                    v1 = 0.5f * v1 * (1.0f + erff(v1 * 0.70710678118654752f));
                }
                if (outf) { outf[o] = v0; outf[o + 1] = v1; }
                if (ohi) {
                    bf16 h0 = __float2bfloat16(v0), h1 = __float2bfloat16(v1);
                    ohi[o]     = h0; olo[o]     = __float2bfloat16(v0 - __bfloat162float(h0));
                    ohi[o + 1] = h1; olo[o + 1] = __float2bfloat16(v1 - __bfloat162float(h1));
                }
            }
}

// ---------------- embedding + positional encoding (writes hi/lo) ------------
__global__ void embed_kernel(const float* __restrict__ x,
                             const float* __restrict__ tokW,
                             const float* __restrict__ tokb,
                             bf16* __restrict__ hhi, bf16* __restrict__ hlo)
{
    size_t idx = (size_t)blockIdx.x * 256 + threadIdx.x;
    size_t token = idx >> 7;
    int d = (int)(idx & 127);
    int t = (int)((token / NN) % TT);
    const float* xp = x + token * FINN;
    float val = xp[0]*tokW[d*3+0] + xp[1]*tokW[d*3+1] + xp[2]*tokW[d*3+2] + tokb[d];
    int i2 = d & ~1;
    float div = expf((float)i2 * (-logf(10000.0f) / (float)DD));
    float ang = (float)t * div;
    val += (d & 1) ? cosf(ang) : sinf(ang);
    bf16 h = __float2bfloat16(val);
    hhi[idx] = h;
    hlo[idx] = __float2bfloat16(val - __bfloat162float(h));
}

// ---------------- temporal attention (over T=12) — writes hi/lo -------------
__global__ void temporal_attn_kernel(const float* __restrict__ qkv,
                                     bf16* __restrict__ ohi, bf16* __restrict__ olo)
{
    const int bidx = blockIdx.x;
    const int b = bidx >> 9, n = bidx & 511;
    const int tid = threadIdx.x;
    __shared__ float q[TT][DD], k[TT][DD], v[TT][DD];
    __shared__ float S[HH][TT][TT];
#pragma unroll
    for (int t = 0; t < TT; ++t) {
        size_t row = ((size_t)(b*TT + t) * NN + n) * 384;
        q[t][tid] = qkv[row + tid];
        k[t][tid] = qkv[row + 128 + tid];
        v[t][tid] = qkv[row + 256 + tid];
    }
    __syncthreads();
    const float scale = 0.17677669529663687f;
    for (int idx = tid; idx < HH*TT*TT; idx += 128) {
        int hh = idx / (TT*TT);
        int rem = idx - hh*(TT*TT);
        int xx = rem / TT, yy = rem - xx*TT;
        float s = 0.f;
#pragma unroll
        for (int e = 0; e < 32; ++e)
            s = fmaf(q[xx][hh*32+e], k[yy][hh*32+e], s);
        S[hh][xx][yy] = s * scale;
    }
    __syncthreads();
    if (tid < HH*TT) {
        int hh = tid / TT, xx = tid % TT;
        float mx = -1e30f;
#pragma unroll
        for (int y = 0; y < TT; ++y) mx = fmaxf(mx, S[hh][xx][y]);
        float sum = 0.f;
#pragma unroll
        for (int y = 0; y < TT; ++y) { float p = __expf(S[hh][xx][y]-mx); S[hh][xx][y] = p; sum += p; }
        float inv = 1.f / sum;
#pragma unroll
        for (int y = 0; y < TT; ++y) S[hh][xx][y] *= inv;
    }
    __syncthreads();
    const int hh = tid >> 5;
    for (int xx = 0; xx < TT; ++xx) {
        float o = 0.f;
#pragma unroll
        for (int yy = 0; yy < TT; ++yy) o = fmaf(S[hh][xx][yy], v[yy][tid], o);
        size_t oi = ((size_t)(b*TT + xx) * NN + n) * DD + tid;
        bf16 h = __float2bfloat16(o);
        ohi[oi] = h;
        olo[oi] = __float2bfloat16(o - __bfloat162float(h));
    }
}

// ============ merged spatial attention (geo+sem, flash, fp16) ===============
// qkv: [tok,768] (geo q|k|v then sem q|k|v). blockIdx.y: sel = y>>2, head = y&3.
__global__ void __launch_bounds__(256, 1)
spatial_attn_mma(const float* __restrict__ qkv,
                 bf16* __restrict__ ghi, bf16* __restrict__ glo,
                 bf16* __restrict__ shi, bf16* __restrict__ slo)
{
    const int qtile = blockIdx.x;
    const int sel   = blockIdx.y >> 2;
    const int head  = blockIdx.y & 3;
    const int bt    = blockIdx.z;
    const int tid  = threadIdx.x;
    const int wid  = tid >> 5;
    const int lane = tid & 31;
    const int l16  = lane & 15;

    bf16* outhi = sel ? shi : ghi;
    bf16* outlo = sel ? slo : glo;
    const int colq = sel * 384 + head * 32;

    __shared__ __half Qs[128][40];
    __shared__ __half Ks[128][40];
    __shared__ __half Vt[32][136];

    const size_t base = (size_t)bt * NN;
    const float scale = 0.17677669529663687f;

    for (int i = tid; i < 128*32; i += 256) {
        int r = i >> 5, e = i & 31;
        Qs[r][e] = __float2half(qkv[(base + (size_t)qtile*128 + r)*768 + colq + e] * scale);
    }
    __syncthreads();

    uint32_t qf[2][4];
#pragma unroll
    for (int kc = 0; kc < 2; ++kc) {
        uint32_t ad = smem_u32(&Qs[wid*16 + l16][kc*16 + (lane>>4)*8]);
        asm volatile("ldmatrix.sync.aligned.m8n8.x4.shared.b16 {%0,%1,%2,%3}, [%4];"
                     : "=r"(qf[kc][0]), "=r"(qf[kc][1]), "=r"(qf[kc][2]), "=r"(qf[kc][3])
                     : "r"(ad));
    }

    float m0 = -1e30f, m1 = -1e30f, l0 = 0.f, l1 = 0.f;
    float oacc[4][4];
#pragma unroll
    for (int ef = 0; ef < 4; ++ef)
#pragma unroll
        for (int r = 0; r < 4; ++r) oacc[ef][r] = 0.f;

    for (int kt = 0; kt < 4; ++kt) {
        __syncthreads();
        for (int i = tid; i < 128*32; i += 256) {
            int j = i >> 5, e = i & 31;
            const float* rp = qkv + (base + (size_t)kt*128 + j)*768 + colq + 128 + e;
            Ks[j][e] = __float2half(rp[0]);
            Vt[e][j] = __float2half(rp[128]);
        }
        __syncthreads();

        float sacc[16][4];
#pragma unroll
        for (int nf = 0; nf < 16; ++nf) {
            sacc[nf][0] = sacc[nf][1] = sacc[nf][2] = sacc[nf][3] = 0.f;
#pragma unroll
            for (int kc = 0; kc < 2; ++kc) {
                uint32_t b0, b1;
                uint32_t bd = smem_u32(&Ks[nf*8 + (l16 & 7)][kc*16 + (l16 >> 3)*8]);
                asm volatile("ldmatrix.sync.aligned.m8n8.x2.shared.b16 {%0,%1}, [%2];"
                             : "=r"(b0), "=r"(b1) : "r"(bd));
                asm volatile(
                    "mma.sync.aligned.m16n8k16.row.col.f32.f16.f16.f32 "
                    "{%0,%1,%2,%3}, {%4,%5,%6,%7}, {%8,%9}, {%0,%1,%2,%3};"
                    : "+f"(sacc[nf][0]), "+f"(sacc[nf][1]),
                      "+f"(sacc[nf][2]), "+f"(sacc[nf][3])
                    : "r"(qf[kc][0]), "r"(qf[kc][1]), "r"(qf[kc][2]), "r"(qf[kc][3]),
                      "r"(b0), "r"(b1));
            }
        }

        float mx0 = -1e30f, mx1 = -1e30f;
#pragma unroll
        for (int nf = 0; nf < 16; ++nf) {
            mx0 = fmaxf(mx0, fmaxf(sacc[nf][0], sacc[nf][1]));
            mx1 = fmaxf(mx1, fmaxf(sacc[nf][2], sacc[nf][3]));
        }
        mx0 = fmaxf(mx0, __shfl_xor_sync(0xffffffffu, mx0, 1));
        mx0 = fmaxf(mx0, __shfl_xor_sync(0xffffffffu, mx0, 2));
        mx1 = fmaxf(mx1, __shfl_xor_sync(0xffffffffu, mx1, 1));
        mx1 = fmaxf(mx1, __shfl_xor_sync(0xffffffffu, mx1, 2));
        const float nm0 = fmaxf(m0, mx0), nm1 = fmaxf(m1, mx1);
        const float c0 = __expf(m0 - nm0), c1 = __expf(m1 - nm1);
        m0 = nm0; m1 = nm1;
#pragma unroll
        for (int ef = 0; ef < 4; ++ef) {
            oacc[ef][0] *= c0; oacc[ef][1] *= c0;
            oacc[ef][2] *= c1; oacc[ef][3] *= c1;
        }

        float rs0 = 0.f, rs1 = 0.f;
#pragma unroll
        for (int jc = 0; jc < 8; ++jc) {
            float p00 = __expf(sacc[2*jc][0]   - nm0);
            float p01 = __expf(sacc[2*jc][1]   - nm0);
            float p10 = __expf(sacc[2*jc][2]   - nm1);
            float p11 = __expf(sacc[2*jc][3]   - nm1);
            float p20 = __expf(sacc[2*jc+1][0] - nm0);
            float p21 = __expf(sacc[2*jc+1][1] - nm0);
            float p30 = __expf(sacc[2*jc+1][2] - nm1);
            float p31 = __expf(sacc[2*jc+1][3] - nm1);
            rs0 += p00 + p01 + p20 + p21;
            rs1 += p10 + p11 + p30 + p31;
            uint32_t pf0 = pack2h(p00, p01);
            uint32_t pf1 = pack2h(p10, p11);
            uint32_t pf2 = pack2h(p20, p21);
            uint32_t pf3 = pack2h(p30, p31);
#pragma unroll
            for (int ef = 0; ef < 4; ++ef) {
                uint32_t b0, b1;
                uint32_t bd = smem_u32(&Vt[ef*8 + (l16 & 7)][jc*16 + (l16 >> 3)*8]);
                asm volatile("ldmatrix.sync.aligned.m8n8.x2.shared.b16 {%0,%1}, [%2];"
                             : "=r"(b0), "=r"(b1) : "r"(bd));
                asm volatile(
                    "mma.sync.aligned.m16n8k16.row.col.f32.f16.f16.f32 "
                    "{%0,%1,%2,%3}, {%4,%5,%6,%7}, {%8,%9}, {%0,%1,%2,%3};"
                    : "+f"(oacc[ef][0]), "+f"(oacc[ef][1]),
                      "+f"(oacc[ef][2]), "+f"(oacc[ef][3])
                    : "r"(pf0), "r"(pf1), "r"(pf2), "r"(pf3),
                      "r"(b0), "r"(b1));
            }
        }
        rs0 += __shfl_xor_sync(0xffffffffu, rs0, 1);
        rs0 += __shfl_xor_sync(0xffffffffu, rs0, 2);
        rs1 += __shfl_xor_sync(0xffffffffu, rs1, 1);
        rs1 += __shfl_xor_sync(0xffffffffu, rs1, 2);
        l0 = l0 * c0 + rs0;
        l1 = l1 * c1 + rs1;
    }

    const float i0 = 1.f / l0, i1 = 1.f / l1;
    const int r0 = wid*16 + (lane >> 2);
#pragma unroll
    for (int ef = 0; ef < 4; ++ef) {
        const int col = head*32 + ef*8 + (lane & 3)*2;
        size_t rowA = (base + (size_t)qtile*128 + r0) * DD + col;
        size_t rowB = (base + (size_t)qtile*128 + r0 + 8) * DD + col;
        float v0 = oacc[ef][0] * i0, v1 = oacc[ef][1] * i0;
        float v2 = oacc[ef][2] * i1, v3 = oacc[ef][3] * i1;
        bf16 h0 = __float2bfloat16(v0), h1 = __float2bfloat16(v1);
        bf16 h2 = __float2bfloat16(v2), h3 = __float2bfloat16(v3);
        outhi[rowA]   = h0; outlo[rowA]   = __float2bfloat16(v0 - __bfloat162float(h0));
        outhi[rowA+1] = h1; outlo[rowA+1] = __float2bfloat16(v1 - __bfloat162float(h1));
        outhi[rowB]   = h2; outlo[rowB]   = __float2bfloat16(v2 - __bfloat162float(h2));
        outhi[rowB+1] = h3; outlo[rowB+1] = __float2bfloat16(v3 - __bfloat162float(h3));
    }
}

// ---------------- layernorm — writes hi/lo + fp32 slice of xc ---------------
__global__ void ln_kernel(const float* __restrict__ pre, const float* __restrict__ g,
                          const float* __restrict__ bta,
                          bf16* __restrict__ hhi, bf16* __restrict__ hlo,
                          float* __restrict__ xc)
{
    const int warp = threadIdx.x >> 5, lane = threadIdx.x & 31;
    size_t token = (size_t)blockIdx.x * 8 + warp;
    const float* p = pre + token * DD;
    float v[4];
#pragma unroll
    for (int i = 0; i < 4; ++i) v[i] = p[lane + 32*i];
    float s = v[0] + v[1] + v[2] + v[3];
#pragma unroll
    for (int o = 16; o; o >>= 1) s += __shfl_xor_sync(0xffffffffu, s, o);
    float mean = s * (1.f/128.f);
    float q = 0.f;
#pragma unroll
    for (int i = 0; i < 4; ++i) { v[i] -= mean; q += v[i]*v[i]; }
#pragma unroll
    for (int o = 16; o; o >>= 1) q += __shfl_xor_sync(0xffffffffu, q, o);
    float inv = rsqrtf(q * (1.f/128.f) + 1e-5f);
#pragma unroll
    for (int i = 0; i < 4; ++i) {
        int d = lane + 32*i;
        float o = v[i] * inv * g[d] + bta[d];
        bf16 h = __float2bfloat16(o);
        hhi[token*DD + d] = h;
        hlo[token*DD + d] = __float2bfloat16(o - __bfloat162float(h));
        xc[token*(LL*DD) + d] = o;
    }
}

// ---------------- output head ------------------------------------------------
__global__ void head_kernel(const float* __restrict__ xc, const float* __restrict__ w1g,
                            const float* __restrict__ b1g, const float* __restrict__ w2g,
                            const float* __restrict__ b2g, float* __restrict__ y)
{
    const int bidx = blockIdx.x;
    const int b = bidx >> 9, n = bidx & 511;
    const int tid = threadIdx.x;
    __shared__ float xs[TT][LL*DD];
    __shared__ float w1[PP][TT];
    __shared__ float b1[PP];
    __shared__ float w2[LL*DD];
    __shared__ float red[PP][4];
    for (int t = 0; t < TT; ++t) {
        size_t rowoff = ((size_t)(b*TT + t) * NN + n) * (LL*DD);
        for (int c = tid; c < LL*DD; c += 128) xs[t][c] = xc[rowoff + c];
    }
    for (int i = tid; i < PP*TT; i += 128) w1[i/TT][i%TT] = w1g[i];
    if (tid < PP) b1[tid] = b1g[tid];
    for (int c = tid; c < LL*DD; c += 128) w2[c] = w2g[c];
    __syncthreads();

    float part[PP];
#pragma unroll
    for (int p = 0; p < PP; ++p) part[p] = 0.f;
    for (int c = tid; c < LL*DD; c += 128) {
        float xt[TT];
#pragma unroll
        for (int t = 0; t < TT; ++t) xt[t] = xs[t][c];
        float wc = w2[c];
#pragma unroll
        for (int p = 0; p < PP; ++p) {
            float sacc = b1[p];
#pragma unroll
            for (int t = 0; t < TT; ++t) sacc = fmaf(xt[t], w1[p][t], sacc);
            sacc = fmaxf(sacc, 0.f);
            part[p] = fmaf(sacc, wc, part[p]);
        }
    }
    const int warp = tid >> 5, lane = tid & 31;
#pragma unroll
    for (int p = 0; p < PP; ++p) {
        float sv = part[p];
#pragma unroll
        for (int o = 16; o; o >>= 1) sv += __shfl_xor_sync(0xffffffffu, sv, o);
        if (lane == 0) red[p][warp] = sv;
    }
    __syncthreads();
    if (tid < PP) {
        float sv = red[tid][0] + red[tid][1] + red[tid][2] + red[tid][3];
        y[(size_t)(b*PP + tid) * NN + n] = sv + b2g[0];
    }
}

// ---------------- launcher ---------------------------------------------------
extern "C" void kernel_launch(void* const* d_in, const int* in_sizes, int n_in,
                              void* d_out, int out_size)
{
    (void)in_sizes; (void)n_in; (void)out_size;
    const float* x      = (const float*)d_in[0];
    const float* tokW   = (const float*)d_in[1];
    const float* tokb   = (const float*)d_in[2];
    const float* t_qkvW = (const float*)d_in[3];
    const float* t_qkvb = (const float*)d_in[4];
    const float* t_pW   = (const float*)d_in[5];
    const float* t_pb   = (const float*)d_in[6];
    const float* g_qkvW = (const float*)d_in[7];
    const float* g_qkvb = (const float*)d_in[8];
    const float* g_pW   = (const float*)d_in[9];
    const float* g_pb   = (const float*)d_in[10];
    const float* s_qkvW = (const float*)d_in[11];
    const float* s_qkvb = (const float*)d_in[12];
    const float* s_pW   = (const float*)d_in[13];
    const float* s_pb   = (const float*)d_in[14];
    const float* resW   = (const float*)d_in[15];
    const float* resb   = (const float*)d_in[16];
    const float* normW  = (const float*)d_in[17];
    const float* normb  = (const float*)d_in[18];
    const float* fc1W   = (const float*)d_in[19];
    const float* fc1b   = (const float*)d_in[20];
    const float* fc2W   = (const float*)d_in[21];
    const float* fc2b   = (const float*)d_in[22];
    const float* e1W    = (const float*)d_in[23];
    const float* e1b    = (const float*)d_in[24];
    const float* e2W    = (const float*)d_in[25];
    const float* e2b    = (const float*)d_in[26];
    float* out = (float*)d_out;

    float *qkvB, *qkv12B, *preB, *xcB, *bgsB;
    cudaGetSymbolAddress((void**)&qkvB,   g_qkv);
    cudaGetSymbolAddress((void**)&qkv12B, g_qkv12);
    cudaGetSymbolAddress((void**)&preB,   g_pre);
    cudaGetSymbolAddress((void**)&xcB,    g_xc);
    cudaGetSymbolAddress((void**)&bgsB,   b_gs);

    bf16 *hAh,*hAl,*hBh,*hBl,*ath,*atl,*a2h,*a2l,*cth,*ctl,*mlh,*mll;
    cudaGetSymbolAddress((void**)&hAh, a_hA_hi); cudaGetSymbolAddress((void**)&hAl, a_hA_lo);
    cudaGetSymbolAddress((void**)&hBh, a_hB_hi); cudaGetSymbolAddress((void**)&hBl, a_hB_lo);
    cudaGetSymbolAddress((void**)&ath, a_at_hi); cudaGetSymbolAddress((void**)&atl, a_at_lo);
    cudaGetSymbolAddress((void**)&a2h, a_a2_hi); cudaGetSymbolAddress((void**)&a2l, a_a2_lo);
    cudaGetSymbolAddress((void**)&cth, a_ct_hi); cudaGetSymbolAddress((void**)&ctl, a_ct_lo);
    cudaGetSymbolAddress((void**)&mlh, a_ml_hi); cudaGetSymbolAddress((void**)&mll, a_ml_lo);

    bf16 *tqh,*tql,*gsh,*gsl,*tph,*tpl,*gph,*gpl,*sph,*spl,*f1h,*f1l,*cbh,*cbl;
    cudaGetSymbolAddress((void**)&tqh, w_tq_hi); cudaGetSymbolAddress((void**)&tql, w_tq_lo);
    cudaGetSymbolAddress((void**)&gsh, w_gs_hi); cudaGetSymbolAddress((void**)&gsl, w_gs_lo);
    cudaGetSymbolAddress((void**)&tph, w_tp_hi); cudaGetSymbolAddress((void**)&tpl, w_tp_lo);
    cudaGetSymbolAddress((void**)&gph, w_gp_hi); cudaGetSymbolAddress((void**)&gpl, w_gp_lo);
    cudaGetSymbolAddress((void**)&sph, w_sp_hi); cudaGetSymbolAddress((void**)&spl, w_sp_lo);
    cudaGetSymbolAddress((void**)&f1h, w_f1_hi); cudaGetSymbolAddress((void**)&f1l, w_f1_lo);
    cudaGetSymbolAddress((void**)&cbh, w_cb_hi); cudaGetSymbolAddress((void**)&cbl, w_cb_lo);

    cudaFuncSetAttribute(mma_gemm, cudaFuncAttributeMaxDynamicSharedMemorySize, 81920);
    const int DSM = 81920;
    const int MBt = TOK / 128;

    // total cvt elements
    const int CVT_N = LL*3*DD*DD + LL*6*DD*DD + 3*(LL*DD*DD) + LL*HMM*2*DD + LL*DD*(HMM+DD);
    cvt_all<<<(CVT_N+255)/256, 256>>>(t_qkvW, g_qkvW, s_qkvW, t_pW, g_pW, s_pW,
                                      fc1W, fc2W, resW, g_qkvb, s_qkvb);

    embed_kernel<<<(TOK*DD)/256, 256>>>(x, tokW, tokb, hAh, hAl);

    for (int l = 0; l < LL; ++l) {
        const size_t oq = (size_t)l*3*DD*DD, oqb = (size_t)l*3*DD;
        const size_t op = (size_t)l*DD*DD,   opb = (size_t)l*DD;
        const size_t ogs = (size_t)l*6*DD*DD;

        // temporal attention
        mma_gemm<<<dim3(3, MBt), 256, DSM>>>(hAh, hAl, DD, nullptr, nullptr, 0,
                                             tqh+oq, tql+oq, t_qkvb+oqb, nullptr,
                                             qkvB, nullptr, nullptr, 3*DD, 0);
        temporal_attn_kernel<<<BB*NN, 128>>>(qkvB, ath, atl);
        mma_gemm<<<dim3(1, MBt), 256, DSM>>>(ath, atl, DD, nullptr, nullptr, 0,
                                             tph+op, tpl+op, t_pb+opb, nullptr,
                                             nullptr, hBh, hBl, DD, 0);
        // merged geo+sem qkv -> qkv12 [tok,768]
        mma_gemm<<<dim3(6, MBt), 256, DSM>>>(hBh, hBl, DD, nullptr, nullptr, 0,
                                             gsh+ogs, gsl+ogs, bgsB + (size_t)l*768, nullptr,
                                             qkv12B, nullptr, nullptr, 6*DD, 0);
        // merged spatial attention: geo -> at, sem -> a2
        spatial_attn_mma<<<dim3(NN/128, 2*HH, BB*TT), 256>>>(qkv12B, ath, atl, a2h, a2l);
        // projections into cat
        mma_gemm<<<dim3(1, MBt), 256, DSM>>>(ath, atl, DD, nullptr, nullptr, 0,
                                             gph+op, gpl+op, g_pb+opb, nullptr,
                                             nullptr, cth, ctl, 2*DD, 0);
        mma_gemm<<<dim3(1, MBt), 256, DSM>>>(a2h, a2l, DD, nullptr, nullptr, 0,
                                             sph+op, spl+op, s_pb+opb, nullptr,
                                             nullptr, cth+DD, ctl+DD, 2*DD, 0);
        // MLP fc1 (+gelu)
        mma_gemm<<<dim3(2, MBt), 256, DSM>>>(cth, ctl, 2*DD, nullptr, nullptr, 0,
                                             f1h+(size_t)l*HMM*2*DD, f1l+(size_t)l*HMM*2*DD,
                                             fc1b+(size_t)l*HMM, nullptr,
                                             nullptr, mlh, mll, HMM, 1);
        // fused fc2 + residual-linear
        mma_gemm<<<dim3(1, MBt), 256, DSM>>>(mlh, mll, HMM, hAh, hAl, DD,
                                             cbh+(size_t)l*DD*(HMM+DD), cbl+(size_t)l*DD*(HMM+DD),
                                             fc2b+opb, resb+opb,
                                             preB, nullptr, nullptr, DD, 0);
        ln_kernel<<<TOK/8, 256>>>(preB, normW+opb, normb+opb, hAh, hAl, xcB + (size_t)l*DD);
    }

    head_kernel<<<BB*NN, 128>>>(xcB, e1W, e1b, e2W, e2b, out);
}

// round 8
// speedup vs baseline: 2.1414x; 1.0094x over previous
#include <cuda_runtime.h>
#include <cuda_bf16.h>
#include <cuda_fp16.h>
#include <math.h>
#include <stdint.h>

#define BB   8
#define TT   12
#define NN   512
#define FINN 3
#define DD   128
#define HH   4
#define HMM  256
#define LL   3
#define PP   12
#define TOK  (BB*TT*NN)          // 49152 tokens

typedef __nv_bfloat16 bf16;

// ---------------- fp32 scratch ----------------------------------------------
__device__ float g_qkv  [TOK*3*DD];    // temporal qkv [tok,384]
__device__ float g_qkv12[TOK*6*DD];    // geo|sem qkv  [tok,768]
__device__ float g_pre[TOK*DD];
__device__ float g_xc [TOK*LL*DD];
__device__ float b_gs [LL*6*DD];       // combined geo|sem qkv bias
// ---------------- bf16 hi/lo activation scratch -----------------------------
__device__ bf16 a_hA_hi[TOK*DD];   __device__ bf16 a_hA_lo[TOK*DD];
__device__ bf16 a_hB_hi[TOK*DD];   __device__ bf16 a_hB_lo[TOK*DD];
__device__ bf16 a_at_hi[TOK*DD];   __device__ bf16 a_at_lo[TOK*DD];
__device__ bf16 a_a2_hi[TOK*DD];   __device__ bf16 a_a2_lo[TOK*DD];
__device__ bf16 a_ct_hi[TOK*2*DD]; __device__ bf16 a_ct_lo[TOK*2*DD];
__device__ bf16 a_ml_hi[TOK*HMM];  __device__ bf16 a_ml_lo[TOK*HMM];
// ---------------- bf16 hi/lo weights ----------------------------------------
__device__ bf16 w_tq_hi[LL*3*DD*DD]; __device__ bf16 w_tq_lo[LL*3*DD*DD];
__device__ bf16 w_gs_hi[LL*6*DD*DD]; __device__ bf16 w_gs_lo[LL*6*DD*DD];
__device__ bf16 w_tp_hi[LL*DD*DD];   __device__ bf16 w_tp_lo[LL*DD*DD];
__device__ bf16 w_gp_hi[LL*DD*DD];   __device__ bf16 w_gp_lo[LL*DD*DD];
__device__ bf16 w_sp_hi[LL*DD*DD];   __device__ bf16 w_sp_lo[LL*DD*DD];
__device__ bf16 w_f1_hi[LL*HMM*2*DD];__device__ bf16 w_f1_lo[LL*HMM*2*DD];
__device__ bf16 w_cb_hi[LL*DD*(HMM+DD)]; __device__ bf16 w_cb_lo[LL*DD*(HMM+DD)];

__device__ __forceinline__ uint32_t smem_u32(const void* p) {
    uint32_t a;
    asm("{ .reg .u64 t; cvta.to.shared.u64 t, %1; cvt.u32.u64 %0, t; }"
        : "=r"(a) : "l"(p));
    return a;
}
__device__ __forceinline__ uint32_t pack2h(float a, float b) {
    __half2 h = __floats2half2_rn(a, b);
    return *(uint32_t*)&h;
}
#define CP_ASYNC16(dst, src) \
    asm volatile("cp.async.cg.shared.global [%0], [%1], 16;" :: "r"(dst), "l"(src))
#define CP_COMMIT() asm volatile("cp.async.commit_group;" ::: "memory")
#define CP_WAIT(n)  asm volatile("cp.async.wait_group %0;" :: "n"(n) : "memory")

// ================= one-shot weight conversion ================================
__global__ void cvt_all(const float* __restrict__ t_qkvW,
                        const float* __restrict__ g_qkvW, const float* __restrict__ s_qkvW,
                        const float* __restrict__ t_pW,   const float* __restrict__ g_pW,
                        const float* __restrict__ s_pW,   const float* __restrict__ fc1W,
                        const float* __restrict__ fc2W,   const float* __restrict__ resW,
                        const float* __restrict__ g_qkvb, const float* __restrict__ s_qkvb)
{
    int i = blockIdx.x * 256 + threadIdx.x;
    const int NQ  = LL*3*DD*DD;
    const int NGS = LL*6*DD*DD;
    const int NPw = LL*DD*DD;
    const int NF1 = LL*HMM*2*DD;
    const int NCB = LL*DD*(HMM+DD);
    float v; bf16 *hi, *lo; int off;
    if (i < NQ) { v = t_qkvW[i]; hi = w_tq_hi; lo = w_tq_lo; off = i; }
    else if ((i -= NQ) < NGS) {
        int l = i / (768*DD), r = (i / DD) % 768, k = i % DD;
        v = (r < 384) ? g_qkvW[((size_t)l*384 + r)*DD + k]
                      : s_qkvW[((size_t)l*384 + (r-384))*DD + k];
        if (k == 0) b_gs[l*768 + r] = (r < 384) ? g_qkvb[l*384 + r] : s_qkvb[l*384 + r - 384];
        hi = w_gs_hi; lo = w_gs_lo; off = i;
    }
    else if ((i -= NGS) < NPw) { v = t_pW[i]; hi = w_tp_hi; lo = w_tp_lo; off = i; }
    else if ((i -= NPw) < NPw) { v = g_pW[i]; hi = w_gp_hi; lo = w_gp_lo; off = i; }
    else if ((i -= NPw) < NPw) { v = s_pW[i]; hi = w_sp_hi; lo = w_sp_lo; off = i; }
    else if ((i -= NPw) < NF1) { v = fc1W[i]; hi = w_f1_hi; lo = w_f1_lo; off = i; }
    else if ((i -= NF1) < NCB) {
        const int KK = HMM + DD;
        int l = i / (DD*KK), r = (i / KK) % DD, k = i % KK;
        v = (k < HMM) ? fc2W[((size_t)l*DD + r)*HMM + k]
                      : resW[((size_t)l*DD + r)*DD + (k - HMM)];
        hi = w_cb_hi; lo = w_cb_lo; off = i;
    }
    else return;
    bf16 h = __float2bfloat16(v);
    hi[off] = h;
    lo[off] = __float2bfloat16(v - __bfloat162float(h));
}

// ================= chunk-fused 3-term mma GEMM (spill-free) ==================
// C = act(concat(A1,A2) @ W^T + bias [+bias2]); per 32-wide k-chunk loads the
// 4 unique tiles (a_hi, a_lo, w_hi, w_lo) once into smem; compute does 3
// sequential register phases: (ah,wh)->hh, reload w<-wl ->hl, reload a<-al,
// w<-wh ->lh. Peak live frags = 24 regs + 64 acc => no spills at 128-reg cap.
__global__ void __launch_bounds__(256, 2)
mma_gemm(const bf16* __restrict__ A1hi, const bf16* __restrict__ A1lo, int K1,
         const bf16* __restrict__ A2hi, const bf16* __restrict__ A2lo, int K2,
         const bf16* __restrict__ Whi, const bf16* __restrict__ Wlo,
         const float* __restrict__ bias, const float* __restrict__ bias2,
         float* __restrict__ outf, bf16* __restrict__ ohi,
         bf16* __restrict__ olo, int ldo, int gelu)
{
    extern __shared__ bf16 sm[];      // [2][4][128*40]
    const int tid  = threadIdx.x;
    const int wid  = tid >> 5;
    const int lane = tid & 31;
    const int l16  = lane & 15;
    const int warp_m = wid >> 2;
    const int warp_n = wid & 3;
    const int m0 = blockIdx.y * 128;
    const int n0 = blockIdx.x * 128;
    const int K  = K1 + K2;
    const int KC = K >> 5;

    float acc[4][4][4];
#pragma unroll
    for (int mi = 0; mi < 4; ++mi)
#pragma unroll
        for (int ni = 0; ni < 4; ++ni)
#pragma unroll
            for (int r = 0; r < 4; ++r) acc[mi][ni][r] = 0.f;

    auto tile = [&](int st, int w) -> bf16* { return sm + (size_t)(st*4 + w) * 5120; };

    auto load_chunk = [&](int st, int kp) {
        const int kof = kp * 32;
        const bf16 *Ah, *Al; int lda, acol;
        if (kof < K1) { Ah = A1hi; Al = A1lo; lda = K1; acol = kof; }
        else          { Ah = A2hi; Al = A2lo; lda = K2; acol = kof - K1; }
        bf16* d0 = tile(st, 0); bf16* d1 = tile(st, 1);
        bf16* d2 = tile(st, 2); bf16* d3 = tile(st, 3);
#pragma unroll
        for (int t = 0; t < 2; ++t) {
            const int c   = tid + t * 256;
            const int row = c >> 2;
            const int cc  = (c & 3) * 8;
            const size_t aoff = (size_t)(m0 + row) * lda + acol + cc;
            const size_t woff = (size_t)(n0 + row) * K + kof + cc;
            const int so = row * 40 + cc;
            CP_ASYNC16(smem_u32(d0 + so), Ah  + aoff);
            CP_ASYNC16(smem_u32(d1 + so), Al  + aoff);
            CP_ASYNC16(smem_u32(d2 + so), Whi + woff);
            CP_ASYNC16(smem_u32(d3 + so), Wlo + woff);
        }
    };

    auto lda4 = [&](uint32_t (&a)[4][4], const bf16* T, int k) {
#pragma unroll
        for (int mi = 0; mi < 4; ++mi) {
            const int so = (warp_m*64 + mi*16 + l16) * 40 + k + (lane >> 4) * 8;
            uint32_t ad = smem_u32(T + so);
            asm volatile("ldmatrix.sync.aligned.m8n8.x4.shared.b16 {%0,%1,%2,%3}, [%4];"
                         : "=r"(a[mi][0]), "=r"(a[mi][1]), "=r"(a[mi][2]), "=r"(a[mi][3])
                         : "r"(ad));
        }
    };
    auto ldw2 = [&](uint32_t (&w)[4][2], const bf16* T, int k) {
#pragma unroll
        for (int ni = 0; ni < 4; ++ni) {
            const int so = (warp_n*32 + ni*8 + (l16 & 7)) * 40 + k + (l16 >> 3) * 8;
            uint32_t bd = smem_u32(T + so);
            asm volatile("ldmatrix.sync.aligned.m8n8.x2.shared.b16 {%0,%1}, [%2];"
                         : "=r"(w[ni][0]), "=r"(w[ni][1]) : "r"(bd));
        }
    };
    auto domma = [&](uint32_t (&a)[4][4], uint32_t (&w)[4][2]) {
#pragma unroll
        for (int mi = 0; mi < 4; ++mi)
#pragma unroll
            for (int ni = 0; ni < 4; ++ni)
                asm volatile(
                    "mma.sync.aligned.m16n8k16.row.col.f32.bf16.bf16.f32 "
                    "{%0,%1,%2,%3}, {%4,%5,%6,%7}, {%8,%9}, {%0,%1,%2,%3};"
                    : "+f"(acc[mi][ni][0]), "+f"(acc[mi][ni][1]),
                      "+f"(acc[mi][ni][2]), "+f"(acc[mi][ni][3])
                    : "r"(a[mi][0]), "r"(a[mi][1]), "r"(a[mi][2]), "r"(a[mi][3]),
                      "r"(w[ni][0]), "r"(w[ni][1]));
    };

    auto compute = [&](int st) {
        const bf16* Ah = tile(st, 0);
        const bf16* Al = tile(st, 1);
        const bf16* Wh = tile(st, 2);
        const bf16* Wl = tile(st, 3);
#pragma unroll
        for (int ks = 0; ks < 2; ++ks) {
            const int k = ks * 16;
            uint32_t a[4][4], w[4][2];
            lda4(a, Ah, k);
            ldw2(w, Wh, k);
            domma(a, w);          // hi*hi
            ldw2(w, Wl, k);
            domma(a, w);          // hi*lo
            lda4(a, Al, k);
            ldw2(w, Wh, k);
            domma(a, w);          // lo*hi
        }
    };

    load_chunk(0, 0);
    CP_COMMIT();
    int buf = 0;
    for (int i = 0; i < KC; ++i) {
        if (i + 1 < KC) {
            load_chunk(buf ^ 1, i + 1);
            CP_COMMIT();
            CP_WAIT(1);
        } else {
            CP_WAIT(0);
        }
        __syncthreads();
        compute(buf);
        __syncthreads();
        buf ^= 1;
    }

    const int quad = lane >> 2, qi = lane & 3;
#pragma unroll
    for (int mi = 0; mi < 4; ++mi)
#pragma unroll
        for (int ni = 0; ni < 4; ++ni)
#pragma unroll
            for (int h = 0; h < 2; ++h) {
                const int row = m0 + warp_m * 64 + mi * 16 + quad + h * 8;
                const int col = n0 + warp_n * 32 + ni * 8 + qi * 2;
                float v0 = acc[mi][ni][h * 2 + 0] + bias[col];
                float v1 = acc[mi][ni][h * 2 + 1] + bias[col + 1];
                if (bias2) { v0 += bias2[col]; v1 += bias2[col + 1]; }
                const size_t o = (size_t)row * ldo + col;
                if (gelu) {
                    v0 = 0.5f * v0 * (1.0f + erff(v0 * 0.70710678118654752f));
                    v1 = 0.5f * v1 * (1.0f + erff(v1 * 0.70710678118654752f));
                }
                if (outf) { outf[o] = v0; outf[o + 1] = v1; }
                if (ohi) {
                    bf16 h0 = __float2bfloat16(v0), h1 = __float2bfloat16(v1);
                    ohi[o]     = h0; olo[o]     = __float2bfloat16(v0 - __bfloat162float(h0));
                    ohi[o + 1] = h1; olo[o + 1] = __float2bfloat16(v1 - __bfloat162float(h1));
                }
            }
}

// ---------------- embedding + positional encoding (writes hi/lo) ------------
__global__ void embed_kernel(const float* __restrict__ x,
                             const float* __restrict__ tokW,
                             const float* __restrict__ tokb,
                             bf16* __restrict__ hhi, bf16* __restrict__ hlo)
{
    size_t idx = (size_t)blockIdx.x * 256 + threadIdx.x;
    size_t token = idx >> 7;
    int d = (int)(idx & 127);
    int t = (int)((token / NN) % TT);
    const float* xp = x + token * FINN;
    float val = xp[0]*tokW[d*3+0] + xp[1]*tokW[d*3+1] + xp[2]*tokW[d*3+2] + tokb[d];
    int i2 = d & ~1;
    float div = expf((float)i2 * (-logf(10000.0f) / (float)DD));
    float ang = (float)t * div;
    val += (d & 1) ? cosf(ang) : sinf(ang);
    bf16 h = __float2bfloat16(val);
    hhi[idx] = h;
    hlo[idx] = __float2bfloat16(val - __bfloat162float(h));
}

// ---------------- temporal attention (over T=12) — vectorized ---------------
__global__ void temporal_attn_kernel(const float* __restrict__ qkv,
                                     bf16* __restrict__ ohi, bf16* __restrict__ olo)
{
    const int bidx = blockIdx.x;
    const int b = bidx >> 9, n = bidx & 511;
    const int tid = threadIdx.x;
    __shared__ float q[TT][DD], k[TT][DD], v[TT][DD];
    __shared__ float S[HH][TT][TT];
#pragma unroll
    for (int t = 0; t < TT; ++t) {
        size_t row = ((size_t)(b*TT + t) * NN + n) * 384;
        q[t][tid] = qkv[row + tid];
        k[t][tid] = qkv[row + 128 + tid];
        v[t][tid] = qkv[row + 256 + tid];
    }
    __syncthreads();
    const float scale = 0.17677669529663687f;
    for (int idx = tid; idx < HH*TT*TT; idx += 128) {
        int hh = idx / (TT*TT);
        int rem = idx - hh*(TT*TT);
        int xx = rem / TT, yy = rem - xx*TT;
        const float4* q4 = (const float4*)&q[xx][hh*32];
        const float4* k4 = (const float4*)&k[yy][hh*32];
        float s = 0.f;
#pragma unroll
        for (int e = 0; e < 8; ++e) {
            float4 qa = q4[e], kb = k4[e];
            s = fmaf(qa.x, kb.x, s); s = fmaf(qa.y, kb.y, s);
            s = fmaf(qa.z, kb.z, s); s = fmaf(qa.w, kb.w, s);
        }
        S[hh][xx][yy] = s * scale;
    }
    __syncthreads();
    if (tid < HH*TT) {
        int hh = tid / TT, xx = tid % TT;
        float mx = -1e30f;
#pragma unroll
        for (int y = 0; y < TT; ++y) mx = fmaxf(mx, S[hh][xx][y]);
        float sum = 0.f;
#pragma unroll
        for (int y = 0; y < TT; ++y) { float p = __expf(S[hh][xx][y]-mx); S[hh][xx][y] = p; sum += p; }
        float inv = 1.f / sum;
#pragma unroll
        for (int y = 0; y < TT; ++y) S[hh][xx][y] *= inv;
    }
    __syncthreads();
    const int hh = tid >> 5;
    float vr[TT];
#pragma unroll
    for (int yy = 0; yy < TT; ++yy) vr[yy] = v[yy][tid];
#pragma unroll
    for (int xx = 0; xx < TT; ++xx) {
        float o = 0.f;
#pragma unroll
        for (int yy = 0; yy < TT; ++yy) o = fmaf(S[hh][xx][yy], vr[yy], o);
        size_t oi = ((size_t)(b*TT + xx) * NN + n) * DD + tid;
        bf16 h = __float2bfloat16(o);
        ohi[oi] = h;
        olo[oi] = __float2bfloat16(o - __bfloat162float(h));
    }
}

// ============ merged spatial attention (geo+sem, flash, fp16) ===============
__global__ void __launch_bounds__(256, 1)
spatial_attn_mma(const float* __restrict__ qkv,
                 bf16* __restrict__ ghi, bf16* __restrict__ glo,
                 bf16* __restrict__ shi, bf16* __restrict__ slo)
{
    const int qtile = blockIdx.x;
    const int sel   = blockIdx.y >> 2;
    const int head  = blockIdx.y & 3;
    const int bt    = blockIdx.z;
    const int tid  = threadIdx.x;
    const int wid  = tid >> 5;
    const int lane = tid & 31;
    const int l16  = lane & 15;

    bf16* outhi = sel ? shi : ghi;
    bf16* outlo = sel ? slo : glo;
    const int colq = sel * 384 + head * 32;

    __shared__ __half Qs[128][40];
    __shared__ __half Ks[128][40];
    __shared__ __half Vt[32][136];

    const size_t base = (size_t)bt * NN;
    const float scale = 0.17677669529663687f;

    for (int i = tid; i < 128*32; i += 256) {
        int r = i >> 5, e = i & 31;
        Qs[r][e] = __float2half(qkv[(base + (size_t)qtile*128 + r)*768 + colq + e] * scale);
    }
    __syncthreads();

    uint32_t qf[2][4];
#pragma unroll
    for (int kc = 0; kc < 2; ++kc) {
        uint32_t ad = smem_u32(&Qs[wid*16 + l16][kc*16 + (lane>>4)*8]);
        asm volatile("ldmatrix.sync.aligned.m8n8.x4.shared.b16 {%0,%1,%2,%3}, [%4];"
                     : "=r"(qf[kc][0]), "=r"(qf[kc][1]), "=r"(qf[kc][2]), "=r"(qf[kc][3])
                     : "r"(ad));
    }

    float m0 = -1e30f, m1 = -1e30f, l0 = 0.f, l1 = 0.f;
    float oacc[4][4];
#pragma unroll
    for (int ef = 0; ef < 4; ++ef)
#pragma unroll
        for (int r = 0; r < 4; ++r) oacc[ef][r] = 0.f;

    for (int kt = 0; kt < 4; ++kt) {
        __syncthreads();
        for (int i = tid; i < 128*32; i += 256) {
            int j = i >> 5, e = i & 31;
            const float* rp = qkv + (base + (size_t)kt*128 + j)*768 + colq + 128 + e;
            Ks[j][e] = __float2half(rp[0]);
            Vt[e][j] = __float2half(rp[128]);
        }
        __syncthreads();

        float sacc[16][4];
#pragma unroll
        for (int nf = 0; nf < 16; ++nf) {
            sacc[nf][0] = sacc[nf][1] = sacc[nf][2] = sacc[nf][3] = 0.f;
#pragma unroll
            for (int kc = 0; kc < 2; ++kc) {
                uint32_t b0, b1;
                uint32_t bd = smem_u32(&Ks[nf*8 + (l16 & 7)][kc*16 + (l16 >> 3)*8]);
                asm volatile("ldmatrix.sync.aligned.m8n8.x2.shared.b16 {%0,%1}, [%2];"
                             : "=r"(b0), "=r"(b1) : "r"(bd));
                asm volatile(
                    "mma.sync.aligned.m16n8k16.row.col.f32.f16.f16.f32 "
                    "{%0,%1,%2,%3}, {%4,%5,%6,%7}, {%8,%9}, {%0,%1,%2,%3};"
                    : "+f"(sacc[nf][0]), "+f"(sacc[nf][1]),
                      "+f"(sacc[nf][2]), "+f"(sacc[nf][3])
                    : "r"(qf[kc][0]), "r"(qf[kc][1]), "r"(qf[kc][2]), "r"(qf[kc][3]),
                      "r"(b0), "r"(b1));
            }
        }

        float mx0 = -1e30f, mx1 = -1e30f;
#pragma unroll
        for (int nf = 0; nf < 16; ++nf) {
            mx0 = fmaxf(mx0, fmaxf(sacc[nf][0], sacc[nf][1]));
            mx1 = fmaxf(mx1, fmaxf(sacc[nf][2], sacc[nf][3]));
        }
        mx0 = fmaxf(mx0, __shfl_xor_sync(0xffffffffu, mx0, 1));
        mx0 = fmaxf(mx0, __shfl_xor_sync(0xffffffffu, mx0, 2));
        mx1 = fmaxf(mx1, __shfl_xor_sync(0xffffffffu, mx1, 1));
        mx1 = fmaxf(mx1, __shfl_xor_sync(0xffffffffu, mx1, 2));
        const float nm0 = fmaxf(m0, mx0), nm1 = fmaxf(m1, mx1);
        const float c0 = __expf(m0 - nm0), c1 = __expf(m1 - nm1);
        m0 = nm0; m1 = nm1;
#pragma unroll
        for (int ef = 0; ef < 4; ++ef) {
            oacc[ef][0] *= c0; oacc[ef][1] *= c0;
            oacc[ef][2] *= c1; oacc[ef][3] *= c1;
        }

        float rs0 = 0.f, rs1 = 0.f;
#pragma unroll
        for (int jc = 0; jc < 8; ++jc) {
            float p00 = __expf(sacc[2*jc][0]   - nm0);
            float p01 = __expf(sacc[2*jc][1]   - nm0);
            float p10 = __expf(sacc[2*jc][2]   - nm1);
            float p11 = __expf(sacc[2*jc][3]   - nm1);
            float p20 = __expf(sacc[2*jc+1][0] - nm0);
            float p21 = __expf(sacc[2*jc+1][1] - nm0);
            float p30 = __expf(sacc[2*jc+1][2] - nm1);
            float p31 = __expf(sacc[2*jc+1][3] - nm1);
            rs0 += p00 + p01 + p20 + p21;
            rs1 += p10 + p11 + p30 + p31;
            uint32_t pf0 = pack2h(p00, p01);
            uint32_t pf1 = pack2h(p10, p11);
            uint32_t pf2 = pack2h(p20, p21);
            uint32_t pf3 = pack2h(p30, p31);
#pragma unroll
            for (int ef = 0; ef < 4; ++ef) {
                uint32_t b0, b1;
                uint32_t bd = smem_u32(&Vt[ef*8 + (l16 & 7)][jc*16 + (l16 >> 3)*8]);
                asm volatile("ldmatrix.sync.aligned.m8n8.x2.shared.b16 {%0,%1}, [%2];"
                             : "=r"(b0), "=r"(b1) : "r"(bd));
                asm volatile(
                    "mma.sync.aligned.m16n8k16.row.col.f32.f16.f16.f32 "
                    "{%0,%1,%2,%3}, {%4,%5,%6,%7}, {%8,%9}, {%0,%1,%2,%3};"
                    : "+f"(oacc[ef][0]), "+f"(oacc[ef][1]),
                      "+f"(oacc[ef][2]), "+f"(oacc[ef][3])
                    : "r"(pf0), "r"(pf1), "r"(pf2), "r"(pf3),
                      "r"(b0), "r"(b1));
            }
        }
        rs0 += __shfl_xor_sync(0xffffffffu, rs0, 1);
        rs0 += __shfl_xor_sync(0xffffffffu, rs0, 2);
        rs1 += __shfl_xor_sync(0xffffffffu, rs1, 1);
        rs1 += __shfl_xor_sync(0xffffffffu, rs1, 2);
        l0 = l0 * c0 + rs0;
        l1 = l1 * c1 + rs1;
    }

    const float i0 = 1.f / l0, i1 = 1.f / l1;
    const int r0 = wid*16 + (lane >> 2);
#pragma unroll
    for (int ef = 0; ef < 4; ++ef) {
        const int col = head*32 + ef*8 + (lane & 3)*2;
        size_t rowA = (base + (size_t)qtile*128 + r0) * DD + col;
        size_t rowB = (base + (size_t)qtile*128 + r0 + 8) * DD + col;
        float v0 = oacc[ef][0] * i0, v1 = oacc[ef][1] * i0;
        float v2 = oacc[ef][2] * i1, v3 = oacc[ef][3] * i1;
        bf16 h0 = __float2bfloat16(v0), h1 = __float2bfloat16(v1);
        bf16 h2 = __float2bfloat16(v2), h3 = __float2bfloat16(v3);
        outhi[rowA]   = h0; outlo[rowA]   = __float2bfloat16(v0 - __bfloat162float(h0));
        outhi[rowA+1] = h1; outlo[rowA+1] = __float2bfloat16(v1 - __bfloat162float(h1));
        outhi[rowB]   = h2; outlo[rowB]   = __float2bfloat16(v2 - __bfloat162float(h2));
        outhi[rowB+1] = h3; outlo[rowB+1] = __float2bfloat16(v3 - __bfloat162float(h3));
    }
}

// ---------------- layernorm — writes hi/lo + fp32 slice of xc ---------------
__global__ void ln_kernel(const float* __restrict__ pre, const float* __restrict__ g,
                          const float* __restrict__ bta,
                          bf16* __restrict__ hhi, bf16* __restrict__ hlo,
                          float* __restrict__ xc)
{
    const int warp = threadIdx.x >> 5, lane = threadIdx.x & 31;
    size_t token = (size_t)blockIdx.x * 8 + warp;
    const float* p = pre + token * DD;
    float v[4];
#pragma unroll
    for (int i = 0; i < 4; ++i) v[i] = p[lane + 32*i];
    float s = v[0] + v[1] + v[2] + v[3];
#pragma unroll
    for (int o = 16; o; o >>= 1) s += __shfl_xor_sync(0xffffffffu, s, o);
    float mean = s * (1.f/128.f);
    float q = 0.f;
#pragma unroll
    for (int i = 0; i < 4; ++i) { v[i] -= mean; q += v[i]*v[i]; }
#pragma unroll
    for (int o = 16; o; o >>= 1) q += __shfl_xor_sync(0xffffffffu, q, o);
    float inv = rsqrtf(q * (1.f/128.f) + 1e-5f);
#pragma unroll
    for (int i = 0; i < 4; ++i) {
        int d = lane + 32*i;
        float o = v[i] * inv * g[d] + bta[d];
        bf16 h = __float2bfloat16(o);
        hhi[token*DD + d] = h;
        hlo[token*DD + d] = __float2bfloat16(o - __bfloat162float(h));
        xc[token*(LL*DD) + d] = o;
    }
}

// ---------------- output head ------------------------------------------------
__global__ void head_kernel(const float* __restrict__ xc, const float* __restrict__ w1g,
                            const float* __restrict__ b1g, const float* __restrict__ w2g,
                            const float* __restrict__ b2g, float* __restrict__ y)
{
    const int bidx = blockIdx.x;
    const int b = bidx >> 9, n = bidx & 511;
    const int tid = threadIdx.x;
    __shared__ float xs[TT][LL*DD];
    __shared__ float w1[PP][TT];
    __shared__ float b1[PP];
    __shared__ float w2[LL*DD];
    __shared__ float red[PP][4];
    for (int t = 0; t < TT; ++t) {
        size_t rowoff = ((size_t)(b*TT + t) * NN + n) * (LL*DD);
        for (int c = tid; c < LL*DD; c += 128) xs[t][c] = xc[rowoff + c];
    }
    for (int i = tid; i < PP*TT; i += 128) w1[i/TT][i%TT] = w1g[i];
    if (tid < PP) b1[tid] = b1g[tid];
    for (int c = tid; c < LL*DD; c += 128) w2[c] = w2g[c];
    __syncthreads();

    float part[PP];
#pragma unroll
    for (int p = 0; p < PP; ++p) part[p] = 0.f;
    for (int c = tid; c < LL*DD; c += 128) {
        float xt[TT];
#pragma unroll
        for (int t = 0; t < TT; ++t) xt[t] = xs[t][c];
        float wc = w2[c];
#pragma unroll
        for (int p = 0; p < PP; ++p) {
            float sacc = b1[p];
#pragma unroll
            for (int t = 0; t < TT; ++t) sacc = fmaf(xt[t], w1[p][t], sacc);
            sacc = fmaxf(sacc, 0.f);
            part[p] = fmaf(sacc, wc, part[p]);
        }
    }
    const int warp = tid >> 5, lane = tid & 31;
#pragma unroll
    for (int p = 0; p < PP; ++p) {
        float sv = part[p];
#pragma unroll
        for (int o = 16; o; o >>= 1) sv += __shfl_xor_sync(0xffffffffu, sv, o);
        if (lane == 0) red[p][warp] = sv;
    }
    __syncthreads();
    if (tid < PP) {
        float sv = red[tid][0] + red[tid][1] + red[tid][2] + red[tid][3];
        y[(size_t)(b*PP + tid) * NN + n] = sv + b2g[0];
    }
}

// ---------------- launcher ---------------------------------------------------
extern "C" void kernel_launch(void* const* d_in, const int* in_sizes, int n_in,
                              void* d_out, int out_size)
{
    (void)in_sizes; (void)n_in; (void)out_size;
    const float* x      = (const float*)d_in[0];
    const float* tokW   = (const float*)d_in[1];
    const float* tokb   = (const float*)d_in[2];
    const float* t_qkvW = (const float*)d_in[3];
    const float* t_qkvb = (const float*)d_in[4];
    const float* t_pW   = (const float*)d_in[5];
    const float* t_pb   = (const float*)d_in[6];
    const float* g_qkvW = (const float*)d_in[7];
    const float* g_qkvb = (const float*)d_in[8];
    const float* g_pW   = (const float*)d_in[9];
    const float* g_pb   = (const float*)d_in[10];
    const float* s_qkvW = (const float*)d_in[11];
    const float* s_qkvb = (const float*)d_in[12];
    const float* s_pW   = (const float*)d_in[13];
    const float* s_pb   = (const float*)d_in[14];
    const float* resW   = (const float*)d_in[15];
    const float* resb   = (const float*)d_in[16];
    const float* normW  = (const float*)d_in[17];
    const float* normb  = (const float*)d_in[18];
    const float* fc1W   = (const float*)d_in[19];
    const float* fc1b   = (const float*)d_in[20];
    const float* fc2W   = (const float*)d_in[21];
    const float* fc2b   = (const float*)d_in[22];
    const float* e1W    = (const float*)d_in[23];
    const float* e1b    = (const float*)d_in[24];
    const float* e2W    = (const float*)d_in[25];
    const float* e2b    = (const float*)d_in[26];
    float* out = (float*)d_out;

    float *qkvB, *qkv12B, *preB, *xcB, *bgsB;
    cudaGetSymbolAddress((void**)&qkvB,   g_qkv);
    cudaGetSymbolAddress((void**)&qkv12B, g_qkv12);
    cudaGetSymbolAddress((void**)&preB,   g_pre);
    cudaGetSymbolAddress((void**)&xcB,    g_xc);
    cudaGetSymbolAddress((void**)&bgsB,   b_gs);

    bf16 *hAh,*hAl,*hBh,*hBl,*ath,*atl,*a2h,*a2l,*cth,*ctl,*mlh,*mll;
    cudaGetSymbolAddress((void**)&hAh, a_hA_hi); cudaGetSymbolAddress((void**)&hAl, a_hA_lo);
    cudaGetSymbolAddress((void**)&hBh, a_hB_hi); cudaGetSymbolAddress((void**)&hBl, a_hB_lo);
    cudaGetSymbolAddress((void**)&ath, a_at_hi); cudaGetSymbolAddress((void**)&atl, a_at_lo);
    cudaGetSymbolAddress((void**)&a2h, a_a2_hi); cudaGetSymbolAddress((void**)&a2l, a_a2_lo);
    cudaGetSymbolAddress((void**)&cth, a_ct_hi); cudaGetSymbolAddress((void**)&ctl, a_ct_lo);
    cudaGetSymbolAddress((void**)&mlh, a_ml_hi); cudaGetSymbolAddress((void**)&mll, a_ml_lo);

    bf16 *tqh,*tql,*gsh,*gsl,*tph,*tpl,*gph,*gpl,*sph,*spl,*f1h,*f1l,*cbh,*cbl;
    cudaGetSymbolAddress((void**)&tqh, w_tq_hi); cudaGetSymbolAddress((void**)&tql, w_tq_lo);
    cudaGetSymbolAddress((void**)&gsh, w_gs_hi); cudaGetSymbolAddress((void**)&gsl, w_gs_lo);
    cudaGetSymbolAddress((void**)&tph, w_tp_hi); cudaGetSymbolAddress((void**)&tpl, w_tp_lo);
    cudaGetSymbolAddress((void**)&gph, w_gp_hi); cudaGetSymbolAddress((void**)&gpl, w_gp_lo);
    cudaGetSymbolAddress((void**)&sph, w_sp_hi); cudaGetSymbolAddress((void**)&spl, w_sp_lo);
    cudaGetSymbolAddress((void**)&f1h, w_f1_hi); cudaGetSymbolAddress((void**)&f1l, w_f1_lo);
    cudaGetSymbolAddress((void**)&cbh, w_cb_hi); cudaGetSymbolAddress((void**)&cbl, w_cb_lo);

    cudaFuncSetAttribute(mma_gemm, cudaFuncAttributeMaxDynamicSharedMemorySize, 81920);
    const int DSM = 81920;
    const int MBt = TOK / 128;

    const int CVT_N = LL*3*DD*DD + LL*6*DD*DD + 3*(LL*DD*DD) + LL*HMM*2*DD + LL*DD*(HMM+DD);
    cvt_all<<<(CVT_N+255)/256, 256>>>(t_qkvW, g_qkvW, s_qkvW, t_pW, g_pW, s_pW,
                                      fc1W, fc2W, resW, g_qkvb, s_qkvb);

    embed_kernel<<<(TOK*DD)/256, 256>>>(x, tokW, tokb, hAh, hAl);

    for (int l = 0; l < LL; ++l) {
        const size_t oq = (size_t)l*3*DD*DD, oqb = (size_t)l*3*DD;
        const size_t op = (size_t)l*DD*DD,   opb = (size_t)l*DD;
        const size_t ogs = (size_t)l*6*DD*DD;

        // temporal attention
        mma_gemm<<<dim3(3, MBt), 256, DSM>>>(hAh, hAl, DD, nullptr, nullptr, 0,
                                             tqh+oq, tql+oq, t_qkvb+oqb, nullptr,
                                             qkvB, nullptr, nullptr, 3*DD, 0);
        temporal_attn_kernel<<<BB*NN, 128>>>(qkvB, ath, atl);
        mma_gemm<<<dim3(1, MBt), 256, DSM>>>(ath, atl, DD, nullptr, nullptr, 0,
                                             tph+op, tpl+op, t_pb+opb, nullptr,
                                             nullptr, hBh, hBl, DD, 0);
        // merged geo+sem qkv -> qkv12 [tok,768]
        mma_gemm<<<dim3(6, MBt), 256, DSM>>>(hBh, hBl, DD, nullptr, nullptr, 0,
                                             gsh+ogs, gsl+ogs, bgsB + (size_t)l*768, nullptr,
                                             qkv12B, nullptr, nullptr, 6*DD, 0);
        // merged spatial attention: geo -> at, sem -> a2
        spatial_attn_mma<<<dim3(NN/128, 2*HH, BB*TT), 256>>>(qkv12B, ath, atl, a2h, a2l);
        // projections into cat
        mma_gemm<<<dim3(1, MBt), 256, DSM>>>(ath, atl, DD, nullptr, nullptr, 0,
                                             gph+op, gpl+op, g_pb+opb, nullptr,
                                             nullptr, cth, ctl, 2*DD, 0);
        mma_gemm<<<dim3(1, MBt), 256, DSM>>>(a2h, a2l, DD, nullptr, nullptr, 0,
                                             sph+op, spl+op, s_pb+opb, nullptr,
                                             nullptr, cth+DD, ctl+DD, 2*DD, 0);
        // MLP fc1 (+gelu)
        mma_gemm<<<dim3(2, MBt), 256, DSM>>>(cth, ctl, 2*DD, nullptr, nullptr, 0,
                                             f1h+(size_t)l*HMM*2*DD, f1l+(size_t)l*HMM*2*DD,
                                             fc1b+(size_t)l*HMM, nullptr,
                                             nullptr, mlh, mll, HMM, 1);
        // fused fc2 + residual-linear
        mma_gemm<<<dim3(1, MBt), 256, DSM>>>(mlh, mll, HMM, hAh, hAl, DD,
                                             cbh+(size_t)l*DD*(HMM+DD), cbl+(size_t)l*DD*(HMM+DD),
                                             fc2b+opb, resb+opb,
                                             preB, nullptr, nullptr, DD, 0);
        ln_kernel<<<TOK/8, 256>>>(preB, normW+opb, normb+opb, hAh, hAl, xcB + (size_t)l*DD);
    }

    head_kernel<<<BB*NN, 128>>>(xcB, e1W, e1b, e2W, e2b, out);
}

// round 9
// speedup vs baseline: 3.0048x; 1.4032x over previous
#include <cuda_runtime.h>
#include <cuda_fp16.h>
#include <math.h>
#include <stdint.h>

#define BB   8
#define TT   12
#define NN   512
#define FINN 3
#define DD   128
#define HH   4
#define HMM  256
#define LL   3
#define PP   12
#define TOK  (BB*TT*NN)          // 49152 tokens

typedef __half h16;

// ---------------- fp32 scratch ----------------------------------------------
__device__ float g_qkv  [TOK*3*DD];    // temporal qkv [tok,384]
__device__ float g_qkv12[TOK*6*DD];    // geo|sem qkv  [tok,768]
__device__ float g_pre[TOK*DD];
__device__ float g_xc [TOK*LL*DD];
__device__ float b_gs [LL*6*DD];       // combined geo|sem qkv bias
// ---------------- fp16 activation scratch ------------------------------------
__device__ h16 a_hA[TOK*DD];
__device__ h16 a_hB[TOK*DD];
__device__ h16 a_at[TOK*DD];
__device__ h16 a_a2[TOK*DD];
__device__ h16 a_ct[TOK*2*DD];
__device__ h16 a_ml[TOK*HMM];
// ---------------- fp16 weights -----------------------------------------------
__device__ h16 w_tq[LL*3*DD*DD];
__device__ h16 w_gs[LL*6*DD*DD];
__device__ h16 w_tp[LL*DD*DD];
__device__ h16 w_gp[LL*DD*DD];
__device__ h16 w_sp[LL*DD*DD];
__device__ h16 w_f1[LL*HMM*2*DD];
__device__ h16 w_cb[LL*DD*(HMM+DD)];   // [fc2 | res] combined, K=384

__device__ __forceinline__ uint32_t smem_u32(const void* p) {
    uint32_t a;
    asm("{ .reg .u64 t; cvta.to.shared.u64 t, %1; cvt.u32.u64 %0, t; }"
        : "=r"(a) : "l"(p));
    return a;
}
__device__ __forceinline__ uint32_t pack2h(float a, float b) {
    __half2 h = __floats2half2_rn(a, b);
    return *(uint32_t*)&h;
}
#define CP_ASYNC16(dst, src) \
    asm volatile("cp.async.cg.shared.global [%0], [%1], 16;" :: "r"(dst), "l"(src))
#define CP_COMMIT() asm volatile("cp.async.commit_group;" ::: "memory")
#define CP_WAIT(n)  asm volatile("cp.async.wait_group %0;" :: "n"(n) : "memory")

// ================= one-shot weight conversion ================================
__global__ void cvt_all(const float* __restrict__ t_qkvW,
                        const float* __restrict__ g_qkvW, const float* __restrict__ s_qkvW,
                        const float* __restrict__ t_pW,   const float* __restrict__ g_pW,
                        const float* __restrict__ s_pW,   const float* __restrict__ fc1W,
                        const float* __restrict__ fc2W,   const float* __restrict__ resW,
                        const float* __restrict__ g_qkvb, const float* __restrict__ s_qkvb)
{
    int i = blockIdx.x * 256 + threadIdx.x;
    const int NQ  = LL*3*DD*DD;
    const int NGS = LL*6*DD*DD;
    const int NPw = LL*DD*DD;
    const int NF1 = LL*HMM*2*DD;
    const int NCB = LL*DD*(HMM+DD);
    float v; h16* dst; int off;
    if (i < NQ) { v = t_qkvW[i]; dst = w_tq; off = i; }
    else if ((i -= NQ) < NGS) {
        int l = i / (768*DD), r = (i / DD) % 768, k = i % DD;
        v = (r < 384) ? g_qkvW[((size_t)l*384 + r)*DD + k]
                      : s_qkvW[((size_t)l*384 + (r-384))*DD + k];
        if (k == 0) b_gs[l*768 + r] = (r < 384) ? g_qkvb[l*384 + r] : s_qkvb[l*384 + r - 384];
        dst = w_gs; off = i;
    }
    else if ((i -= NGS) < NPw) { v = t_pW[i]; dst = w_tp; off = i; }
    else if ((i -= NPw) < NPw) { v = g_pW[i]; dst = w_gp; off = i; }
    else if ((i -= NPw) < NPw) { v = s_pW[i]; dst = w_sp; off = i; }
    else if ((i -= NPw) < NF1) { v = fc1W[i]; dst = w_f1; off = i; }
    else if ((i -= NF1) < NCB) {
        const int KK = HMM + DD;
        int l = i / (DD*KK), r = (i / KK) % DD, k = i % KK;
        v = (k < HMM) ? fc2W[((size_t)l*DD + r)*HMM + k]
                      : resW[((size_t)l*DD + r)*DD + (k - HMM)];
        dst = w_cb; off = i;
    }
    else return;
    dst[off] = __float2half(v);
}

// ================= single-pass fp16 mma GEMM =================================
// C = act(concat(A1,A2) @ W^T + bias [+bias2]); fp16 inputs, fp32 accum.
// grid=(N/128, M/128), 256 threads (8 warps 2x4), double-buffered cp.async.
__global__ void __launch_bounds__(256, 2)
mma_gemm(const h16* __restrict__ A1, int K1, const h16* __restrict__ A2, int K2,
         const h16* __restrict__ W,
         const float* __restrict__ bias, const float* __restrict__ bias2,
         float* __restrict__ outf, h16* __restrict__ outh, int ldo, int gelu)
{
    __shared__ h16 As[2][128][40];
    __shared__ h16 Bs[2][128][40];

    const int tid  = threadIdx.x;
    const int wid  = tid >> 5;
    const int lane = tid & 31;
    const int l16  = lane & 15;
    const int warp_m = wid >> 2;
    const int warp_n = wid & 3;
    const int m0 = blockIdx.y * 128;
    const int n0 = blockIdx.x * 128;
    const int K  = K1 + K2;
    const int KC = K >> 5;

    float acc[4][4][4];
#pragma unroll
    for (int mi = 0; mi < 4; ++mi)
#pragma unroll
        for (int ni = 0; ni < 4; ++ni)
#pragma unroll
            for (int r = 0; r < 4; ++r) acc[mi][ni][r] = 0.f;

    auto load_chunk = [&](int buf, int kp) {
        const int kof = kp * 32;
        const h16* Asrc; int lda, acol;
        if (kof < K1) { Asrc = A1; lda = K1; acol = kof; }
        else          { Asrc = A2; lda = K2; acol = kof - K1; }
#pragma unroll
        for (int t = 0; t < 2; ++t) {
            const int c   = tid + t * 256;      // 0..511
            const int row = c >> 2;
            const int cc  = (c & 3) * 8;
            CP_ASYNC16(smem_u32(&As[buf][row][cc]),
                       Asrc + (size_t)(m0 + row) * lda + acol + cc);
            CP_ASYNC16(smem_u32(&Bs[buf][row][cc]),
                       W + (size_t)(n0 + row) * K + kof + cc);
        }
    };

    auto compute = [&](int buf) {
#pragma unroll
        for (int ks = 0; ks < 2; ++ks) {
            const int k = ks * 16;
            uint32_t a[4][4], b[4][2];
#pragma unroll
            for (int mi = 0; mi < 4; ++mi) {
                uint32_t ad = smem_u32(&As[buf][warp_m*64 + mi*16 + l16][k + (lane >> 4) * 8]);
                asm volatile("ldmatrix.sync.aligned.m8n8.x4.shared.b16 {%0,%1,%2,%3}, [%4];"
                             : "=r"(a[mi][0]), "=r"(a[mi][1]), "=r"(a[mi][2]), "=r"(a[mi][3])
                             : "r"(ad));
            }
#pragma unroll
            for (int ni = 0; ni < 4; ++ni) {
                uint32_t bd = smem_u32(&Bs[buf][warp_n*32 + ni*8 + (l16 & 7)][k + (l16 >> 3) * 8]);
                asm volatile("ldmatrix.sync.aligned.m8n8.x2.shared.b16 {%0,%1}, [%2];"
                             : "=r"(b[ni][0]), "=r"(b[ni][1]) : "r"(bd));
            }
#pragma unroll
            for (int mi = 0; mi < 4; ++mi)
#pragma unroll
                for (int ni = 0; ni < 4; ++ni)
                    asm volatile(
                        "mma.sync.aligned.m16n8k16.row.col.f32.f16.f16.f32 "
                        "{%0,%1,%2,%3}, {%4,%5,%6,%7}, {%8,%9}, {%0,%1,%2,%3};"
                        : "+f"(acc[mi][ni][0]), "+f"(acc[mi][ni][1]),
                          "+f"(acc[mi][ni][2]), "+f"(acc[mi][ni][3])
                        : "r"(a[mi][0]), "r"(a[mi][1]), "r"(a[mi][2]), "r"(a[mi][3]),
                          "r"(b[ni][0]), "r"(b[ni][1]));
        }
    };

    load_chunk(0, 0);
    CP_COMMIT();
    int buf = 0;
    for (int i = 0; i < KC; ++i) {
        if (i + 1 < KC) {
            load_chunk(buf ^ 1, i + 1);
            CP_COMMIT();
            CP_WAIT(1);
        } else {
            CP_WAIT(0);
        }
        __syncthreads();
        compute(buf);
        __syncthreads();
        buf ^= 1;
    }

    const int quad = lane >> 2, qi = lane & 3;
#pragma unroll
    for (int mi = 0; mi < 4; ++mi)
#pragma unroll
        for (int ni = 0; ni < 4; ++ni)
#pragma unroll
            for (int h = 0; h < 2; ++h) {
                const int row = m0 + warp_m * 64 + mi * 16 + quad + h * 8;
                const int col = n0 + warp_n * 32 + ni * 8 + qi * 2;
                float v0 = acc[mi][ni][h * 2 + 0] + bias[col];
                float v1 = acc[mi][ni][h * 2 + 1] + bias[col + 1];
                if (bias2) { v0 += bias2[col]; v1 += bias2[col + 1]; }
                const size_t o = (size_t)row * ldo + col;
                if (gelu) {
                    v0 = 0.5f * v0 * (1.0f + erff(v0 * 0.70710678118654752f));
                    v1 = 0.5f * v1 * (1.0f + erff(v1 * 0.70710678118654752f));
                }
                if (outf) { outf[o] = v0; outf[o + 1] = v1; }
                if (outh) {
                    *(uint32_t*)&outh[o] = pack2h(v0, v1);
                }
            }
}

// ---------------- embedding + positional encoding ---------------------------
__global__ void embed_kernel(const float* __restrict__ x,
                             const float* __restrict__ tokW,
                             const float* __restrict__ tokb,
                             h16* __restrict__ h)
{
    size_t idx = (size_t)blockIdx.x * 256 + threadIdx.x;
    size_t token = idx >> 7;
    int d = (int)(idx & 127);
    int t = (int)((token / NN) % TT);
    const float* xp = x + token * FINN;
    float val = xp[0]*tokW[d*3+0] + xp[1]*tokW[d*3+1] + xp[2]*tokW[d*3+2] + tokb[d];
    int i2 = d & ~1;
    float div = expf((float)i2 * (-logf(10000.0f) / (float)DD));
    float ang = (float)t * div;
    val += (d & 1) ? cosf(ang) : sinf(ang);
    h[idx] = __float2half(val);
}

// ---------------- temporal attention (T=12), padded smem --------------------
__global__ void temporal_attn_kernel(const float* __restrict__ qkv,
                                     h16* __restrict__ outp)
{
    const int bidx = blockIdx.x;
    const int b = bidx >> 9, n = bidx & 511;
    const int tid = threadIdx.x;
    __shared__ float q[TT][DD+4], k[TT][DD+4], v[TT][DD+4];   // 528B rows: no bank-align
    __shared__ float S[HH][TT][TT];
#pragma unroll
    for (int t = 0; t < TT; ++t) {
        size_t row = ((size_t)(b*TT + t) * NN + n) * 384;
        q[t][tid] = qkv[row + tid];
        k[t][tid] = qkv[row + 128 + tid];
        v[t][tid] = qkv[row + 256 + tid];
    }
    __syncthreads();
    const float scale = 0.17677669529663687f;
    for (int idx = tid; idx < HH*TT*TT; idx += 128) {
        int hh = idx / (TT*TT);
        int rem = idx - hh*(TT*TT);
        int xx = rem / TT, yy = rem - xx*TT;
        const float4* q4 = (const float4*)&q[xx][hh*32];
        const float4* k4 = (const float4*)&k[yy][hh*32];
        float s = 0.f;
#pragma unroll
        for (int e = 0; e < 8; ++e) {
            float4 qa = q4[e], kb = k4[e];
            s = fmaf(qa.x, kb.x, s); s = fmaf(qa.y, kb.y, s);
            s = fmaf(qa.z, kb.z, s); s = fmaf(qa.w, kb.w, s);
        }
        S[hh][xx][yy] = s * scale;
    }
    __syncthreads();
    if (tid < HH*TT) {
        int hh = tid / TT, xx = tid % TT;
        float mx = -1e30f;
#pragma unroll
        for (int y = 0; y < TT; ++y) mx = fmaxf(mx, S[hh][xx][y]);
        float sum = 0.f;
#pragma unroll
        for (int y = 0; y < TT; ++y) { float p = __expf(S[hh][xx][y]-mx); S[hh][xx][y] = p; sum += p; }
        float inv = 1.f / sum;
#pragma unroll
        for (int y = 0; y < TT; ++y) S[hh][xx][y] *= inv;
    }
    __syncthreads();
    const int hh = tid >> 5;
    float vr[TT];
#pragma unroll
    for (int yy = 0; yy < TT; ++yy) vr[yy] = v[yy][tid];
#pragma unroll
    for (int xx = 0; xx < TT; ++xx) {
        float o = 0.f;
#pragma unroll
        for (int yy = 0; yy < TT; ++yy) o = fmaf(S[hh][xx][yy], vr[yy], o);
        outp[((size_t)(b*TT + xx) * NN + n) * DD + tid] = __float2half(o);
    }
}

// ============ merged spatial attention (geo+sem, flash, fp16) ===============
__global__ void __launch_bounds__(256, 1)
spatial_attn_mma(const float* __restrict__ qkv,
                 h16* __restrict__ gout, h16* __restrict__ sout)
{
    const int qtile = blockIdx.x;
    const int sel   = blockIdx.y >> 2;
    const int head  = blockIdx.y & 3;
    const int bt    = blockIdx.z;
    const int tid  = threadIdx.x;
    const int wid  = tid >> 5;
    const int lane = tid & 31;
    const int l16  = lane & 15;

    h16* outp = sel ? sout : gout;
    const int colq = sel * 384 + head * 32;

    __shared__ __half Qs[128][40];
    __shared__ __half Ks[128][40];
    __shared__ __half Vt[32][136];

    const size_t base = (size_t)bt * NN;
    const float scale = 0.17677669529663687f;

    for (int i = tid; i < 128*32; i += 256) {
        int r = i >> 5, e = i & 31;
        Qs[r][e] = __float2half(qkv[(base + (size_t)qtile*128 + r)*768 + colq + e] * scale);
    }
    __syncthreads();

    uint32_t qf[2][4];
#pragma unroll
    for (int kc = 0; kc < 2; ++kc) {
        uint32_t ad = smem_u32(&Qs[wid*16 + l16][kc*16 + (lane>>4)*8]);
        asm volatile("ldmatrix.sync.aligned.m8n8.x4.shared.b16 {%0,%1,%2,%3}, [%4];"
                     : "=r"(qf[kc][0]), "=r"(qf[kc][1]), "=r"(qf[kc][2]), "=r"(qf[kc][3])
                     : "r"(ad));
    }

    float m0 = -1e30f, m1 = -1e30f, l0 = 0.f, l1 = 0.f;
    float oacc[4][4];
#pragma unroll
    for (int ef = 0; ef < 4; ++ef)
#pragma unroll
        for (int r = 0; r < 4; ++r) oacc[ef][r] = 0.f;

    for (int kt = 0; kt < 4; ++kt) {
        __syncthreads();
        for (int i = tid; i < 128*32; i += 256) {
            int j = i >> 5, e = i & 31;
            const float* rp = qkv + (base + (size_t)kt*128 + j)*768 + colq + 128 + e;
            Ks[j][e] = __float2half(rp[0]);
            Vt[e][j] = __float2half(rp[128]);
        }
        __syncthreads();

        float sacc[16][4];
#pragma unroll
        for (int nf = 0; nf < 16; ++nf) {
            sacc[nf][0] = sacc[nf][1] = sacc[nf][2] = sacc[nf][3] = 0.f;
#pragma unroll
            for (int kc = 0; kc < 2; ++kc) {
                uint32_t b0, b1;
                uint32_t bd = smem_u32(&Ks[nf*8 + (l16 & 7)][kc*16 + (l16 >> 3)*8]);
                asm volatile("ldmatrix.sync.aligned.m8n8.x2.shared.b16 {%0,%1}, [%2];"
                             : "=r"(b0), "=r"(b1) : "r"(bd));
                asm volatile(
                    "mma.sync.aligned.m16n8k16.row.col.f32.f16.f16.f32 "
                    "{%0,%1,%2,%3}, {%4,%5,%6,%7}, {%8,%9}, {%0,%1,%2,%3};"
                    : "+f"(sacc[nf][0]), "+f"(sacc[nf][1]),
                      "+f"(sacc[nf][2]), "+f"(sacc[nf][3])
                    : "r"(qf[kc][0]), "r"(qf[kc][1]), "r"(qf[kc][2]), "r"(qf[kc][3]),
                      "r"(b0), "r"(b1));
            }
        }

        float mx0 = -1e30f, mx1 = -1e30f;
#pragma unroll
        for (int nf = 0; nf < 16; ++nf) {
            mx0 = fmaxf(mx0, fmaxf(sacc[nf][0], sacc[nf][1]));
            mx1 = fmaxf(mx1, fmaxf(sacc[nf][2], sacc[nf][3]));
        }
        mx0 = fmaxf(mx0, __shfl_xor_sync(0xffffffffu, mx0, 1));
        mx0 = fmaxf(mx0, __shfl_xor_sync(0xffffffffu, mx0, 2));
        mx1 = fmaxf(mx1, __shfl_xor_sync(0xffffffffu, mx1, 1));
        mx1 = fmaxf(mx1, __shfl_xor_sync(0xffffffffu, mx1, 2));
        const float nm0 = fmaxf(m0, mx0), nm1 = fmaxf(m1, mx1);
        const float c0 = __expf(m0 - nm0), c1 = __expf(m1 - nm1);
        m0 = nm0; m1 = nm1;
#pragma unroll
        for (int ef = 0; ef < 4; ++ef) {
            oacc[ef][0] *= c0; oacc[ef][1] *= c0;
            oacc[ef][2] *= c1; oacc[ef][3] *= c1;
        }

        float rs0 = 0.f, rs1 = 0.f;
#pragma unroll
        for (int jc = 0; jc < 8; ++jc) {
            float p00 = __expf(sacc[2*jc][0]   - nm0);
            float p01 = __expf(sacc[2*jc][1]   - nm0);
            float p10 = __expf(sacc[2*jc][2]   - nm1);
            float p11 = __expf(sacc[2*jc][3]   - nm1);
            float p20 = __expf(sacc[2*jc+1][0] - nm0);
            float p21 = __expf(sacc[2*jc+1][1] - nm0);
            float p30 = __expf(sacc[2*jc+1][2] - nm1);
            float p31 = __expf(sacc[2*jc+1][3] - nm1);
            rs0 += p00 + p01 + p20 + p21;
            rs1 += p10 + p11 + p30 + p31;
            uint32_t pf0 = pack2h(p00, p01);
            uint32_t pf1 = pack2h(p10, p11);
            uint32_t pf2 = pack2h(p20, p21);
            uint32_t pf3 = pack2h(p30, p31);
#pragma unroll
            for (int ef = 0; ef < 4; ++ef) {
                uint32_t b0, b1;
                uint32_t bd = smem_u32(&Vt[ef*8 + (l16 & 7)][jc*16 + (l16 >> 3)*8]);
                asm volatile("ldmatrix.sync.aligned.m8n8.x2.shared.b16 {%0,%1}, [%2];"
                             : "=r"(b0), "=r"(b1) : "r"(bd));
                asm volatile(
                    "mma.sync.aligned.m16n8k16.row.col.f32.f16.f16.f32 "
                    "{%0,%1,%2,%3}, {%4,%5,%6,%7}, {%8,%9}, {%0,%1,%2,%3};"
                    : "+f"(oacc[ef][0]), "+f"(oacc[ef][1]),
                      "+f"(oacc[ef][2]), "+f"(oacc[ef][3])
                    : "r"(pf0), "r"(pf1), "r"(pf2), "r"(pf3),
                      "r"(b0), "r"(b1));
            }
        }
        rs0 += __shfl_xor_sync(0xffffffffu, rs0, 1);
        rs0 += __shfl_xor_sync(0xffffffffu, rs0, 2);
        rs1 += __shfl_xor_sync(0xffffffffu, rs1, 1);
        rs1 += __shfl_xor_sync(0xffffffffu, rs1, 2);
        l0 = l0 * c0 + rs0;
        l1 = l1 * c1 + rs1;
    }

    const float i0 = 1.f / l0, i1 = 1.f / l1;
    const int r0 = wid*16 + (lane >> 2);
#pragma unroll
    for (int ef = 0; ef < 4; ++ef) {
        const int col = head*32 + ef*8 + (lane & 3)*2;
        size_t rowA = (base + (size_t)qtile*128 + r0) * DD + col;
        size_t rowB = (base + (size_t)qtile*128 + r0 + 8) * DD + col;
        *(uint32_t*)&outp[rowA] = pack2h(oacc[ef][0] * i0, oacc[ef][1] * i0);
        *(uint32_t*)&outp[rowB] = pack2h(oacc[ef][2] * i1, oacc[ef][3] * i1);
    }
}

// ---------------- layernorm — writes fp16 + fp32 slice of xc ----------------
__global__ void ln_kernel(const float* __restrict__ pre, const float* __restrict__ g,
                          const float* __restrict__ bta,
                          h16* __restrict__ hout, float* __restrict__ xc)
{
    const int warp = threadIdx.x >> 5, lane = threadIdx.x & 31;
    size_t token = (size_t)blockIdx.x * 8 + warp;
    const float* p = pre + token * DD;
    float v[4];
#pragma unroll
    for (int i = 0; i < 4; ++i) v[i] = p[lane + 32*i];
    float s = v[0] + v[1] + v[2] + v[3];
#pragma unroll
    for (int o = 16; o; o >>= 1) s += __shfl_xor_sync(0xffffffffu, s, o);
    float mean = s * (1.f/128.f);
    float q = 0.f;
#pragma unroll
    for (int i = 0; i < 4; ++i) { v[i] -= mean; q += v[i]*v[i]; }
#pragma unroll
    for (int o = 16; o; o >>= 1) q += __shfl_xor_sync(0xffffffffu, q, o);
    float inv = rsqrtf(q * (1.f/128.f) + 1e-5f);
#pragma unroll
    for (int i = 0; i < 4; ++i) {
        int d = lane + 32*i;
        float o = v[i] * inv * g[d] + bta[d];
        hout[token*DD + d] = __float2half(o);
        xc[token*(LL*DD) + d] = o;
    }
}

// ---------------- output head ------------------------------------------------
__global__ void head_kernel(const float* __restrict__ xc, const float* __restrict__ w1g,
                            const float* __restrict__ b1g, const float* __restrict__ w2g,
                            const float* __restrict__ b2g, float* __restrict__ y)
{
    const int bidx = blockIdx.x;
    const int b = bidx >> 9, n = bidx & 511;
    const int tid = threadIdx.x;
    __shared__ float xs[TT][LL*DD];
    __shared__ float w1[PP][TT];
    __shared__ float b1[PP];
    __shared__ float w2[LL*DD];
    __shared__ float red[PP][4];
    for (int t = 0; t < TT; ++t) {
        size_t rowoff = ((size_t)(b*TT + t) * NN + n) * (LL*DD);
        for (int c = tid; c < LL*DD; c += 128) xs[t][c] = xc[rowoff + c];
    }
    for (int i = tid; i < PP*TT; i += 128) w1[i/TT][i%TT] = w1g[i];
    if (tid < PP) b1[tid] = b1g[tid];
    for (int c = tid; c < LL*DD; c += 128) w2[c] = w2g[c];
    __syncthreads();

    float part[PP];
#pragma unroll
    for (int p = 0; p < PP; ++p) part[p] = 0.f;
    for (int c = tid; c < LL*DD; c += 128) {
        float xt[TT];
#pragma unroll
        for (int t = 0; t < TT; ++t) xt[t] = xs[t][c];
        float wc = w2[c];
#pragma unroll
        for (int p = 0; p < PP; ++p) {
            float sacc = b1[p];
#pragma unroll
            for (int t = 0; t < TT; ++t) sacc = fmaf(xt[t], w1[p][t], sacc);
            sacc = fmaxf(sacc, 0.f);
            part[p] = fmaf(sacc, wc, part[p]);
        }
    }
    const int warp = tid >> 5, lane = tid & 31;
#pragma unroll
    for (int p = 0; p < PP; ++p) {
        float sv = part[p];
#pragma unroll
        for (int o = 16; o; o >>= 1) sv += __shfl_xor_sync(0xffffffffu, sv, o);
        if (lane == 0) red[p][warp] = sv;
    }
    __syncthreads();
    if (tid < PP) {
        float sv = red[tid][0] + red[tid][1] + red[tid][2] + red[tid][3];
        y[(size_t)(b*PP + tid) * NN + n] = sv + b2g[0];
    }
}

// ---------------- launcher ---------------------------------------------------
extern "C" void kernel_launch(void* const* d_in, const int* in_sizes, int n_in,
                              void* d_out, int out_size)
{
    (void)in_sizes; (void)n_in; (void)out_size;
    const float* x      = (const float*)d_in[0];
    const float* tokW   = (const float*)d_in[1];
    const float* tokb   = (const float*)d_in[2];
    const float* t_qkvW = (const float*)d_in[3];
    const float* t_qkvb = (const float*)d_in[4];
    const float* t_pW   = (const float*)d_in[5];
    const float* t_pb   = (const float*)d_in[6];
    const float* g_qkvW = (const float*)d_in[7];
    const float* g_qkvb = (const float*)d_in[8];
    const float* g_pW   = (const float*)d_in[9];
    const float* g_pb   = (const float*)d_in[10];
    const float* s_qkvW = (const float*)d_in[11];
    const float* s_qkvb = (const float*)d_in[12];
    const float* s_pW   = (const float*)d_in[13];
    const float* s_pb   = (const float*)d_in[14];
    const float* resW   = (const float*)d_in[15];
    const float* resb   = (const float*)d_in[16];
    const float* normW  = (const float*)d_in[17];
    const float* normb  = (const float*)d_in[18];
    const float* fc1W   = (const float*)d_in[19];
    const float* fc1b   = (const float*)d_in[20];
    const float* fc2W   = (const float*)d_in[21];
    const float* fc2b   = (const float*)d_in[22];
    const float* e1W    = (const float*)d_in[23];
    const float* e1b    = (const float*)d_in[24];
    const float* e2W    = (const float*)d_in[25];
    const float* e2b    = (const float*)d_in[26];
    float* out = (float*)d_out;

    float *qkvB, *qkv12B, *preB, *xcB, *bgsB;
    cudaGetSymbolAddress((void**)&qkvB,   g_qkv);
    cudaGetSymbolAddress((void**)&qkv12B, g_qkv12);
    cudaGetSymbolAddress((void**)&preB,   g_pre);
    cudaGetSymbolAddress((void**)&xcB,    g_xc);
    cudaGetSymbolAddress((void**)&bgsB,   b_gs);

    h16 *hA,*hB,*at,*a2,*ct,*ml;
    cudaGetSymbolAddress((void**)&hA, a_hA);
    cudaGetSymbolAddress((void**)&hB, a_hB);
    cudaGetSymbolAddress((void**)&at, a_at);
    cudaGetSymbolAddress((void**)&a2, a_a2);
    cudaGetSymbolAddress((void**)&ct, a_ct);
    cudaGetSymbolAddress((void**)&ml, a_ml);

    h16 *tq,*gs,*tp,*gp,*sp,*f1,*cb;
    cudaGetSymbolAddress((void**)&tq, w_tq);
    cudaGetSymbolAddress((void**)&gs, w_gs);
    cudaGetSymbolAddress((void**)&tp, w_tp);
    cudaGetSymbolAddress((void**)&gp, w_gp);
    cudaGetSymbolAddress((void**)&sp, w_sp);
    cudaGetSymbolAddress((void**)&f1, w_f1);
    cudaGetSymbolAddress((void**)&cb, w_cb);

    const int MBt = TOK / 128;

    const int CVT_N = LL*3*DD*DD + LL*6*DD*DD + 3*(LL*DD*DD) + LL*HMM*2*DD + LL*DD*(HMM+DD);
    cvt_all<<<(CVT_N+255)/256, 256>>>(t_qkvW, g_qkvW, s_qkvW, t_pW, g_pW, s_pW,
                                      fc1W, fc2W, resW, g_qkvb, s_qkvb);

    embed_kernel<<<(TOK*DD)/256, 256>>>(x, tokW, tokb, hA);

    for (int l = 0; l < LL; ++l) {
        const size_t oq = (size_t)l*3*DD*DD, oqb = (size_t)l*3*DD;
        const size_t op = (size_t)l*DD*DD,   opb = (size_t)l*DD;
        const size_t ogs = (size_t)l*6*DD*DD;

        // temporal attention
        mma_gemm<<<dim3(3, MBt), 256>>>(hA, DD, nullptr, 0, tq+oq,
                                        t_qkvb+oqb, nullptr, qkvB, nullptr, 3*DD, 0);
        temporal_attn_kernel<<<BB*NN, 128>>>(qkvB, at);
        mma_gemm<<<dim3(1, MBt), 256>>>(at, DD, nullptr, 0, tp+op,
                                        t_pb+opb, nullptr, nullptr, hB, DD, 0);
        // merged geo+sem qkv -> qkv12 [tok,768]
        mma_gemm<<<dim3(6, MBt), 256>>>(hB, DD, nullptr, 0, gs+ogs,
                                        bgsB + (size_t)l*768, nullptr, qkv12B, nullptr, 6*DD, 0);
        // merged spatial attention: geo -> at, sem -> a2
        spatial_attn_mma<<<dim3(NN/128, 2*HH, BB*TT), 256>>>(qkv12B, at, a2);
        // projections into cat
        mma_gemm<<<dim3(1, MBt), 256>>>(at, DD, nullptr, 0, gp+op,
                                        g_pb+opb, nullptr, nullptr, ct, 2*DD, 0);
        mma_gemm<<<dim3(1, MBt), 256>>>(a2, DD, nullptr, 0, sp+op,
                                        s_pb+opb, nullptr, nullptr, ct+DD, 2*DD, 0);
        // MLP fc1 (+gelu)
        mma_gemm<<<dim3(2, MBt), 256>>>(ct, 2*DD, nullptr, 0,
                                        f1+(size_t)l*HMM*2*DD,
                                        fc1b+(size_t)l*HMM, nullptr,
                                        nullptr, ml, HMM, 1);
        // fused fc2 + residual-linear
        mma_gemm<<<dim3(1, MBt), 256>>>(ml, HMM, hA, DD,
                                        cb+(size_t)l*DD*(HMM+DD),
                                        fc2b+opb, resb+opb,
                                        preB, nullptr, DD, 0);
        ln_kernel<<<TOK/8, 256>>>(preB, normW+opb, normb+opb, hA, xcB + (size_t)l*DD);
    }

    head_kernel<<<BB*NN, 128>>>(xcB, e1W, e1b, e2W, e2b, out);
}

// round 10
// speedup vs baseline: 4.4610x; 1.4846x over previous
#include <cuda_runtime.h>
#include <cuda_fp16.h>
#include <math.h>
#include <stdint.h>

#define BB   8
#define TT   12
#define NN   512
#define FINN 3
#define DD   128
#define HH   4
#define HMM  256
#define LL   3
#define PP   12
#define TOK  (BB*TT*NN)          // 49152 tokens

typedef __half h16;

// ---------------- scratch ----------------------------------------------------
__device__ h16   g_qkv  [TOK*3*DD];    // temporal qkv [tok,384] fp16
__device__ h16   g_qkv12[TOK*6*DD];    // geo|sem qkv  [tok,768] fp16
__device__ float g_pre[TOK*DD];
__device__ float g_xc [TOK*LL*DD];
__device__ float b_gs [LL*6*DD];
// fp16 activations
__device__ h16 a_hA[TOK*DD];
__device__ h16 a_hB[TOK*DD];
__device__ h16 a_at[TOK*DD];
__device__ h16 a_a2[TOK*DD];
__device__ h16 a_ct[TOK*2*DD];
__device__ h16 a_ml[TOK*HMM];
// fp16 weights
__device__ h16 w_tq[LL*3*DD*DD];
__device__ h16 w_gs[LL*6*DD*DD];
__device__ h16 w_tp[LL*DD*DD];
__device__ h16 w_gp[LL*DD*DD];
__device__ h16 w_sp[LL*DD*DD];
__device__ h16 w_f1[LL*HMM*2*DD];
__device__ h16 w_cb[LL*DD*(HMM+DD)];

__device__ __forceinline__ uint32_t smem_u32(const void* p) {
    uint32_t a;
    asm("{ .reg .u64 t; cvta.to.shared.u64 t, %1; cvt.u32.u64 %0, t; }"
        : "=r"(a) : "l"(p));
    return a;
}
__device__ __forceinline__ uint32_t pack2h(float a, float b) {
    __half2 h = __floats2half2_rn(a, b);
    return *(uint32_t*)&h;
}
#define CP_ASYNC16(dst, src) \
    asm volatile("cp.async.cg.shared.global [%0], [%1], 16;" :: "r"(dst), "l"(src))
#define CP_COMMIT() asm volatile("cp.async.commit_group;" ::: "memory")
#define CP_WAIT(n)  asm volatile("cp.async.wait_group %0;" :: "n"(n) : "memory")

// ================= one-shot weight conversion ================================
__global__ void cvt_all(const float* __restrict__ t_qkvW,
                        const float* __restrict__ g_qkvW, const float* __restrict__ s_qkvW,
                        const float* __restrict__ t_pW,   const float* __restrict__ g_pW,
                        const float* __restrict__ s_pW,   const float* __restrict__ fc1W,
                        const float* __restrict__ fc2W,   const float* __restrict__ resW,
                        const float* __restrict__ g_qkvb, const float* __restrict__ s_qkvb)
{
    int i = blockIdx.x * 256 + threadIdx.x;
    const int NQ  = LL*3*DD*DD;
    const int NGS = LL*6*DD*DD;
    const int NPw = LL*DD*DD;
    const int NF1 = LL*HMM*2*DD;
    const int NCB = LL*DD*(HMM+DD);
    float v; h16* dst; int off;
    if (i < NQ) { v = t_qkvW[i]; dst = w_tq; off = i; }
    else if ((i -= NQ) < NGS) {
        int l = i / (768*DD), r = (i / DD) % 768, k = i % DD;
        v = (r < 384) ? g_qkvW[((size_t)l*384 + r)*DD + k]
                      : s_qkvW[((size_t)l*384 + (r-384))*DD + k];
        if (k == 0) b_gs[l*768 + r] = (r < 384) ? g_qkvb[l*384 + r] : s_qkvb[l*384 + r - 384];
        dst = w_gs; off = i;
    }
    else if ((i -= NGS) < NPw) { v = t_pW[i]; dst = w_tp; off = i; }
    else if ((i -= NPw) < NPw) { v = g_pW[i]; dst = w_gp; off = i; }
    else if ((i -= NPw) < NPw) { v = s_pW[i]; dst = w_sp; off = i; }
    else if ((i -= NPw) < NF1) { v = fc1W[i]; dst = w_f1; off = i; }
    else if ((i -= NF1) < NCB) {
        const int KK = HMM + DD;
        int l = i / (DD*KK), r = (i / KK) % DD, k = i % KK;
        v = (k < HMM) ? fc2W[((size_t)l*DD + r)*HMM + k]
                      : resW[((size_t)l*DD + r)*DD + (k - HMM)];
        dst = w_cb; off = i;
    }
    else return;
    dst[off] = __float2half(v);
}

// ================= single-pass fp16 mma GEMM =================================
__global__ void __launch_bounds__(256, 2)
mma_gemm(const h16* __restrict__ A1, int K1, const h16* __restrict__ A2, int K2,
         const h16* __restrict__ W,
         const float* __restrict__ bias, const float* __restrict__ bias2,
         float* __restrict__ outf, h16* __restrict__ outh, int ldo, int gelu)
{
    __shared__ h16 As[2][128][40];
    __shared__ h16 Bs[2][128][40];

    const int tid  = threadIdx.x;
    const int wid  = tid >> 5;
    const int lane = tid & 31;
    const int l16  = lane & 15;
    const int warp_m = wid >> 2;
    const int warp_n = wid & 3;
    const int m0 = blockIdx.y * 128;
    const int n0 = blockIdx.x * 128;
    const int K  = K1 + K2;
    const int KC = K >> 5;

    float acc[4][4][4];
#pragma unroll
    for (int mi = 0; mi < 4; ++mi)
#pragma unroll
        for (int ni = 0; ni < 4; ++ni)
#pragma unroll
            for (int r = 0; r < 4; ++r) acc[mi][ni][r] = 0.f;

    auto load_chunk = [&](int buf, int kp) {
        const int kof = kp * 32;
        const h16* Asrc; int lda, acol;
        if (kof < K1) { Asrc = A1; lda = K1; acol = kof; }
        else          { Asrc = A2; lda = K2; acol = kof - K1; }
#pragma unroll
        for (int t = 0; t < 2; ++t) {
            const int c   = tid + t * 256;
            const int row = c >> 2;
            const int cc  = (c & 3) * 8;
            CP_ASYNC16(smem_u32(&As[buf][row][cc]),
                       Asrc + (size_t)(m0 + row) * lda + acol + cc);
            CP_ASYNC16(smem_u32(&Bs[buf][row][cc]),
                       W + (size_t)(n0 + row) * K + kof + cc);
        }
    };

    auto compute = [&](int buf) {
#pragma unroll
        for (int ks = 0; ks < 2; ++ks) {
            const int k = ks * 16;
            uint32_t a[4][4], b[4][2];
#pragma unroll
            for (int mi = 0; mi < 4; ++mi) {
                uint32_t ad = smem_u32(&As[buf][warp_m*64 + mi*16 + l16][k + (lane >> 4) * 8]);
                asm volatile("ldmatrix.sync.aligned.m8n8.x4.shared.b16 {%0,%1,%2,%3}, [%4];"
                             : "=r"(a[mi][0]), "=r"(a[mi][1]), "=r"(a[mi][2]), "=r"(a[mi][3])
                             : "r"(ad));
            }
#pragma unroll
            for (int ni = 0; ni < 4; ++ni) {
                uint32_t bd = smem_u32(&Bs[buf][warp_n*32 + ni*8 + (l16 & 7)][k + (l16 >> 3) * 8]);
                asm volatile("ldmatrix.sync.aligned.m8n8.x2.shared.b16 {%0,%1}, [%2];"
                             : "=r"(b[ni][0]), "=r"(b[ni][1]) : "r"(bd));
            }
#pragma unroll
            for (int mi = 0; mi < 4; ++mi)
#pragma unroll
                for (int ni = 0; ni < 4; ++ni)
                    asm volatile(
                        "mma.sync.aligned.m16n8k16.row.col.f32.f16.f16.f32 "
                        "{%0,%1,%2,%3}, {%4,%5,%6,%7}, {%8,%9}, {%0,%1,%2,%3};"
                        : "+f"(acc[mi][ni][0]), "+f"(acc[mi][ni][1]),
                          "+f"(acc[mi][ni][2]), "+f"(acc[mi][ni][3])
                        : "r"(a[mi][0]), "r"(a[mi][1]), "r"(a[mi][2]), "r"(a[mi][3]),
                          "r"(b[ni][0]), "r"(b[ni][1]));
        }
    };

    load_chunk(0, 0);
    CP_COMMIT();
    int buf = 0;
    for (int i = 0; i < KC; ++i) {
        if (i + 1 < KC) {
            load_chunk(buf ^ 1, i + 1);
            CP_COMMIT();
            CP_WAIT(1);
        } else {
            CP_WAIT(0);
        }
        __syncthreads();
        compute(buf);
        __syncthreads();
        buf ^= 1;
    }

    const int quad = lane >> 2, qi = lane & 3;
#pragma unroll
    for (int mi = 0; mi < 4; ++mi)
#pragma unroll
        for (int ni = 0; ni < 4; ++ni)
#pragma unroll
            for (int h = 0; h < 2; ++h) {
                const int row = m0 + warp_m * 64 + mi * 16 + quad + h * 8;
                const int col = n0 + warp_n * 32 + ni * 8 + qi * 2;
                float v0 = acc[mi][ni][h * 2 + 0] + bias[col];
                float v1 = acc[mi][ni][h * 2 + 1] + bias[col + 1];
                if (bias2) { v0 += bias2[col]; v1 += bias2[col + 1]; }
                const size_t o = (size_t)row * ldo + col;
                if (gelu) {
                    v0 = 0.5f * v0 * (1.0f + erff(v0 * 0.70710678118654752f));
                    v1 = 0.5f * v1 * (1.0f + erff(v1 * 0.70710678118654752f));
                }
                if (outf) { outf[o] = v0; outf[o + 1] = v1; }
                if (outh) *(uint32_t*)&outh[o] = pack2h(v0, v1);
            }
}

// ================= dual-source projection GEMM ===============================
// blockIdx.x==0: ct[:,0:128]   = at @ gpW^T + gpb
// blockIdx.x==1: ct[:,128:256] = a2 @ spW^T + spb
__global__ void __launch_bounds__(256, 2)
mma_gemm_dual(const h16* __restrict__ Aa, const h16* __restrict__ Ab,
              const h16* __restrict__ Wa, const h16* __restrict__ Wb,
              const float* __restrict__ ba, const float* __restrict__ bb,
              h16* __restrict__ outh /* [tok, 256] */)
{
    __shared__ h16 As[2][128][40];
    __shared__ h16 Bs[2][128][40];

    const int tid  = threadIdx.x;
    const int wid  = tid >> 5;
    const int lane = tid & 31;
    const int l16  = lane & 15;
    const int warp_m = wid >> 2;
    const int warp_n = wid & 3;
    const int m0 = blockIdx.y * 128;
    const int sel = blockIdx.x;
    const h16* A = sel ? Ab : Aa;
    const h16* W = sel ? Wb : Wa;
    const float* bias = sel ? bb : ba;
    const int n0 = sel * 128;

    float acc[4][4][4];
#pragma unroll
    for (int mi = 0; mi < 4; ++mi)
#pragma unroll
        for (int ni = 0; ni < 4; ++ni)
#pragma unroll
            for (int r = 0; r < 4; ++r) acc[mi][ni][r] = 0.f;

    auto load_chunk = [&](int buf, int kp) {
        const int kof = kp * 32;
#pragma unroll
        for (int t = 0; t < 2; ++t) {
            const int c   = tid + t * 256;
            const int row = c >> 2;
            const int cc  = (c & 3) * 8;
            CP_ASYNC16(smem_u32(&As[buf][row][cc]),
                       A + (size_t)(m0 + row) * DD + kof + cc);
            CP_ASYNC16(smem_u32(&Bs[buf][row][cc]),
                       W + (size_t)row * DD + kof + cc);
        }
    };

    auto compute = [&](int buf) {
#pragma unroll
        for (int ks = 0; ks < 2; ++ks) {
            const int k = ks * 16;
            uint32_t a[4][4], b[4][2];
#pragma unroll
            for (int mi = 0; mi < 4; ++mi) {
                uint32_t ad = smem_u32(&As[buf][warp_m*64 + mi*16 + l16][k + (lane >> 4) * 8]);
                asm volatile("ldmatrix.sync.aligned.m8n8.x4.shared.b16 {%0,%1,%2,%3}, [%4];"
                             : "=r"(a[mi][0]), "=r"(a[mi][1]), "=r"(a[mi][2]), "=r"(a[mi][3])
                             : "r"(ad));
            }
#pragma unroll
            for (int ni = 0; ni < 4; ++ni) {
                uint32_t bd = smem_u32(&Bs[buf][warp_n*32 + ni*8 + (l16 & 7)][k + (l16 >> 3) * 8]);
                asm volatile("ldmatrix.sync.aligned.m8n8.x2.shared.b16 {%0,%1}, [%2];"
                             : "=r"(b[ni][0]), "=r"(b[ni][1]) : "r"(bd));
            }
#pragma unroll
            for (int mi = 0; mi < 4; ++mi)
#pragma unroll
                for (int ni = 0; ni < 4; ++ni)
                    asm volatile(
                        "mma.sync.aligned.m16n8k16.row.col.f32.f16.f16.f32 "
                        "{%0,%1,%2,%3}, {%4,%5,%6,%7}, {%8,%9}, {%0,%1,%2,%3};"
                        : "+f"(acc[mi][ni][0]), "+f"(acc[mi][ni][1]),
                          "+f"(acc[mi][ni][2]), "+f"(acc[mi][ni][3])
                        : "r"(a[mi][0]), "r"(a[mi][1]), "r"(a[mi][2]), "r"(a[mi][3]),
                          "r"(b[ni][0]), "r"(b[ni][1]));
        }
    };

    load_chunk(0, 0);
    CP_COMMIT();
    int buf = 0;
    for (int i = 0; i < 4; ++i) {        // K=128 -> 4 chunks
        if (i + 1 < 4) {
            load_chunk(buf ^ 1, i + 1);
            CP_COMMIT();
            CP_WAIT(1);
        } else {
            CP_WAIT(0);
        }
        __syncthreads();
        compute(buf);
        __syncthreads();
        buf ^= 1;
    }

    const int quad = lane >> 2, qi = lane & 3;
#pragma unroll
    for (int mi = 0; mi < 4; ++mi)
#pragma unroll
        for (int ni = 0; ni < 4; ++ni)
#pragma unroll
            for (int h = 0; h < 2; ++h) {
                const int row = m0 + warp_m * 64 + mi * 16 + quad + h * 8;
                const int col = warp_n * 32 + ni * 8 + qi * 2;
                float v0 = acc[mi][ni][h * 2 + 0] + bias[col];
                float v1 = acc[mi][ni][h * 2 + 1] + bias[col + 1];
                *(uint32_t*)&outh[(size_t)row * (2*DD) + n0 + col] = pack2h(v0, v1);
            }
}

// ---------------- embedding + positional encoding ---------------------------
__global__ void embed_kernel(const float* __restrict__ x,
                             const float* __restrict__ tokW,
                             const float* __restrict__ tokb,
                             h16* __restrict__ h)
{
    size_t idx = (size_t)blockIdx.x * 256 + threadIdx.x;
    size_t token = idx >> 7;
    int d = (int)(idx & 127);
    int t = (int)((token / NN) % TT);
    const float* xp = x + token * FINN;
    float val = xp[0]*tokW[d*3+0] + xp[1]*tokW[d*3+1] + xp[2]*tokW[d*3+2] + tokb[d];
    int i2 = d & ~1;
    float div = expf((float)i2 * (-logf(10000.0f) / (float)DD));
    float ang = (float)t * div;
    val += (d & 1) ? cosf(ang) : sinf(ang);
    h[idx] = __float2half(val);
}

// ---------------- temporal attention (T=12), fp16 qkv ------------------------
__global__ void temporal_attn_kernel(const h16* __restrict__ qkv,
                                     h16* __restrict__ outp)
{
    const int bidx = blockIdx.x;
    const int b = bidx >> 9, n = bidx & 511;
    const int tid = threadIdx.x;
    __shared__ float q[TT][DD+4], k[TT][DD+4], v[TT][DD+4];
    __shared__ float S[HH][TT][TT];
#pragma unroll
    for (int t = 0; t < TT; ++t) {
        size_t row = ((size_t)(b*TT + t) * NN + n) * 384;
        q[t][tid] = __half2float(qkv[row + tid]);
        k[t][tid] = __half2float(qkv[row + 128 + tid]);
        v[t][tid] = __half2float(qkv[row + 256 + tid]);
    }
    __syncthreads();
    const float scale = 0.17677669529663687f;
    for (int idx = tid; idx < HH*TT*TT; idx += 128) {
        int hh = idx / (TT*TT);
        int rem = idx - hh*(TT*TT);
        int xx = rem / TT, yy = rem - xx*TT;
        const float4* q4 = (const float4*)&q[xx][hh*32];
        const float4* k4 = (const float4*)&k[yy][hh*32];
        float s = 0.f;
#pragma unroll
        for (int e = 0; e < 8; ++e) {
            float4 qa = q4[e], kb = k4[e];
            s = fmaf(qa.x, kb.x, s); s = fmaf(qa.y, kb.y, s);
            s = fmaf(qa.z, kb.z, s); s = fmaf(qa.w, kb.w, s);
        }
        S[hh][xx][yy] = s * scale;
    }
    __syncthreads();
    if (tid < HH*TT) {
        int hh = tid / TT, xx = tid % TT;
        float mx = -1e30f;
#pragma unroll
        for (int y = 0; y < TT; ++y) mx = fmaxf(mx, S[hh][xx][y]);
        float sum = 0.f;
#pragma unroll
        for (int y = 0; y < TT; ++y) { float p = __expf(S[hh][xx][y]-mx); S[hh][xx][y] = p; sum += p; }
        float inv = 1.f / sum;
#pragma unroll
        for (int y = 0; y < TT; ++y) S[hh][xx][y] *= inv;
    }
    __syncthreads();
    const int hh = tid >> 5;
    float vr[TT];
#pragma unroll
    for (int yy = 0; yy < TT; ++yy) vr[yy] = v[yy][tid];
#pragma unroll
    for (int xx = 0; xx < TT; ++xx) {
        float o = 0.f;
#pragma unroll
        for (int yy = 0; yy < TT; ++yy) o = fmaf(S[hh][xx][yy], vr[yy], o);
        outp[((size_t)(b*TT + xx) * NN + n) * DD + tid] = __float2half(o);
    }
}

// ============ merged spatial attention (geo+sem, flash, fp16 in/out) =========
__global__ void __launch_bounds__(256, 1)
spatial_attn_mma(const h16* __restrict__ qkv,
                 h16* __restrict__ gout, h16* __restrict__ sout)
{
    const int qtile = blockIdx.x;
    const int sel   = blockIdx.y >> 2;
    const int head  = blockIdx.y & 3;
    const int bt    = blockIdx.z;
    const int tid  = threadIdx.x;
    const int wid  = tid >> 5;
    const int lane = tid & 31;
    const int l16  = lane & 15;

    h16* outp = sel ? sout : gout;
    const int colq = sel * 384 + head * 32;

    __shared__ __half Qs[128][40];
    __shared__ __half Ks[128][40];
    __shared__ __half Vt[32][136];

    const size_t base = (size_t)bt * NN;
    const float scale = 0.17677669529663687f;
    const __half2 hs2 = __floats2half2_rn(scale, scale);

    // vectorized Q load (8 halves per thread-iter) with scale fold
    for (int i = tid; i < 128*4; i += 256) {
        int r = i >> 2, ec = (i & 3) * 8;
        uint4 vq = *(const uint4*)(qkv + (base + (size_t)qtile*128 + r)*768 + colq + ec);
        __half2* p = (__half2*)&vq;
#pragma unroll
        for (int z = 0; z < 4; ++z) p[z] = __hmul2(p[z], hs2);
        *(uint4*)&Qs[r][ec] = vq;
    }
    __syncthreads();

    uint32_t qf[2][4];
#pragma unroll
    for (int kc = 0; kc < 2; ++kc) {
        uint32_t ad = smem_u32(&Qs[wid*16 + l16][kc*16 + (lane>>4)*8]);
        asm volatile("ldmatrix.sync.aligned.m8n8.x4.shared.b16 {%0,%1,%2,%3}, [%4];"
                     : "=r"(qf[kc][0]), "=r"(qf[kc][1]), "=r"(qf[kc][2]), "=r"(qf[kc][3])
                     : "r"(ad));
    }

    float m0 = -1e30f, m1 = -1e30f, l0 = 0.f, l1 = 0.f;
    float oacc[4][4];
#pragma unroll
    for (int ef = 0; ef < 4; ++ef)
#pragma unroll
        for (int r = 0; r < 4; ++r) oacc[ef][r] = 0.f;

    for (int kt = 0; kt < 4; ++kt) {
        __syncthreads();
        for (int i = tid; i < 128*4; i += 256) {
            int j = i >> 2, ec = (i & 3) * 8;
            const h16* rp = qkv + (base + (size_t)kt*128 + j)*768 + colq + 128 + ec;
            *(uint4*)&Ks[j][ec] = *(const uint4*)rp;
            uint4 vv = *(const uint4*)(rp + 128);
            h16 tmp[8]; *(uint4*)tmp = vv;
#pragma unroll
            for (int z = 0; z < 8; ++z) Vt[ec + z][j] = tmp[z];
        }
        __syncthreads();

        float sacc[16][4];
#pragma unroll
        for (int nf = 0; nf < 16; ++nf) {
            sacc[nf][0] = sacc[nf][1] = sacc[nf][2] = sacc[nf][3] = 0.f;
#pragma unroll
            for (int kc = 0; kc < 2; ++kc) {
                uint32_t b0, b1;
                uint32_t bd = smem_u32(&Ks[nf*8 + (l16 & 7)][kc*16 + (l16 >> 3)*8]);
                asm volatile("ldmatrix.sync.aligned.m8n8.x2.shared.b16 {%0,%1}, [%2];"
                             : "=r"(b0), "=r"(b1) : "r"(bd));
                asm volatile(
                    "mma.sync.aligned.m16n8k16.row.col.f32.f16.f16.f32 "
                    "{%0,%1,%2,%3}, {%4,%5,%6,%7}, {%8,%9}, {%0,%1,%2,%3};"
                    : "+f"(sacc[nf][0]), "+f"(sacc[nf][1]),
                      "+f"(sacc[nf][2]), "+f"(sacc[nf][3])
                    : "r"(qf[kc][0]), "r"(qf[kc][1]), "r"(qf[kc][2]), "r"(qf[kc][3]),
                      "r"(b0), "r"(b1));
            }
        }

        float mx0 = -1e30f, mx1 = -1e30f;
#pragma unroll
        for (int nf = 0; nf < 16; ++nf) {
            mx0 = fmaxf(mx0, fmaxf(sacc[nf][0], sacc[nf][1]));
            mx1 = fmaxf(mx1, fmaxf(sacc[nf][2], sacc[nf][3]));
        }
        mx0 = fmaxf(mx0, __shfl_xor_sync(0xffffffffu, mx0, 1));
        mx0 = fmaxf(mx0, __shfl_xor_sync(0xffffffffu, mx0, 2));
        mx1 = fmaxf(mx1, __shfl_xor_sync(0xffffffffu, mx1, 1));
        mx1 = fmaxf(mx1, __shfl_xor_sync(0xffffffffu, mx1, 2));
        const float nm0 = fmaxf(m0, mx0), nm1 = fmaxf(m1, mx1);
        const float c0 = __expf(m0 - nm0), c1 = __expf(m1 - nm1);
        m0 = nm0; m1 = nm1;
#pragma unroll
        for (int ef = 0; ef < 4; ++ef) {
            oacc[ef][0] *= c0; oacc[ef][1] *= c0;
            oacc[ef][2] *= c1; oacc[ef][3] *= c1;
        }

        float rs0 = 0.f, rs1 = 0.f;
#pragma unroll
        for (int jc = 0; jc < 8; ++jc) {
            float p00 = __expf(sacc[2*jc][0]   - nm0);
            float p01 = __expf(sacc[2*jc][1]   - nm0);
            float p10 = __expf(sacc[2*jc][2]   - nm1);
            float p11 = __expf(sacc[2*jc][3]   - nm1);
            float p20 = __expf(sacc[2*jc+1][0] - nm0);
            float p21 = __expf(sacc[2*jc+1][1] - nm0);
            float p30 = __expf(sacc[2*jc+1][2] - nm1);
            float p31 = __expf(sacc[2*jc+1][3] - nm1);
            rs0 += p00 + p01 + p20 + p21;
            rs1 += p10 + p11 + p30 + p31;
            uint32_t pf0 = pack2h(p00, p01);
            uint32_t pf1 = pack2h(p10, p11);
            uint32_t pf2 = pack2h(p20, p21);
            uint32_t pf3 = pack2h(p30, p31);
#pragma unroll
            for (int ef = 0; ef < 4; ++ef) {
                uint32_t b0, b1;
                uint32_t bd = smem_u32(&Vt[ef*8 + (l16 & 7)][jc*16 + (l16 >> 3)*8]);
                asm volatile("ldmatrix.sync.aligned.m8n8.x2.shared.b16 {%0,%1}, [%2];"
                             : "=r"(b0), "=r"(b1) : "r"(bd));
                asm volatile(
                    "mma.sync.aligned.m16n8k16.row.col.f32.f16.f16.f32 "
                    "{%0,%1,%2,%3}, {%4,%5,%6,%7}, {%8,%9}, {%0,%1,%2,%3};"
                    : "+f"(oacc[ef][0]), "+f"(oacc[ef][1]),
                      "+f"(oacc[ef][2]), "+f"(oacc[ef][3])
                    : "r"(pf0), "r"(pf1), "r"(pf2), "r"(pf3),
                      "r"(b0), "r"(b1));
            }
        }
        rs0 += __shfl_xor_sync(0xffffffffu, rs0, 1);
        rs0 += __shfl_xor_sync(0xffffffffu, rs0, 2);
        rs1 += __shfl_xor_sync(0xffffffffu, rs1, 1);
        rs1 += __shfl_xor_sync(0xffffffffu, rs1, 2);
        l0 = l0 * c0 + rs0;
        l1 = l1 * c1 + rs1;
    }

    const float i0 = 1.f / l0, i1 = 1.f / l1;
    const int r0 = wid*16 + (lane >> 2);
#pragma unroll
    for (int ef = 0; ef < 4; ++ef) {
        const int col = head*32 + ef*8 + (lane & 3)*2;
        size_t rowA = (base + (size_t)qtile*128 + r0) * DD + col;
        size_t rowB = (base + (size_t)qtile*128 + r0 + 8) * DD + col;
        *(uint32_t*)&outp[rowA] = pack2h(oacc[ef][0] * i0, oacc[ef][1] * i0);
        *(uint32_t*)&outp[rowB] = pack2h(oacc[ef][2] * i1, oacc[ef][3] * i1);
    }
}

// ---------------- layernorm --------------------------------------------------
__global__ void ln_kernel(const float* __restrict__ pre, const float* __restrict__ g,
                          const float* __restrict__ bta,
                          h16* __restrict__ hout, float* __restrict__ xc)
{
    const int warp = threadIdx.x >> 5, lane = threadIdx.x & 31;
    size_t token = (size_t)blockIdx.x * 8 + warp;
    const float* p = pre + token * DD;
    float v[4];
#pragma unroll
    for (int i = 0; i < 4; ++i) v[i] = p[lane + 32*i];
    float s = v[0] + v[1] + v[2] + v[3];
#pragma unroll
    for (int o = 16; o; o >>= 1) s += __shfl_xor_sync(0xffffffffu, s, o);
    float mean = s * (1.f/128.f);
    float q = 0.f;
#pragma unroll
    for (int i = 0; i < 4; ++i) { v[i] -= mean; q += v[i]*v[i]; }
#pragma unroll
    for (int o = 16; o; o >>= 1) q += __shfl_xor_sync(0xffffffffu, q, o);
    float inv = rsqrtf(q * (1.f/128.f) + 1e-5f);
#pragma unroll
    for (int i = 0; i < 4; ++i) {
        int d = lane + 32*i;
        float o = v[i] * inv * g[d] + bta[d];
        hout[token*DD + d] = __float2half(o);
        xc[token*(LL*DD) + d] = o;
    }
}

// ---------------- output head ------------------------------------------------
__global__ void head_kernel(const float* __restrict__ xc, const float* __restrict__ w1g,
                            const float* __restrict__ b1g, const float* __restrict__ w2g,
                            const float* __restrict__ b2g, float* __restrict__ y)
{
    const int bidx = blockIdx.x;
    const int b = bidx >> 9, n = bidx & 511;
    const int tid = threadIdx.x;
    __shared__ float xs[TT][LL*DD];
    __shared__ float w1[PP][TT];
    __shared__ float b1[PP];
    __shared__ float w2[LL*DD];
    __shared__ float red[PP][4];
    for (int t = 0; t < TT; ++t) {
        size_t rowoff = ((size_t)(b*TT + t) * NN + n) * (LL*DD);
        for (int c = tid; c < LL*DD; c += 128) xs[t][c] = xc[rowoff + c];
    }
    for (int i = tid; i < PP*TT; i += 128) w1[i/TT][i%TT] = w1g[i];
    if (tid < PP) b1[tid] = b1g[tid];
    for (int c = tid; c < LL*DD; c += 128) w2[c] = w2g[c];
    __syncthreads();

    float part[PP];
#pragma unroll
    for (int p = 0; p < PP; ++p) part[p] = 0.f;
    for (int c = tid; c < LL*DD; c += 128) {
        float xt[TT];
#pragma unroll
        for (int t = 0; t < TT; ++t) xt[t] = xs[t][c];
        float wc = w2[c];
#pragma unroll
        for (int p = 0; p < PP; ++p) {
            float sacc = b1[p];
#pragma unroll
            for (int t = 0; t < TT; ++t) sacc = fmaf(xt[t], w1[p][t], sacc);
            sacc = fmaxf(sacc, 0.f);
            part[p] = fmaf(sacc, wc, part[p]);
        }
    }
    const int warp = tid >> 5, lane = tid & 31;
#pragma unroll
    for (int p = 0; p < PP; ++p) {
        float sv = part[p];
#pragma unroll
        for (int o = 16; o; o >>= 1) sv += __shfl_xor_sync(0xffffffffu, sv, o);
        if (lane == 0) red[p][warp] = sv;
    }
    __syncthreads();
    if (tid < PP) {
        float sv = red[tid][0] + red[tid][1] + red[tid][2] + red[tid][3];
        y[(size_t)(b*PP + tid) * NN + n] = sv + b2g[0];
    }
}

// ---------------- launcher ---------------------------------------------------
extern "C" void kernel_launch(void* const* d_in, const int* in_sizes, int n_in,
                              void* d_out, int out_size)
{
    (void)in_sizes; (void)n_in; (void)out_size;
    const float* x      = (const float*)d_in[0];
    const float* tokW   = (const float*)d_in[1];
    const float* tokb   = (const float*)d_in[2];
    const float* t_qkvW = (const float*)d_in[3];
    const float* t_qkvb = (const float*)d_in[4];
    const float* t_pW   = (const float*)d_in[5];
    const float* t_pb   = (const float*)d_in[6];
    const float* g_qkvW = (const float*)d_in[7];
    const float* g_qkvb = (const float*)d_in[8];
    const float* g_pW   = (const float*)d_in[9];
    const float* g_pb   = (const float*)d_in[10];
    const float* s_qkvW = (const float*)d_in[11];
    const float* s_qkvb = (const float*)d_in[12];
    const float* s_pW   = (const float*)d_in[13];
    const float* s_pb   = (const float*)d_in[14];
    const float* resW   = (const float*)d_in[15];
    const float* resb   = (const float*)d_in[16];
    const float* normW  = (const float*)d_in[17];
    const float* normb  = (const float*)d_in[18];
    const float* fc1W   = (const float*)d_in[19];
    const float* fc1b   = (const float*)d_in[20];
    const float* fc2W   = (const float*)d_in[21];
    const float* fc2b   = (const float*)d_in[22];
    const float* e1W    = (const float*)d_in[23];
    const float* e1b    = (const float*)d_in[24];
    const float* e2W    = (const float*)d_in[25];
    const float* e2b    = (const float*)d_in[26];
    float* out = (float*)d_out;

    float *preB, *xcB, *bgsB;
    h16 *qkvB, *qkv12B;
    cudaGetSymbolAddress((void**)&qkvB,   g_qkv);
    cudaGetSymbolAddress((void**)&qkv12B, g_qkv12);
    cudaGetSymbolAddress((void**)&preB,   g_pre);
    cudaGetSymbolAddress((void**)&xcB,    g_xc);
    cudaGetSymbolAddress((void**)&bgsB,   b_gs);

    h16 *hA,*hB,*at,*a2,*ct,*ml;
    cudaGetSymbolAddress((void**)&hA, a_hA);
    cudaGetSymbolAddress((void**)&hB, a_hB);
    cudaGetSymbolAddress((void**)&at, a_at);
    cudaGetSymbolAddress((void**)&a2, a_a2);
    cudaGetSymbolAddress((void**)&ct, a_ct);
    cudaGetSymbolAddress((void**)&ml, a_ml);

    h16 *tq,*gs,*tp,*gp,*sp,*f1,*cb;
    cudaGetSymbolAddress((void**)&tq, w_tq);
    cudaGetSymbolAddress((void**)&gs, w_gs);
    cudaGetSymbolAddress((void**)&tp, w_tp);
    cudaGetSymbolAddress((void**)&gp, w_gp);
    cudaGetSymbolAddress((void**)&sp, w_sp);
    cudaGetSymbolAddress((void**)&f1, w_f1);
    cudaGetSymbolAddress((void**)&cb, w_cb);

    const int MBt = TOK / 128;

    const int CVT_N = LL*3*DD*DD + LL*6*DD*DD + 3*(LL*DD*DD) + LL*HMM*2*DD + LL*DD*(HMM+DD);
    cvt_all<<<(CVT_N+255)/256, 256>>>(t_qkvW, g_qkvW, s_qkvW, t_pW, g_pW, s_pW,
                                      fc1W, fc2W, resW, g_qkvb, s_qkvb);

    embed_kernel<<<(TOK*DD)/256, 256>>>(x, tokW, tokb, hA);

    for (int l = 0; l < LL; ++l) {
        const size_t oq = (size_t)l*3*DD*DD, oqb = (size_t)l*3*DD;
        const size_t op = (size_t)l*DD*DD,   opb = (size_t)l*DD;
        const size_t ogs = (size_t)l*6*DD*DD;

        // temporal attention
        mma_gemm<<<dim3(3, MBt), 256>>>(hA, DD, nullptr, 0, tq+oq,
                                        t_qkvb+oqb, nullptr, nullptr, qkvB, 3*DD, 0);
        temporal_attn_kernel<<<BB*NN, 128>>>(qkvB, at);
        mma_gemm<<<dim3(1, MBt), 256>>>(at, DD, nullptr, 0, tp+op,
                                        t_pb+opb, nullptr, nullptr, hB, DD, 0);
        // merged geo+sem qkv -> qkv12 [tok,768] fp16
        mma_gemm<<<dim3(6, MBt), 256>>>(hB, DD, nullptr, 0, gs+ogs,
                                        bgsB + (size_t)l*768, nullptr, nullptr, qkv12B, 6*DD, 0);
        // merged spatial attention: geo -> at, sem -> a2
        spatial_attn_mma<<<dim3(NN/128, 2*HH, BB*TT), 256>>>(qkv12B, at, a2);
        // dual projection into cat
        mma_gemm_dual<<<dim3(2, MBt), 256>>>(at, a2, gp+op, sp+op,
                                             g_pb+opb, s_pb+opb, ct);
        // MLP fc1 (+gelu)
        mma_gemm<<<dim3(2, MBt), 256>>>(ct, 2*DD, nullptr, 0,
                                        f1+(size_t)l*HMM*2*DD,
                                        fc1b+(size_t)l*HMM, nullptr,
                                        nullptr, ml, HMM, 1);
        // fused fc2 + residual-linear
        mma_gemm<<<dim3(1, MBt), 256>>>(ml, HMM, hA, DD,
                                        cb+(size_t)l*DD*(HMM+DD),
                                        fc2b+opb, resb+opb,
                                        preB, nullptr, DD, 0);
        ln_kernel<<<TOK/8, 256>>>(preB, normW+opb, normb+opb, hA, xcB + (size_t)l*DD);
    }

    head_kernel<<<BB*NN, 128>>>(xcB, e1W, e1b, e2W, e2b, out);
}